// round 1
// baseline (speedup 1.0000x reference)
#include <cuda_runtime.h>
#include <cuda_bf16.h>
#include <math.h>

// Problem constants
#define BB 2
#define TT 2048
#define DD 1024
#define HH 16
#define HD 64
#define MM (BB*TT)   // 4096

// ---------------------------------------------------------------------------
// Scratch (device globals; no allocation allowed)
// ---------------------------------------------------------------------------
__device__ float g_Q[MM*DD];   // [B,H,T,HD]
__device__ float g_K[MM*DD];
__device__ float g_V[MM*DD];
__device__ float g_O[MM*DD];   // [B,T,H*HD]  (row-major [4096,1024])
__device__ float g_c[BB*HH*TT];

// ---------------------------------------------------------------------------
// SGEMM: C[M=4096, N=1024] = A[4096,1024] @ W[1024,1024]
// 128x128 block tile, BK=8, 8x8 micro tile, 256 threads.
// MODE 0: row-major store. MODE 1: store to [B,H,T,HD] layout.
// ---------------------------------------------------------------------------
template<int MODE>
__global__ __launch_bounds__(256) void gemm128(
    const float* __restrict__ A, const float* __restrict__ W,
    float* __restrict__ C)
{
    __shared__ float As[8][128];
    __shared__ float Bs[8][128];

    const int tid = threadIdx.x;
    const int m0 = blockIdx.y * 128;
    const int n0 = blockIdx.x * 128;

    const int aRow = tid >> 1;           // 0..127
    const int aCol = (tid & 1) * 4;      // 0 or 4
    const int bRow = tid >> 5;           // 0..7
    const int bCol = (tid & 31) * 4;     // 0..124

    const float* Aptr = A + (size_t)(m0 + aRow) * DD + aCol;
    const float* Bptr = W + (size_t)bRow * DD + n0 + bCol;

    const int tx = tid & 15;
    const int ty = tid >> 4;

    float acc[8][8];
#pragma unroll
    for (int i = 0; i < 8; i++)
#pragma unroll
        for (int j = 0; j < 8; j++) acc[i][j] = 0.f;

    for (int k0 = 0; k0 < DD; k0 += 8) {
        float4 av = *(const float4*)(Aptr + k0);
        float4 bv = *(const float4*)(Bptr + (size_t)k0 * DD);
        As[aCol + 0][aRow] = av.x;
        As[aCol + 1][aRow] = av.y;
        As[aCol + 2][aRow] = av.z;
        As[aCol + 3][aRow] = av.w;
        *(float4*)&Bs[bRow][bCol] = bv;
        __syncthreads();

#pragma unroll
        for (int kk = 0; kk < 8; kk++) {
            float a[8], b[8];
#pragma unroll
            for (int i = 0; i < 8; i++) a[i] = As[kk][ty * 8 + i];
#pragma unroll
            for (int j = 0; j < 8; j++) b[j] = Bs[kk][tx * 8 + j];
#pragma unroll
            for (int i = 0; i < 8; i++)
#pragma unroll
                for (int j = 0; j < 8; j++)
                    acc[i][j] = fmaf(a[i], b[j], acc[i][j]);
        }
        __syncthreads();
    }

#pragma unroll
    for (int i = 0; i < 8; i++) {
        const int m = m0 + ty * 8 + i;
#pragma unroll
        for (int j = 0; j < 8; j++) {
            const int n = n0 + tx * 8 + j;
            if (MODE == 0) {
                C[(size_t)m * DD + n] = acc[i][j];
            } else {
                const int b  = m >> 11;       // /T
                const int t  = m & (TT - 1);
                const int h  = n >> 6;        // /HD
                const int hd = n & (HD - 1);
                C[((size_t)((b * HH + h) * TT + t) << 6) + hd] = acc[i][j];
            }
        }
    }
}

// ---------------------------------------------------------------------------
// Forget gate: lf[b,h,t] = clip(logsigmoid(x[b,t,:]@Wf[:,h] + bf[h]), -10, 0)
// one block per (b,t) row; 128 threads; 8 threads per head.
// ---------------------------------------------------------------------------
__global__ __launch_bounds__(128) void forget_kernel(
    const float* __restrict__ x, const float* __restrict__ Wf,
    const float* __restrict__ bf, float* __restrict__ lf)
{
    const int row = blockIdx.x;           // 0..4095  (b*T + t)
    __shared__ float xs[DD];
    for (int i = threadIdx.x; i < DD; i += blockDim.x)
        xs[i] = x[(size_t)row * DD + i];
    __syncthreads();

    const int h = threadIdx.x >> 3;       // 0..15
    const int l8 = threadIdx.x & 7;
    float acc = 0.f;
    for (int d = l8; d < DD; d += 8)
        acc = fmaf(xs[d], Wf[d * HH + h], acc);
#pragma unroll
    for (int off = 1; off < 8; off <<= 1)
        acc += __shfl_xor_sync(0xffffffffu, acc, off);

    if (l8 == 0) {
        float z = acc + bf[h];
        float ls = (z >= 0.f) ? -log1pf(__expf(-z)) : z - log1pf(__expf(z));
        ls = fminf(fmaxf(ls, -10.f), 0.f);
        const int b = row >> 11;
        const int t = row & (TT - 1);
        lf[(size_t)(b * HH + h) * TT + t] = ls;
    }
}

// ---------------------------------------------------------------------------
// In-place inclusive cumsum over T per (b,h); 1 warp per row.
// ---------------------------------------------------------------------------
__global__ __launch_bounds__(32) void cumsum_kernel(float* __restrict__ lf)
{
    const int bh = blockIdx.x;
    const int lane = threadIdx.x;
    float* p = lf + (size_t)bh * TT;
    float carry = 0.f;
    for (int c = 0; c < TT; c += 32) {
        float v = p[c + lane];
#pragma unroll
        for (int off = 1; off < 32; off <<= 1) {
            float n = __shfl_up_sync(0xffffffffu, v, off);
            if (lane >= off) v += n;
        }
        v += carry;
        p[c + lane] = v;
        carry = __shfl_sync(0xffffffffu, v, 31);
    }
}

// ---------------------------------------------------------------------------
// Forgetting attention, flash-style online softmax.
// Grid: (T/64, B*H). 256 threads. Thread (r,g): row r=tid/4, cols g*16..+15.
// ---------------------------------------------------------------------------
struct AttnSmem {
    float Qs[64][68];    // [q-row][hd]     (68 pitch: conflict-free scalar reads)
    float Kts[64][64];   // [hd][k-row]     (transposed K)
    float Vs[64][68];    // [k-row][hd]
    float Ps[64][68];    // [q-row][k-row]
    float cqs[64];
    float cks[64];
};

__global__ __launch_bounds__(256) void attn_kernel(
    const float* __restrict__ Q, const float* __restrict__ K,
    const float* __restrict__ V, const float* __restrict__ C,
    float* __restrict__ O)
{
    extern __shared__ AttnSmem sm[];
    AttnSmem& s = sm[0];

    const int qt = blockIdx.x;            // query tile
    const int bh = blockIdx.y;            // b*H + h
    const float* Qh = Q + (size_t)bh * TT * HD;
    const float* Kh = K + (size_t)bh * TT * HD;
    const float* Vh = V + (size_t)bh * TT * HD;
    const float* ch = C + (size_t)bh * TT;

    const int tid = threadIdx.x;
    const int r = tid >> 2;
    const int g = tid & 3;
    const int q0 = qt * 64;

    // Load Q tile
    {
        const int lr = tid >> 2, c0 = (tid & 3) * 16;
        const float* src = Qh + (size_t)(q0 + lr) * HD + c0;
#pragma unroll
        for (int i = 0; i < 4; i++)
            *(float4*)&s.Qs[lr][c0 + i * 4] = *(const float4*)(src + i * 4);
    }
    if (tid < 64) s.cqs[tid] = ch[q0 + tid];

    float m = -1e30f, l = 0.f;
    float o[16];
#pragma unroll
    for (int j = 0; j < 16; j++) o[j] = 0.f;

    const float cq_pre = ch[q0 + r];   // also read directly (register copy)
    const int qg = q0 + r;

    for (int kt = 0; kt <= qt; kt++) {
        const int k0 = kt * 64;
        __syncthreads();   // protect Kts/Vs/Ps from prior-iteration readers
        {
            const int lr = tid >> 2, c0 = (tid & 3) * 16;
            const float* ksrc = Kh + (size_t)(k0 + lr) * HD + c0;
            const float* vsrc = Vh + (size_t)(k0 + lr) * HD + c0;
#pragma unroll
            for (int i = 0; i < 4; i++) {
                float4 kv = *(const float4*)(ksrc + i * 4);
                s.Kts[c0 + i * 4 + 0][lr] = kv.x;
                s.Kts[c0 + i * 4 + 1][lr] = kv.y;
                s.Kts[c0 + i * 4 + 2][lr] = kv.z;
                s.Kts[c0 + i * 4 + 3][lr] = kv.w;
                *(float4*)&s.Vs[lr][c0 + i * 4] = *(const float4*)(vsrc + i * 4);
            }
        }
        if (tid < 64) s.cks[tid] = ch[k0 + tid];
        __syncthreads();

        // --- S = Q @ K^T ---
        float sc[16];
#pragma unroll
        for (int j = 0; j < 16; j++) sc[j] = 0.f;
#pragma unroll 4
        for (int k = 0; k < 64; k++) {
            const float qv = s.Qs[r][k];
            const float4* kp4 = (const float4*)&s.Kts[k][g * 16];
#pragma unroll
            for (int i = 0; i < 4; i++) {
                float4 kv = kp4[i];
                sc[4*i+0] = fmaf(qv, kv.x, sc[4*i+0]);
                sc[4*i+1] = fmaf(qv, kv.y, sc[4*i+1]);
                sc[4*i+2] = fmaf(qv, kv.z, sc[4*i+2]);
                sc[4*i+3] = fmaf(qv, kv.w, sc[4*i+3]);
            }
        }

        // --- bias + mask + online softmax ---
        const bool diag = (kt == qt);
        float mloc = -1e30f;
#pragma unroll
        for (int j = 0; j < 16; j++) {
            const int cidx = g * 16 + j;
            float decay = fmaxf(cq_pre - s.cks[cidx], -50.f);
            float val = fmaf(sc[j], 0.125f, decay);
            if (diag && (k0 + cidx) > qg) val = -1e30f;
            sc[j] = val;
            mloc = fmaxf(mloc, val);
        }
        mloc = fmaxf(mloc, __shfl_xor_sync(0xffffffffu, mloc, 1));
        mloc = fmaxf(mloc, __shfl_xor_sync(0xffffffffu, mloc, 2));
        const float mnew = fmaxf(m, mloc);
        const float corr = __expf(m - mnew);

        float lloc = 0.f;
#pragma unroll
        for (int j = 0; j < 16; j++) {
            float p = __expf(sc[j] - mnew);
            sc[j] = p;
            lloc += p;
        }
        lloc += __shfl_xor_sync(0xffffffffu, lloc, 1);
        lloc += __shfl_xor_sync(0xffffffffu, lloc, 2);
        l = l * corr + lloc;
        m = mnew;

        // write P tile
#pragma unroll
        for (int i = 0; i < 4; i++)
            *(float4*)&s.Ps[r][g * 16 + i * 4] =
                make_float4(sc[4*i+0], sc[4*i+1], sc[4*i+2], sc[4*i+3]);
#pragma unroll
        for (int j = 0; j < 16; j++) o[j] *= corr;
        __syncthreads();

        // --- O += P @ V ---
#pragma unroll 4
        for (int k = 0; k < 64; k++) {
            const float p = s.Ps[r][k];
            const float4* vp4 = (const float4*)&s.Vs[k][g * 16];
#pragma unroll
            for (int i = 0; i < 4; i++) {
                float4 vv = vp4[i];
                o[4*i+0] = fmaf(p, vv.x, o[4*i+0]);
                o[4*i+1] = fmaf(p, vv.y, o[4*i+1]);
                o[4*i+2] = fmaf(p, vv.z, o[4*i+2]);
                o[4*i+3] = fmaf(p, vv.w, o[4*i+3]);
            }
        }
    }

    // Final write: O[b, t, h*64 + c] = o/l
    const float inv = 1.f / l;
    const int b = bh >> 4, h = bh & 15;
    const int t = q0 + r;
    float* dst = O + ((size_t)(b * TT + t) * DD) + h * HD + g * 16;
#pragma unroll
    for (int j = 0; j < 16; j += 4)
        *(float4*)(dst + j) =
            make_float4(o[j]*inv, o[j+1]*inv, o[j+2]*inv, o[j+3]*inv);
}

// ---------------------------------------------------------------------------
// kernel_launch
// ---------------------------------------------------------------------------
extern "C" void kernel_launch(void* const* d_in, const int* in_sizes, int n_in,
                              void* d_out, int out_size)
{
    (void)in_sizes; (void)n_in; (void)out_size;
    const float* x  = (const float*)d_in[0];
    const float* Wq = (const float*)d_in[1];
    const float* Wk = (const float*)d_in[2];
    const float* Wv = (const float*)d_in[3];
    const float* Wo = (const float*)d_in[4];
    const float* Wf = (const float*)d_in[5];
    const float* bf = (const float*)d_in[6];
    float* out = (float*)d_out;

    float *qp, *kp, *vp, *op, *cp;
    cudaGetSymbolAddress((void**)&qp, g_Q);
    cudaGetSymbolAddress((void**)&kp, g_K);
    cudaGetSymbolAddress((void**)&vp, g_V);
    cudaGetSymbolAddress((void**)&op, g_O);
    cudaGetSymbolAddress((void**)&cp, g_c);

    const int attn_smem = (int)sizeof(AttnSmem);
    cudaFuncSetAttribute(attn_kernel,
                         cudaFuncAttributeMaxDynamicSharedMemorySize, attn_smem);

    dim3 ggrid(DD / 128, MM / 128);   // (8, 32)
    gemm128<1><<<ggrid, 256>>>(x, Wq, qp);
    gemm128<1><<<ggrid, 256>>>(x, Wk, kp);
    gemm128<1><<<ggrid, 256>>>(x, Wv, vp);

    forget_kernel<<<MM, 128>>>(x, Wf, bf, cp);
    cumsum_kernel<<<BB * HH, 32>>>(cp);

    attn_kernel<<<dim3(TT / 64, BB * HH), 256, attn_smem>>>(qp, kp, vp, cp, op);

    gemm128<0><<<ggrid, 256>>>(op, Wo, out);
}

// round 3
// speedup vs baseline: 1.1775x; 1.1775x over previous
#include <cuda_runtime.h>
#include <cuda_bf16.h>
#include <math.h>
#include <stdint.h>

// Problem constants
#define BB 2
#define TT 2048
#define DD 1024
#define HH 16
#define HD 64
#define MM (BB*TT)   // 4096

// ---------------------------------------------------------------------------
// Scratch (device globals; no allocation allowed)
// ---------------------------------------------------------------------------
__device__ float g_Q[MM*DD];   // [B,H,T,HD]
__device__ float g_K[MM*DD];
__device__ float g_V[MM*DD];
__device__ float g_O[MM*DD];   // [B,T,H*HD]
__device__ float g_c[BB*HH*TT];

__device__ __nv_bfloat16 g_xhi[MM*DD], g_xlo[MM*DD];
__device__ __nv_bfloat16 g_ohi[MM*DD], g_olo[MM*DD];
// transposed+split weights: [N=1024][K=1024]
__device__ __nv_bfloat16 g_wqh[DD*DD], g_wql[DD*DD];
__device__ __nv_bfloat16 g_wkh[DD*DD], g_wkl[DD*DD];
__device__ __nv_bfloat16 g_wvh[DD*DD], g_wvl[DD*DD];
__device__ __nv_bfloat16 g_woh[DD*DD], g_wol[DD*DD];

// ---------------------------------------------------------------------------
// PTX helpers (sm_100-safe: cp.async + ldmatrix + mma.sync)
// ---------------------------------------------------------------------------
__device__ __forceinline__ uint32_t smem_u32(const void* p) {
    uint32_t a;
    asm("{ .reg .u64 t; cvta.to.shared.u64 t, %1; cvt.u32.u64 %0, t; }"
        : "=r"(a) : "l"(p));
    return a;
}
__device__ __forceinline__ void cp16(uint32_t dst, const void* src) {
    asm volatile("cp.async.cg.shared.global [%0], [%1], 16;"
                 :: "r"(dst), "l"(src) : "memory");
}
__device__ __forceinline__ void cp_commit() {
    asm volatile("cp.async.commit_group;" ::: "memory");
}
template<int N> __device__ __forceinline__ void cp_wait() {
    asm volatile("cp.async.wait_group %0;" :: "n"(N) : "memory");
}
__device__ __forceinline__ void ldmx4(uint32_t* r, uint32_t addr) {
    asm volatile("ldmatrix.sync.aligned.m8n8.x4.shared.b16 {%0,%1,%2,%3}, [%4];"
                 : "=r"(r[0]), "=r"(r[1]), "=r"(r[2]), "=r"(r[3]) : "r"(addr));
}
__device__ __forceinline__ void mma16816(float* c, const uint32_t* a,
                                         uint32_t b0, uint32_t b1) {
    asm volatile(
        "mma.sync.aligned.m16n8k16.row.col.f32.bf16.bf16.f32 "
        "{%0,%1,%2,%3}, {%4,%5,%6,%7}, {%8,%9}, {%0,%1,%2,%3};"
        : "+f"(c[0]), "+f"(c[1]), "+f"(c[2]), "+f"(c[3])
        : "r"(a[0]), "r"(a[1]), "r"(a[2]), "r"(a[3]), "r"(b0), "r"(b1));
}

// ---------------------------------------------------------------------------
// fp32 -> bf16 (hi, lo) split, elementwise x4
// ---------------------------------------------------------------------------
__global__ __launch_bounds__(256) void split_kernel(
    const float* __restrict__ in, __nv_bfloat16* __restrict__ hi,
    __nv_bfloat16* __restrict__ lo, int n4)
{
    int i = blockIdx.x * blockDim.x + threadIdx.x;
    if (i >= n4) return;
    float4 v = ((const float4*)in)[i];
    __nv_bfloat16 hx = __float2bfloat16(v.x);
    __nv_bfloat16 hy = __float2bfloat16(v.y);
    __nv_bfloat16 hz = __float2bfloat16(v.z);
    __nv_bfloat16 hw = __float2bfloat16(v.w);
    __nv_bfloat16 lx = __float2bfloat16(v.x - __bfloat162float(hx));
    __nv_bfloat16 ly = __float2bfloat16(v.y - __bfloat162float(hy));
    __nv_bfloat16 lz = __float2bfloat16(v.z - __bfloat162float(hz));
    __nv_bfloat16 lw = __float2bfloat16(v.w - __bfloat162float(hw));
    __nv_bfloat162* H = (__nv_bfloat162*)hi;
    __nv_bfloat162* L = (__nv_bfloat162*)lo;
    __nv_bfloat162 a; a.x = hx; a.y = hy;
    __nv_bfloat162 b; b.x = hz; b.y = hw;
    __nv_bfloat162 c; c.x = lx; c.y = ly;
    __nv_bfloat162 d; d.x = lz; d.y = lw;
    H[2*i] = a; H[2*i+1] = b;
    L[2*i] = c; L[2*i+1] = d;
}

// ---------------------------------------------------------------------------
// Weight transpose + split: W[K][N] fp32 -> Wt_hi/lo[N][K] bf16
// ---------------------------------------------------------------------------
__global__ __launch_bounds__(256) void wsplit_kernel(
    const float* __restrict__ W, __nv_bfloat16* __restrict__ Whi,
    __nv_bfloat16* __restrict__ Wlo)
{
    __shared__ float t[32][33];
    const int tx = threadIdx.x, ty = threadIdx.y;
    const int bx = blockIdx.x * 32;   // n tile
    const int by = blockIdx.y * 32;   // k tile
#pragma unroll
    for (int j = 0; j < 32; j += 8)
        t[ty + j][tx] = W[(size_t)(by + ty + j) * DD + bx + tx];
    __syncthreads();
#pragma unroll
    for (int j = 0; j < 32; j += 8) {
        float v = t[tx][ty + j];   // = W[by+tx][bx+ty+j]
        __nv_bfloat16 h = __float2bfloat16(v);
        __nv_bfloat16 l = __float2bfloat16(v - __bfloat162float(h));
        size_t idx = (size_t)(bx + ty + j) * DD + by + tx;
        Whi[idx] = h;
        Wlo[idx] = l;
    }
}

// ---------------------------------------------------------------------------
// HMMA split-bf16 GEMM: C[4096,1024] = A[4096,1024] @ Bt^T   (Bt: [N][K])
// 128x128 CTA tile, BK=32, cp.async double buffer, 8 warps (4 M x 2 N).
// MODE 0: row-major store. MODE 1: [B,H,T,HD] store.
// ---------------------------------------------------------------------------
#define ROWP   80                 // padded row pitch in bytes (32 bf16 + 8 pad)
#define MATB   (128*ROWP)         // 10240 B per matrix tile
#define STAGEB (4*MATB)           // Ahi,Alo,Bhi,Blo
#define GEMM_SMEM (2*STAGEB)      // 81920 B

__device__ __forceinline__ void stage_load(
    uint32_t sbase,
    const __nv_bfloat16* a_hi, const __nv_bfloat16* a_lo,
    const __nv_bfloat16* b_hi, const __nv_bfloat16* b_lo,
    int k0, int tid)
{
    const __nv_bfloat16* bases[4] = { a_hi + k0, a_lo + k0, b_hi + k0, b_lo + k0 };
#pragma unroll
    for (int mat = 0; mat < 4; mat++) {
#pragma unroll
        for (int i = 0; i < 2; i++) {
            int s = tid + i * 256;        // 0..511
            int row = s >> 2;
            int c = s & 3;
            cp16(sbase + mat * MATB + row * ROWP + c * 16,
                 bases[mat] + (size_t)row * DD + c * 8);
        }
    }
}

template<int MODE>
__global__ __launch_bounds__(256) void gemm_mma(
    const __nv_bfloat16* __restrict__ Ahi, const __nv_bfloat16* __restrict__ Alo,
    const __nv_bfloat16* __restrict__ Bhi, const __nv_bfloat16* __restrict__ Blo,
    float* __restrict__ C)
{
    extern __shared__ char smraw[];
    const uint32_t smb = smem_u32(smraw);

    const int tid  = threadIdx.x;
    const int wid  = tid >> 5;
    const int lane = tid & 31;
    const int n0 = blockIdx.x * 128;
    const int m0 = blockIdx.y * 128;
    const int wm = (wid & 3) * 32;     // warp M offset in tile
    const int wn = (wid >> 2) * 64;    // warp N offset in tile

    const __nv_bfloat16* a_hi = Ahi + (size_t)m0 * DD;
    const __nv_bfloat16* a_lo = Alo + (size_t)m0 * DD;
    const __nv_bfloat16* b_hi = Bhi + (size_t)n0 * DD;
    const __nv_bfloat16* b_lo = Blo + (size_t)n0 * DD;

    float acc[2][8][4];
#pragma unroll
    for (int i = 0; i < 2; i++)
#pragma unroll
        for (int j = 0; j < 8; j++)
#pragma unroll
            for (int k = 0; k < 4; k++) acc[i][j][k] = 0.f;

    // ldmatrix lane addressing (precomputed)
    const int a_row = lane & 15;         // row within 16
    const int a_chk = lane >> 4;         // k-half (16B)
    const int b_mat = lane >> 3;
    const int b_row = (b_mat >> 1) * 8 + (lane & 7);   // n within 16
    const int b_chk = b_mat & 1;                        // k-half

    stage_load(smb, a_hi, a_lo, b_hi, b_lo, 0, tid);
    cp_commit();

    for (int it = 0; it < 32; it++) {
        if (it + 1 < 32) {
            stage_load(smb + ((it + 1) & 1) * STAGEB,
                       a_hi, a_lo, b_hi, b_lo, (it + 1) * 32, tid);
            cp_commit();
            cp_wait<1>();
        } else {
            cp_wait<0>();
        }
        __syncthreads();

        const uint32_t sb = smb + (it & 1) * STAGEB;
#pragma unroll
        for (int ks = 0; ks < 2; ks++) {
            uint32_t ah[2][4], al[2][4], bh[4][4], bl[4][4];
#pragma unroll
            for (int mt = 0; mt < 2; mt++) {
                uint32_t ad = sb + (wm + mt * 16 + a_row) * ROWP
                            + ks * 32 + a_chk * 16;
                ldmx4(ah[mt], ad);
                ldmx4(al[mt], ad + MATB);
            }
#pragma unroll
            for (int ng = 0; ng < 4; ng++) {
                uint32_t bd = sb + 2 * MATB
                            + (wn + ng * 16 + b_row) * ROWP
                            + ks * 32 + b_chk * 16;
                ldmx4(bh[ng], bd);
                ldmx4(bl[ng], bd + MATB);
            }
#pragma unroll
            for (int mt = 0; mt < 2; mt++)
#pragma unroll
                for (int ng = 0; ng < 4; ng++)
#pragma unroll
                    for (int h = 0; h < 2; h++) {
                        float* c = acc[mt][ng * 2 + h];
                        mma16816(c, ah[mt], bh[ng][h * 2], bh[ng][h * 2 + 1]);
                        mma16816(c, ah[mt], bl[ng][h * 2], bl[ng][h * 2 + 1]);
                        mma16816(c, al[mt], bh[ng][h * 2], bh[ng][h * 2 + 1]);
                    }
        }
        __syncthreads();
    }

    // Epilogue
    const int r0 = lane >> 2;
    const int cp = (lane & 3) * 2;
#pragma unroll
    for (int mt = 0; mt < 2; mt++) {
#pragma unroll
        for (int nt = 0; nt < 8; nt++) {
            const int m = m0 + wm + mt * 16 + r0;
            const int n = n0 + wn + nt * 8 + cp;
            float* dst0;
            float* dst1;
            if (MODE == 0) {
                dst0 = C + (size_t)m * DD + n;
                dst1 = C + (size_t)(m + 8) * DD + n;
            } else {
                const int b = m >> 11;
                const int t = m & (TT - 1);
                const int h = n >> 6;
                const int hd = n & (HD - 1);
                dst0 = C + ((size_t)((b * HH + h) * TT + t) << 6) + hd;
                dst1 = C + ((size_t)((b * HH + h) * TT + t + 8) << 6) + hd;
            }
            *(float2*)dst0 = make_float2(acc[mt][nt][0], acc[mt][nt][1]);
            *(float2*)dst1 = make_float2(acc[mt][nt][2], acc[mt][nt][3]);
        }
    }
}

// ---------------------------------------------------------------------------
// Forget gate
// ---------------------------------------------------------------------------
__global__ __launch_bounds__(128) void forget_kernel(
    const float* __restrict__ x, const float* __restrict__ Wf,
    const float* __restrict__ bf, float* __restrict__ lf)
{
    const int row = blockIdx.x;
    __shared__ float xs[DD];
    for (int i = threadIdx.x; i < DD; i += blockDim.x)
        xs[i] = x[(size_t)row * DD + i];
    __syncthreads();

    const int h = threadIdx.x >> 3;
    const int l8 = threadIdx.x & 7;
    float acc = 0.f;
    for (int d = l8; d < DD; d += 8)
        acc = fmaf(xs[d], Wf[d * HH + h], acc);
#pragma unroll
    for (int off = 1; off < 8; off <<= 1)
        acc += __shfl_xor_sync(0xffffffffu, acc, off);

    if (l8 == 0) {
        float z = acc + bf[h];
        float ls = (z >= 0.f) ? -log1pf(__expf(-z)) : z - log1pf(__expf(z));
        ls = fminf(fmaxf(ls, -10.f), 0.f);
        const int b = row >> 11;
        const int t = row & (TT - 1);
        lf[(size_t)(b * HH + h) * TT + t] = ls;
    }
}

// ---------------------------------------------------------------------------
// Cumsum over T per (b,h)
// ---------------------------------------------------------------------------
__global__ __launch_bounds__(32) void cumsum_kernel(float* __restrict__ lf)
{
    const int bh = blockIdx.x;
    const int lane = threadIdx.x;
    float* p = lf + (size_t)bh * TT;
    float carry = 0.f;
    for (int c = 0; c < TT; c += 32) {
        float v = p[c + lane];
#pragma unroll
        for (int off = 1; off < 32; off <<= 1) {
            float n = __shfl_up_sync(0xffffffffu, v, off);
            if (lane >= off) v += n;
        }
        v += carry;
        p[c + lane] = v;
        carry = __shfl_sync(0xffffffffu, v, 31);
    }
}

// ---------------------------------------------------------------------------
// Forgetting attention (fp32, flash-style)
// ---------------------------------------------------------------------------
struct AttnSmem {
    float Qs[64][68];
    float Kts[64][64];
    float Vs[64][68];
    float Ps[64][68];
    float cqs[64];
    float cks[64];
};

__global__ __launch_bounds__(256) void attn_kernel(
    const float* __restrict__ Q, const float* __restrict__ K,
    const float* __restrict__ V, const float* __restrict__ C,
    float* __restrict__ O)
{
    extern __shared__ AttnSmem sm[];
    AttnSmem& s = sm[0];

    const int qt = blockIdx.x;
    const int bh = blockIdx.y;
    const float* Qh = Q + (size_t)bh * TT * HD;
    const float* Kh = K + (size_t)bh * TT * HD;
    const float* Vh = V + (size_t)bh * TT * HD;
    const float* ch = C + (size_t)bh * TT;

    const int tid = threadIdx.x;
    const int r = tid >> 2;
    const int g = tid & 3;
    const int q0 = qt * 64;

    {
        const int lr = tid >> 2, c0 = (tid & 3) * 16;
        const float* src = Qh + (size_t)(q0 + lr) * HD + c0;
#pragma unroll
        for (int i = 0; i < 4; i++)
            *(float4*)&s.Qs[lr][c0 + i * 4] = *(const float4*)(src + i * 4);
    }
    if (tid < 64) s.cqs[tid] = ch[q0 + tid];

    float m = -1e30f, l = 0.f;
    float o[16];
#pragma unroll
    for (int j = 0; j < 16; j++) o[j] = 0.f;

    const float cq_pre = ch[q0 + r];
    const int qg = q0 + r;

    for (int kt = 0; kt <= qt; kt++) {
        const int k0 = kt * 64;
        __syncthreads();
        {
            const int lr = tid >> 2, c0 = (tid & 3) * 16;
            const float* ksrc = Kh + (size_t)(k0 + lr) * HD + c0;
            const float* vsrc = Vh + (size_t)(k0 + lr) * HD + c0;
#pragma unroll
            for (int i = 0; i < 4; i++) {
                float4 kv = *(const float4*)(ksrc + i * 4);
                s.Kts[c0 + i * 4 + 0][lr] = kv.x;
                s.Kts[c0 + i * 4 + 1][lr] = kv.y;
                s.Kts[c0 + i * 4 + 2][lr] = kv.z;
                s.Kts[c0 + i * 4 + 3][lr] = kv.w;
                *(float4*)&s.Vs[lr][c0 + i * 4] = *(const float4*)(vsrc + i * 4);
            }
        }
        if (tid < 64) s.cks[tid] = ch[k0 + tid];
        __syncthreads();

        float sc[16];
#pragma unroll
        for (int j = 0; j < 16; j++) sc[j] = 0.f;
#pragma unroll 4
        for (int k = 0; k < 64; k++) {
            const float qv = s.Qs[r][k];
            const float4* kp4 = (const float4*)&s.Kts[k][g * 16];
#pragma unroll
            for (int i = 0; i < 4; i++) {
                float4 kv = kp4[i];
                sc[4*i+0] = fmaf(qv, kv.x, sc[4*i+0]);
                sc[4*i+1] = fmaf(qv, kv.y, sc[4*i+1]);
                sc[4*i+2] = fmaf(qv, kv.z, sc[4*i+2]);
                sc[4*i+3] = fmaf(qv, kv.w, sc[4*i+3]);
            }
        }

        const bool diag = (kt == qt);
        float mloc = -1e30f;
#pragma unroll
        for (int j = 0; j < 16; j++) {
            const int cidx = g * 16 + j;
            float decay = fmaxf(cq_pre - s.cks[cidx], -50.f);
            float val = fmaf(sc[j], 0.125f, decay);
            if (diag && (k0 + cidx) > qg) val = -1e30f;
            sc[j] = val;
            mloc = fmaxf(mloc, val);
        }
        mloc = fmaxf(mloc, __shfl_xor_sync(0xffffffffu, mloc, 1));
        mloc = fmaxf(mloc, __shfl_xor_sync(0xffffffffu, mloc, 2));
        const float mnew = fmaxf(m, mloc);
        const float corr = __expf(m - mnew);

        float lloc = 0.f;
#pragma unroll
        for (int j = 0; j < 16; j++) {
            float p = __expf(sc[j] - mnew);
            sc[j] = p;
            lloc += p;
        }
        lloc += __shfl_xor_sync(0xffffffffu, lloc, 1);
        lloc += __shfl_xor_sync(0xffffffffu, lloc, 2);
        l = l * corr + lloc;
        m = mnew;

#pragma unroll
        for (int i = 0; i < 4; i++)
            *(float4*)&s.Ps[r][g * 16 + i * 4] =
                make_float4(sc[4*i+0], sc[4*i+1], sc[4*i+2], sc[4*i+3]);
#pragma unroll
        for (int j = 0; j < 16; j++) o[j] *= corr;
        __syncthreads();

#pragma unroll 4
        for (int k = 0; k < 64; k++) {
            const float p = s.Ps[r][k];
            const float4* vp4 = (const float4*)&s.Vs[k][g * 16];
#pragma unroll
            for (int i = 0; i < 4; i++) {
                float4 vv = vp4[i];
                o[4*i+0] = fmaf(p, vv.x, o[4*i+0]);
                o[4*i+1] = fmaf(p, vv.y, o[4*i+1]);
                o[4*i+2] = fmaf(p, vv.z, o[4*i+2]);
                o[4*i+3] = fmaf(p, vv.w, o[4*i+3]);
            }
        }
    }

    const float inv = 1.f / l;
    const int b = bh >> 4, h = bh & 15;
    const int t = q0 + r;
    float* dst = O + ((size_t)(b * TT + t) * DD) + h * HD + g * 16;
#pragma unroll
    for (int j = 0; j < 16; j += 4)
        *(float4*)(dst + j) =
            make_float4(o[j]*inv, o[j+1]*inv, o[j+2]*inv, o[j+3]*inv);
}

// ---------------------------------------------------------------------------
// kernel_launch
// ---------------------------------------------------------------------------
extern "C" void kernel_launch(void* const* d_in, const int* in_sizes, int n_in,
                              void* d_out, int out_size)
{
    (void)in_sizes; (void)n_in; (void)out_size;
    const float* x  = (const float*)d_in[0];
    const float* Wq = (const float*)d_in[1];
    const float* Wk = (const float*)d_in[2];
    const float* Wv = (const float*)d_in[3];
    const float* Wo = (const float*)d_in[4];
    const float* Wf = (const float*)d_in[5];
    const float* bf = (const float*)d_in[6];
    float* out = (float*)d_out;

    float *qp, *kp, *vp, *op, *cp;
    cudaGetSymbolAddress((void**)&qp, g_Q);
    cudaGetSymbolAddress((void**)&kp, g_K);
    cudaGetSymbolAddress((void**)&vp, g_V);
    cudaGetSymbolAddress((void**)&op, g_O);
    cudaGetSymbolAddress((void**)&cp, g_c);

    __nv_bfloat16 *xhi, *xlo, *ohi, *olo;
    __nv_bfloat16 *wqh, *wql, *wkh, *wkl, *wvh, *wvl, *woh, *wol;
    cudaGetSymbolAddress((void**)&xhi, g_xhi);
    cudaGetSymbolAddress((void**)&xlo, g_xlo);
    cudaGetSymbolAddress((void**)&ohi, g_ohi);
    cudaGetSymbolAddress((void**)&olo, g_olo);
    cudaGetSymbolAddress((void**)&wqh, g_wqh);
    cudaGetSymbolAddress((void**)&wql, g_wql);
    cudaGetSymbolAddress((void**)&wkh, g_wkh);
    cudaGetSymbolAddress((void**)&wkl, g_wkl);
    cudaGetSymbolAddress((void**)&wvh, g_wvh);
    cudaGetSymbolAddress((void**)&wvl, g_wvl);
    cudaGetSymbolAddress((void**)&woh, g_woh);
    cudaGetSymbolAddress((void**)&wol, g_wol);

    const int attn_smem = (int)sizeof(AttnSmem);
    cudaFuncSetAttribute(attn_kernel,
                         cudaFuncAttributeMaxDynamicSharedMemorySize, attn_smem);
    cudaFuncSetAttribute(gemm_mma<0>,
                         cudaFuncAttributeMaxDynamicSharedMemorySize, GEMM_SMEM);
    cudaFuncSetAttribute(gemm_mma<1>,
                         cudaFuncAttributeMaxDynamicSharedMemorySize, GEMM_SMEM);

    // split inputs
    split_kernel<<<MM*DD/4/256, 256>>>(x, xhi, xlo, MM*DD/4);
    dim3 wgrid(32, 32), wblk(32, 8);
    wsplit_kernel<<<wgrid, wblk>>>(Wq, wqh, wql);
    wsplit_kernel<<<wgrid, wblk>>>(Wk, wkh, wkl);
    wsplit_kernel<<<wgrid, wblk>>>(Wv, wvh, wvl);
    wsplit_kernel<<<wgrid, wblk>>>(Wo, woh, wol);

    // QKV projections on tensor cores (HMMA)
    dim3 ggrid(DD / 128, MM / 128);   // (8, 32)
    gemm_mma<1><<<ggrid, 256, GEMM_SMEM>>>(xhi, xlo, wqh, wql, qp);
    gemm_mma<1><<<ggrid, 256, GEMM_SMEM>>>(xhi, xlo, wkh, wkl, kp);
    gemm_mma<1><<<ggrid, 256, GEMM_SMEM>>>(xhi, xlo, wvh, wvl, vp);

    forget_kernel<<<MM, 128>>>(x, Wf, bf, cp);
    cumsum_kernel<<<BB * HH, 32>>>(cp);

    attn_kernel<<<dim3(TT / 64, BB * HH), 256, attn_smem>>>(qp, kp, vp, cp, op);

    split_kernel<<<MM*DD/4/256, 256>>>(op, ohi, olo, MM*DD/4);
    gemm_mma<0><<<ggrid, 256, GEMM_SMEM>>>(ohi, olo, woh, wol, out);
}

// round 4
// speedup vs baseline: 5.8102x; 4.9344x over previous
#include <cuda_runtime.h>
#include <cuda_bf16.h>
#include <math.h>
#include <stdint.h>

// Problem constants
#define BB 2
#define TT 2048
#define DD 1024
#define HH 16
#define HD 64
#define MM (BB*TT)   // 4096

// ---------------------------------------------------------------------------
// Scratch (device globals; no allocation allowed)
// ---------------------------------------------------------------------------
__device__ float g_c[BB*HH*TT];

__device__ __nv_bfloat16 g_xhi[MM*DD], g_xlo[MM*DD];
// [B,H,T,HD] bf16 splits produced by projection GEMMs
__device__ __nv_bfloat16 g_qhi[MM*DD], g_qlo[MM*DD];
__device__ __nv_bfloat16 g_khi[MM*DD], g_klo[MM*DD];
__device__ __nv_bfloat16 g_vhi[MM*DD], g_vlo[MM*DD];
// attention output splits, row-major [M][D]
__device__ __nv_bfloat16 g_ohi[MM*DD], g_olo[MM*DD];
// transposed+split weights: [N=1024][K=1024]
__device__ __nv_bfloat16 g_wqh[DD*DD], g_wql[DD*DD];
__device__ __nv_bfloat16 g_wkh[DD*DD], g_wkl[DD*DD];
__device__ __nv_bfloat16 g_wvh[DD*DD], g_wvl[DD*DD];
__device__ __nv_bfloat16 g_woh[DD*DD], g_wol[DD*DD];

// ---------------------------------------------------------------------------
// PTX helpers (sm_100-safe: cp.async + ldmatrix + mma.sync)
// ---------------------------------------------------------------------------
__device__ __forceinline__ uint32_t smem_u32(const void* p) {
    uint32_t a;
    asm("{ .reg .u64 t; cvta.to.shared.u64 t, %1; cvt.u32.u64 %0, t; }"
        : "=r"(a) : "l"(p));
    return a;
}
__device__ __forceinline__ void cp16(uint32_t dst, const void* src) {
    asm volatile("cp.async.cg.shared.global [%0], [%1], 16;"
                 :: "r"(dst), "l"(src) : "memory");
}
__device__ __forceinline__ void cp_commit() {
    asm volatile("cp.async.commit_group;" ::: "memory");
}
template<int N> __device__ __forceinline__ void cp_wait() {
    asm volatile("cp.async.wait_group %0;" :: "n"(N) : "memory");
}
__device__ __forceinline__ void ldmx4(uint32_t* r, uint32_t addr) {
    asm volatile("ldmatrix.sync.aligned.m8n8.x4.shared.b16 {%0,%1,%2,%3}, [%4];"
                 : "=r"(r[0]), "=r"(r[1]), "=r"(r[2]), "=r"(r[3]) : "r"(addr));
}
__device__ __forceinline__ void ldmx4t(uint32_t* r, uint32_t addr) {
    asm volatile("ldmatrix.sync.aligned.m8n8.x4.trans.shared.b16 {%0,%1,%2,%3}, [%4];"
                 : "=r"(r[0]), "=r"(r[1]), "=r"(r[2]), "=r"(r[3]) : "r"(addr));
}
__device__ __forceinline__ void mma16816(float* c, const uint32_t* a,
                                         uint32_t b0, uint32_t b1) {
    asm volatile(
        "mma.sync.aligned.m16n8k16.row.col.f32.bf16.bf16.f32 "
        "{%0,%1,%2,%3}, {%4,%5,%6,%7}, {%8,%9}, {%0,%1,%2,%3};"
        : "+f"(c[0]), "+f"(c[1]), "+f"(c[2]), "+f"(c[3])
        : "r"(a[0]), "r"(a[1]), "r"(a[2]), "r"(a[3]), "r"(b0), "r"(b1));
}
__device__ __forceinline__ float ex2f(float x) {
    float r;
    asm("ex2.approx.ftz.f32 %0, %1;" : "=f"(r) : "f"(x));
    return r;
}
__device__ __forceinline__ void pack_split(float a, float b,
                                           uint32_t& hi, uint32_t& lo) {
    __nv_bfloat16 ha = __float2bfloat16(a);
    __nv_bfloat16 hb = __float2bfloat16(b);
    __nv_bfloat16 la = __float2bfloat16(a - __bfloat162float(ha));
    __nv_bfloat16 lb = __float2bfloat16(b - __bfloat162float(hb));
    __nv_bfloat162 H; H.x = ha; H.y = hb;
    __nv_bfloat162 L; L.x = la; L.y = lb;
    hi = *reinterpret_cast<uint32_t*>(&H);
    lo = *reinterpret_cast<uint32_t*>(&L);
}

#define LOG2E 1.44269504088896340736f

// ---------------------------------------------------------------------------
// fp32 -> bf16 (hi, lo) split, elementwise x4
// ---------------------------------------------------------------------------
__global__ __launch_bounds__(256) void split_kernel(
    const float* __restrict__ in, __nv_bfloat16* __restrict__ hi,
    __nv_bfloat16* __restrict__ lo, int n4)
{
    int i = blockIdx.x * blockDim.x + threadIdx.x;
    if (i >= n4) return;
    float4 v = ((const float4*)in)[i];
    uint32_t h0, l0, h1, l1;
    pack_split(v.x, v.y, h0, l0);
    pack_split(v.z, v.w, h1, l1);
    ((uint32_t*)hi)[2*i]   = h0;
    ((uint32_t*)hi)[2*i+1] = h1;
    ((uint32_t*)lo)[2*i]   = l0;
    ((uint32_t*)lo)[2*i+1] = l1;
}

// ---------------------------------------------------------------------------
// Weight transpose + split: W[K][N] fp32 -> Wt_hi/lo[N][K] bf16
// ---------------------------------------------------------------------------
__global__ __launch_bounds__(256) void wsplit_kernel(
    const float* __restrict__ W, __nv_bfloat16* __restrict__ Whi,
    __nv_bfloat16* __restrict__ Wlo)
{
    __shared__ float t[32][33];
    const int tx = threadIdx.x, ty = threadIdx.y;
    const int bx = blockIdx.x * 32;   // n tile
    const int by = blockIdx.y * 32;   // k tile
#pragma unroll
    for (int j = 0; j < 32; j += 8)
        t[ty + j][tx] = W[(size_t)(by + ty + j) * DD + bx + tx];
    __syncthreads();
#pragma unroll
    for (int j = 0; j < 32; j += 8) {
        float v = t[tx][ty + j];   // = W[by+tx][bx+ty+j]
        __nv_bfloat16 h = __float2bfloat16(v);
        __nv_bfloat16 l = __float2bfloat16(v - __bfloat162float(h));
        size_t idx = (size_t)(bx + ty + j) * DD + by + tx;
        Whi[idx] = h;
        Wlo[idx] = l;
    }
}

// ---------------------------------------------------------------------------
// HMMA split-bf16 GEMM: C = A[4096,1024] @ Bt^T  (Bt: [N][K])
// MODE 0: fp32 row-major store (final output).
// MODE 1: bf16 hi/lo split store in [B,H,T,HD] layout (Q/K/V).
// ---------------------------------------------------------------------------
#define ROWP   80
#define MATB   (128*ROWP)
#define STAGEB (4*MATB)
#define GEMM_SMEM (2*STAGEB)

__device__ __forceinline__ void stage_load(
    uint32_t sbase,
    const __nv_bfloat16* a_hi, const __nv_bfloat16* a_lo,
    const __nv_bfloat16* b_hi, const __nv_bfloat16* b_lo,
    int k0, int tid)
{
    const __nv_bfloat16* bases[4] = { a_hi + k0, a_lo + k0, b_hi + k0, b_lo + k0 };
#pragma unroll
    for (int mat = 0; mat < 4; mat++) {
#pragma unroll
        for (int i = 0; i < 2; i++) {
            int s = tid + i * 256;
            int row = s >> 2;
            int c = s & 3;
            cp16(sbase + mat * MATB + row * ROWP + c * 16,
                 bases[mat] + (size_t)row * DD + c * 8);
        }
    }
}

template<int MODE>
__global__ __launch_bounds__(256) void gemm_mma(
    const __nv_bfloat16* __restrict__ Ahi, const __nv_bfloat16* __restrict__ Alo,
    const __nv_bfloat16* __restrict__ Bhi, const __nv_bfloat16* __restrict__ Blo,
    float* __restrict__ Cf,
    __nv_bfloat16* __restrict__ Chi, __nv_bfloat16* __restrict__ Clo)
{
    extern __shared__ char smraw[];
    const uint32_t smb = smem_u32(smraw);

    const int tid  = threadIdx.x;
    const int wid  = tid >> 5;
    const int lane = tid & 31;
    const int n0 = blockIdx.x * 128;
    const int m0 = blockIdx.y * 128;
    const int wm = (wid & 3) * 32;
    const int wn = (wid >> 2) * 64;

    const __nv_bfloat16* a_hi = Ahi + (size_t)m0 * DD;
    const __nv_bfloat16* a_lo = Alo + (size_t)m0 * DD;
    const __nv_bfloat16* b_hi = Bhi + (size_t)n0 * DD;
    const __nv_bfloat16* b_lo = Blo + (size_t)n0 * DD;

    float acc[2][8][4];
#pragma unroll
    for (int i = 0; i < 2; i++)
#pragma unroll
        for (int j = 0; j < 8; j++)
#pragma unroll
            for (int k = 0; k < 4; k++) acc[i][j][k] = 0.f;

    const int a_row = lane & 15;
    const int a_chk = lane >> 4;
    const int b_mat = lane >> 3;
    const int b_row = (b_mat >> 1) * 8 + (lane & 7);
    const int b_chk = b_mat & 1;

    stage_load(smb, a_hi, a_lo, b_hi, b_lo, 0, tid);
    cp_commit();

    for (int it = 0; it < 32; it++) {
        if (it + 1 < 32) {
            stage_load(smb + ((it + 1) & 1) * STAGEB,
                       a_hi, a_lo, b_hi, b_lo, (it + 1) * 32, tid);
            cp_commit();
            cp_wait<1>();
        } else {
            cp_wait<0>();
        }
        __syncthreads();

        const uint32_t sb = smb + (it & 1) * STAGEB;
#pragma unroll
        for (int ks = 0; ks < 2; ks++) {
            uint32_t ah[2][4], al[2][4], bh[4][4], bl[4][4];
#pragma unroll
            for (int mt = 0; mt < 2; mt++) {
                uint32_t ad = sb + (wm + mt * 16 + a_row) * ROWP
                            + ks * 32 + a_chk * 16;
                ldmx4(ah[mt], ad);
                ldmx4(al[mt], ad + MATB);
            }
#pragma unroll
            for (int ng = 0; ng < 4; ng++) {
                uint32_t bd = sb + 2 * MATB
                            + (wn + ng * 16 + b_row) * ROWP
                            + ks * 32 + b_chk * 16;
                ldmx4(bh[ng], bd);
                ldmx4(bl[ng], bd + MATB);
            }
#pragma unroll
            for (int mt = 0; mt < 2; mt++)
#pragma unroll
                for (int ng = 0; ng < 4; ng++)
#pragma unroll
                    for (int h = 0; h < 2; h++) {
                        float* c = acc[mt][ng * 2 + h];
                        mma16816(c, ah[mt], bh[ng][h * 2], bh[ng][h * 2 + 1]);
                        mma16816(c, ah[mt], bl[ng][h * 2], bl[ng][h * 2 + 1]);
                        mma16816(c, al[mt], bh[ng][h * 2], bh[ng][h * 2 + 1]);
                    }
        }
        __syncthreads();
    }

    // Epilogue
    const int r0 = lane >> 2;
    const int cpair = (lane & 3) * 2;
#pragma unroll
    for (int mt = 0; mt < 2; mt++) {
#pragma unroll
        for (int nt = 0; nt < 8; nt++) {
            const int m = m0 + wm + mt * 16 + r0;
            const int n = n0 + wn + nt * 8 + cpair;
            if (MODE == 0) {
                float* dst0 = Cf + (size_t)m * DD + n;
                float* dst1 = Cf + (size_t)(m + 8) * DD + n;
                *(float2*)dst0 = make_float2(acc[mt][nt][0], acc[mt][nt][1]);
                *(float2*)dst1 = make_float2(acc[mt][nt][2], acc[mt][nt][3]);
            } else {
                const int b = m >> 11;
                const int t = m & (TT - 1);
                const int h = n >> 6;
                const int hd = n & (HD - 1);
                size_t i0 = ((size_t)((b * HH + h) * TT + t) << 6) + hd;
                size_t i1 = i0 + (size_t)(8 << 6);
                uint32_t h0, l0, h1, l1;
                pack_split(acc[mt][nt][0], acc[mt][nt][1], h0, l0);
                pack_split(acc[mt][nt][2], acc[mt][nt][3], h1, l1);
                *(uint32_t*)(Chi + i0) = h0;
                *(uint32_t*)(Clo + i0) = l0;
                *(uint32_t*)(Chi + i1) = h1;
                *(uint32_t*)(Clo + i1) = l1;
            }
        }
    }
}

// ---------------------------------------------------------------------------
// Forget gate
// ---------------------------------------------------------------------------
__global__ __launch_bounds__(128) void forget_kernel(
    const float* __restrict__ x, const float* __restrict__ Wf,
    const float* __restrict__ bf, float* __restrict__ lf)
{
    const int row = blockIdx.x;
    __shared__ float xs[DD];
    for (int i = threadIdx.x; i < DD; i += blockDim.x)
        xs[i] = x[(size_t)row * DD + i];
    __syncthreads();

    const int h = threadIdx.x >> 3;
    const int l8 = threadIdx.x & 7;
    float acc = 0.f;
    for (int d = l8; d < DD; d += 8)
        acc = fmaf(xs[d], Wf[d * HH + h], acc);
#pragma unroll
    for (int off = 1; off < 8; off <<= 1)
        acc += __shfl_xor_sync(0xffffffffu, acc, off);

    if (l8 == 0) {
        float z = acc + bf[h];
        float ls = (z >= 0.f) ? -log1pf(__expf(-z)) : z - log1pf(__expf(z));
        ls = fminf(fmaxf(ls, -10.f), 0.f);
        const int b = row >> 11;
        const int t = row & (TT - 1);
        lf[(size_t)(b * HH + h) * TT + t] = ls;
    }
}

// ---------------------------------------------------------------------------
// Cumsum over T per (b,h)
// ---------------------------------------------------------------------------
__global__ __launch_bounds__(32) void cumsum_kernel(float* __restrict__ lf)
{
    const int bh = blockIdx.x;
    const int lane = threadIdx.x;
    float* p = lf + (size_t)bh * TT;
    float carry = 0.f;
    for (int c = 0; c < TT; c += 32) {
        float v = p[c + lane];
#pragma unroll
        for (int off = 1; off < 32; off <<= 1) {
            float n = __shfl_up_sync(0xffffffffu, v, off);
            if (lane >= off) v += n;
        }
        v += carry;
        p[c + lane] = v;
        carry = __shfl_sync(0xffffffffu, v, 31);
    }
}

// ---------------------------------------------------------------------------
// HMMA forgetting attention (FA2 style, split-bf16).
// Block: 64 q-rows, 4 warps (m16 each). K-tile = 64. Double-buffered cp.async.
// smem tile: 64 rows x 128B, XOR-swizzled 16B chunks.
// ---------------------------------------------------------------------------
#define ATILE  8192                 // 64*128
#define ACKS   (4*ATILE)            // cks offset inside stage
#define ASTAGE (4*ATILE + 256)      // Khi,Klo,Vhi,Vlo + cks(64 f32)
#define AQOFF  (2*ASTAGE)           // Q hi/lo area
#define ATTN_SMEM (2*ASTAGE + 2*ATILE)   // 82432

__device__ __forceinline__ uint32_t asw(int row, int chunk) {
    return (uint32_t)(row * 128 + ((chunk ^ (row & 7)) * 16));
}

__device__ __forceinline__ void attn_stage(
    uint32_t sb,
    const __nv_bfloat16* Kh, const __nv_bfloat16* Kl,
    const __nv_bfloat16* Vh, const __nv_bfloat16* Vl,
    const float* cptr, int k0, int tid)
{
    const __nv_bfloat16* mats[4] = {
        Kh + (size_t)k0 * HD, Kl + (size_t)k0 * HD,
        Vh + (size_t)k0 * HD, Vl + (size_t)k0 * HD };
#pragma unroll
    for (int mt = 0; mt < 4; mt++) {
#pragma unroll
        for (int i = 0; i < 4; i++) {
            int s = tid + i * 128;
            int row = s >> 3, c = s & 7;
            cp16(sb + mt * ATILE + asw(row, c), mats[mt] + row * HD + c * 8);
        }
    }
    if (tid < 16) cp16(sb + ACKS + tid * 16, cptr + k0 + tid * 4);
}

__global__ __launch_bounds__(128) void attn_mma(
    const __nv_bfloat16* __restrict__ Qhi, const __nv_bfloat16* __restrict__ Qlo,
    const __nv_bfloat16* __restrict__ Khi, const __nv_bfloat16* __restrict__ Klo,
    const __nv_bfloat16* __restrict__ Vhi, const __nv_bfloat16* __restrict__ Vlo,
    const float* __restrict__ C,
    __nv_bfloat16* __restrict__ Ohi, __nv_bfloat16* __restrict__ Olo)
{
    extern __shared__ char smraw[];
    const uint32_t smb = smem_u32(smraw);

    const int tid  = threadIdx.x;
    const int wid  = tid >> 5;
    const int lane = tid & 31;
    const int qt = blockIdx.x;
    const int bh = blockIdx.y;
    const int q0 = qt * 64;

    const __nv_bfloat16* Qh = Qhi + (size_t)bh * TT * HD;
    const __nv_bfloat16* Ql = Qlo + (size_t)bh * TT * HD;
    const __nv_bfloat16* Kh = Khi + (size_t)bh * TT * HD;
    const __nv_bfloat16* Kl = Klo + (size_t)bh * TT * HD;
    const __nv_bfloat16* Vh = Vhi + (size_t)bh * TT * HD;
    const __nv_bfloat16* Vl = Vlo + (size_t)bh * TT * HD;
    const float* cptr = C + (size_t)bh * TT;

    // ---- load Q tile (hi+lo) into smem and pick up fragments ----
#pragma unroll
    for (int i = 0; i < 8; i++) {
        int s = tid + i * 128;          // 0..1023; mat = s>>9
        int mat = s >> 9;
        int rc = s & 511;
        int row = rc >> 3, c = rc & 7;
        const __nv_bfloat16* src = (mat == 0 ? Qh : Ql);
        cp16(smb + AQOFF + mat * ATILE + asw(row, c),
             src + (size_t)(q0 + row) * HD + c * 8);
    }
    cp_commit();
    cp_wait<0>();
    __syncthreads();

    const int a_row = lane & 15;
    const int a_chk = lane >> 4;
    uint32_t qh[4][4], ql[4][4];
#pragma unroll
    for (int ks = 0; ks < 4; ks++) {
        uint32_t ad = smb + AQOFF + asw(wid * 16 + a_row, ks * 2 + a_chk);
        ldmx4(qh[ks], ad);
        ldmx4(ql[ks], ad + ATILE);
    }

    const int r0 = wid * 16 + (lane >> 2);          // local q row (first)
    const float cq0 = cptr[q0 + r0];
    const float cq1 = cptr[q0 + r0 + 8];

    float m0 = -1e30f, m1 = -1e30f, l0 = 0.f, l1 = 0.f;
    float o[8][4];
#pragma unroll
    for (int i = 0; i < 8; i++)
#pragma unroll
        for (int j = 0; j < 4; j++) o[i][j] = 0.f;

    const int b_mat = lane >> 3;
    const int b_row = (b_mat >> 1) * 8 + (lane & 7);
    const int b_chk = b_mat & 1;
    const int v_g = lane >> 3;
    const int v_r = lane & 7;

    attn_stage(smb, Kh, Kl, Vh, Vl, cptr, 0, tid);
    cp_commit();

    for (int kt = 0; kt <= qt; kt++) {
        if (kt < qt) {
            attn_stage(smb + ((kt + 1) & 1) * ASTAGE,
                       Kh, Kl, Vh, Vl, cptr, (kt + 1) * 64, tid);
            cp_commit();
            cp_wait<1>();
        } else {
            cp_wait<0>();
        }
        __syncthreads();

        const uint32_t sb = smb + (kt & 1) * ASTAGE;
        const float* cks = (const float*)(smraw + (kt & 1) * ASTAGE + ACKS);

        // ---- S = Q K^T (3-product split) ----
        float s[8][4];
#pragma unroll
        for (int i = 0; i < 8; i++)
#pragma unroll
            for (int j = 0; j < 4; j++) s[i][j] = 0.f;

#pragma unroll
        for (int ks = 0; ks < 4; ks++) {
            uint32_t kh[4][4], kl[4][4];
#pragma unroll
            for (int ng = 0; ng < 4; ng++) {
                uint32_t bd = sb + asw(ng * 16 + b_row, ks * 2 + b_chk);
                ldmx4(kh[ng], bd);
                ldmx4(kl[ng], bd + ATILE);
            }
#pragma unroll
            for (int ng = 0; ng < 4; ng++)
#pragma unroll
                for (int h = 0; h < 2; h++) {
                    float* c = s[ng * 2 + h];
                    mma16816(c, qh[ks], kh[ng][h * 2], kh[ng][h * 2 + 1]);
                    mma16816(c, qh[ks], kl[ng][h * 2], kl[ng][h * 2 + 1]);
                    mma16816(c, ql[ks], kh[ng][h * 2], kh[ng][h * 2 + 1]);
                }
        }

        // ---- decay bias + causal mask ----
        const bool diag = (kt == qt);
        const int k0g = kt * 64;
#pragma unroll
        for (int nt = 0; nt < 8; nt++) {
            const int col = nt * 8 + (lane & 3) * 2;
            const float ck0 = cks[col], ck1 = cks[col + 1];
            float d00 = fmaxf(cq0 - ck0, -50.f);
            float d01 = fmaxf(cq0 - ck1, -50.f);
            float d10 = fmaxf(cq1 - ck0, -50.f);
            float d11 = fmaxf(cq1 - ck1, -50.f);
            s[nt][0] = fmaf(s[nt][0], 0.125f, d00);
            s[nt][1] = fmaf(s[nt][1], 0.125f, d01);
            s[nt][2] = fmaf(s[nt][2], 0.125f, d10);
            s[nt][3] = fmaf(s[nt][3], 0.125f, d11);
            if (diag) {
                if (k0g + col     > q0 + r0)     s[nt][0] = -1e30f;
                if (k0g + col + 1 > q0 + r0)     s[nt][1] = -1e30f;
                if (k0g + col     > q0 + r0 + 8) s[nt][2] = -1e30f;
                if (k0g + col + 1 > q0 + r0 + 8) s[nt][3] = -1e30f;
            }
        }

        // ---- online softmax ----
        float ml0 = -1e30f, ml1 = -1e30f;
#pragma unroll
        for (int nt = 0; nt < 8; nt++) {
            ml0 = fmaxf(ml0, fmaxf(s[nt][0], s[nt][1]));
            ml1 = fmaxf(ml1, fmaxf(s[nt][2], s[nt][3]));
        }
        ml0 = fmaxf(ml0, __shfl_xor_sync(0xffffffffu, ml0, 1));
        ml0 = fmaxf(ml0, __shfl_xor_sync(0xffffffffu, ml0, 2));
        ml1 = fmaxf(ml1, __shfl_xor_sync(0xffffffffu, ml1, 1));
        ml1 = fmaxf(ml1, __shfl_xor_sync(0xffffffffu, ml1, 2));
        const float mn0 = fmaxf(m0, ml0);
        const float mn1 = fmaxf(m1, ml1);
        const float corr0 = ex2f((m0 - mn0) * LOG2E);
        const float corr1 = ex2f((m1 - mn1) * LOG2E);
        m0 = mn0; m1 = mn1;

        float sum0 = 0.f, sum1 = 0.f;
#pragma unroll
        for (int nt = 0; nt < 8; nt++) {
            s[nt][0] = ex2f((s[nt][0] - mn0) * LOG2E);
            s[nt][1] = ex2f((s[nt][1] - mn0) * LOG2E);
            s[nt][2] = ex2f((s[nt][2] - mn1) * LOG2E);
            s[nt][3] = ex2f((s[nt][3] - mn1) * LOG2E);
            sum0 += s[nt][0] + s[nt][1];
            sum1 += s[nt][2] + s[nt][3];
        }
        l0 = l0 * corr0 + sum0;
        l1 = l1 * corr1 + sum1;
#pragma unroll
        for (int nt = 0; nt < 8; nt++) {
            o[nt][0] *= corr0; o[nt][1] *= corr0;
            o[nt][2] *= corr1; o[nt][3] *= corr1;
        }

        // ---- pack P (hi/lo) into A fragments ----
        uint32_t ph[4][4], pl[4][4];
#pragma unroll
        for (int kc = 0; kc < 4; kc++) {
            pack_split(s[kc*2][0],   s[kc*2][1],   ph[kc][0], pl[kc][0]);
            pack_split(s[kc*2][2],   s[kc*2][3],   ph[kc][1], pl[kc][1]);
            pack_split(s[kc*2+1][0], s[kc*2+1][1], ph[kc][2], pl[kc][2]);
            pack_split(s[kc*2+1][2], s[kc*2+1][3], ph[kc][3], pl[kc][3]);
        }

        // ---- O += P V (3-product split), V via ldmatrix.trans ----
#pragma unroll
        for (int kc = 0; kc < 4; kc++) {
            uint32_t vh[4][4], vl[4][4];
#pragma unroll
            for (int p = 0; p < 4; p++) {
                int row = kc * 16 + (v_g & 1) * 8 + v_r;
                int chunk = p * 2 + (v_g >> 1);
                uint32_t vd = sb + 2 * ATILE + asw(row, chunk);
                ldmx4t(vh[p], vd);
                ldmx4t(vl[p], vd + ATILE);
            }
#pragma unroll
            for (int p = 0; p < 4; p++)
#pragma unroll
                for (int h = 0; h < 2; h++) {
                    float* c = o[p * 2 + h];
                    mma16816(c, ph[kc], vh[p][h * 2], vh[p][h * 2 + 1]);
                    mma16816(c, ph[kc], vl[p][h * 2], vl[p][h * 2 + 1]);
                    mma16816(c, pl[kc], vh[p][h * 2], vh[p][h * 2 + 1]);
                }
        }
        __syncthreads();
    }

    // ---- finalize + store O hi/lo ----
    l0 += __shfl_xor_sync(0xffffffffu, l0, 1);
    l0 += __shfl_xor_sync(0xffffffffu, l0, 2);
    l1 += __shfl_xor_sync(0xffffffffu, l1, 1);
    l1 += __shfl_xor_sync(0xffffffffu, l1, 2);
    const float inv0 = 1.f / l0;
    const float inv1 = 1.f / l1;

    const int b = bh >> 4, h = bh & 15;
    const int t0 = q0 + r0;
    size_t base0 = ((size_t)(b * TT + t0)) * DD + h * HD;
    size_t base1 = base0 + (size_t)8 * DD;
#pragma unroll
    for (int nt = 0; nt < 8; nt++) {
        const int col = nt * 8 + (lane & 3) * 2;
        uint32_t h0, lo0, h1, lo1;
        pack_split(o[nt][0] * inv0, o[nt][1] * inv0, h0, lo0);
        pack_split(o[nt][2] * inv1, o[nt][3] * inv1, h1, lo1);
        *(uint32_t*)(Ohi + base0 + col) = h0;
        *(uint32_t*)(Olo + base0 + col) = lo0;
        *(uint32_t*)(Ohi + base1 + col) = h1;
        *(uint32_t*)(Olo + base1 + col) = lo1;
    }
}

// ---------------------------------------------------------------------------
// kernel_launch
// ---------------------------------------------------------------------------
extern "C" void kernel_launch(void* const* d_in, const int* in_sizes, int n_in,
                              void* d_out, int out_size)
{
    (void)in_sizes; (void)n_in; (void)out_size;
    const float* x  = (const float*)d_in[0];
    const float* Wq = (const float*)d_in[1];
    const float* Wk = (const float*)d_in[2];
    const float* Wv = (const float*)d_in[3];
    const float* Wo = (const float*)d_in[4];
    const float* Wf = (const float*)d_in[5];
    const float* bf = (const float*)d_in[6];
    float* out = (float*)d_out;

    float* cp;
    cudaGetSymbolAddress((void**)&cp, g_c);

    __nv_bfloat16 *xhi, *xlo, *ohi, *olo;
    __nv_bfloat16 *qhi, *qlo, *khi, *klo, *vhi, *vlo;
    __nv_bfloat16 *wqh, *wql, *wkh, *wkl, *wvh, *wvl, *woh, *wol;
    cudaGetSymbolAddress((void**)&xhi, g_xhi);
    cudaGetSymbolAddress((void**)&xlo, g_xlo);
    cudaGetSymbolAddress((void**)&ohi, g_ohi);
    cudaGetSymbolAddress((void**)&olo, g_olo);
    cudaGetSymbolAddress((void**)&qhi, g_qhi);
    cudaGetSymbolAddress((void**)&qlo, g_qlo);
    cudaGetSymbolAddress((void**)&khi, g_khi);
    cudaGetSymbolAddress((void**)&klo, g_klo);
    cudaGetSymbolAddress((void**)&vhi, g_vhi);
    cudaGetSymbolAddress((void**)&vlo, g_vlo);
    cudaGetSymbolAddress((void**)&wqh, g_wqh);
    cudaGetSymbolAddress((void**)&wql, g_wql);
    cudaGetSymbolAddress((void**)&wkh, g_wkh);
    cudaGetSymbolAddress((void**)&wkl, g_wkl);
    cudaGetSymbolAddress((void**)&wvh, g_wvh);
    cudaGetSymbolAddress((void**)&wvl, g_wvl);
    cudaGetSymbolAddress((void**)&woh, g_woh);
    cudaGetSymbolAddress((void**)&wol, g_wol);

    cudaFuncSetAttribute(gemm_mma<0>,
                         cudaFuncAttributeMaxDynamicSharedMemorySize, GEMM_SMEM);
    cudaFuncSetAttribute(gemm_mma<1>,
                         cudaFuncAttributeMaxDynamicSharedMemorySize, GEMM_SMEM);
    cudaFuncSetAttribute(attn_mma,
                         cudaFuncAttributeMaxDynamicSharedMemorySize, ATTN_SMEM);

    split_kernel<<<MM*DD/4/256, 256>>>(x, xhi, xlo, MM*DD/4);
    dim3 wgrid(32, 32), wblk(32, 8);
    wsplit_kernel<<<wgrid, wblk>>>(Wq, wqh, wql);
    wsplit_kernel<<<wgrid, wblk>>>(Wk, wkh, wkl);
    wsplit_kernel<<<wgrid, wblk>>>(Wv, wvh, wvl);
    wsplit_kernel<<<wgrid, wblk>>>(Wo, woh, wol);

    dim3 ggrid(DD / 128, MM / 128);
    gemm_mma<1><<<ggrid, 256, GEMM_SMEM>>>(xhi, xlo, wqh, wql, nullptr, qhi, qlo);
    gemm_mma<1><<<ggrid, 256, GEMM_SMEM>>>(xhi, xlo, wkh, wkl, nullptr, khi, klo);
    gemm_mma<1><<<ggrid, 256, GEMM_SMEM>>>(xhi, xlo, wvh, wvl, nullptr, vhi, vlo);

    forget_kernel<<<MM, 128>>>(x, Wf, bf, cp);
    cumsum_kernel<<<BB * HH, 32>>>(cp);

    attn_mma<<<dim3(TT / 64, BB * HH), 128, ATTN_SMEM>>>(
        qhi, qlo, khi, klo, vhi, vlo, cp, ohi, olo);

    gemm_mma<0><<<ggrid, 256, GEMM_SMEM>>>(ohi, olo, woh, wol, out, nullptr, nullptr);
}

// round 5
// speedup vs baseline: 7.2481x; 1.2475x over previous
#include <cuda_runtime.h>
#include <cuda_bf16.h>
#include <math.h>
#include <stdint.h>

// Problem constants
#define BB 2
#define TT 2048
#define DD 1024
#define HH 16
#define HD 64
#define MM (BB*TT)   // 4096

// ---------------------------------------------------------------------------
// Scratch (device globals; no allocation allowed)
// ---------------------------------------------------------------------------
__device__ float g_c[BB*HH*TT];

__device__ __nv_bfloat16 g_xhi[MM*DD], g_xlo[MM*DD];
__device__ __nv_bfloat16 g_qhi[MM*DD], g_qlo[MM*DD];
__device__ __nv_bfloat16 g_khi[MM*DD], g_klo[MM*DD];
__device__ __nv_bfloat16 g_vhi[MM*DD], g_vlo[MM*DD];
__device__ __nv_bfloat16 g_ohi[MM*DD], g_olo[MM*DD];
__device__ __nv_bfloat16 g_wqh[DD*DD], g_wql[DD*DD];
__device__ __nv_bfloat16 g_wkh[DD*DD], g_wkl[DD*DD];
__device__ __nv_bfloat16 g_wvh[DD*DD], g_wvl[DD*DD];
__device__ __nv_bfloat16 g_woh[DD*DD], g_wol[DD*DD];

// ---------------------------------------------------------------------------
// PTX helpers (sm_100-safe: cp.async + ldmatrix + mma.sync)
// ---------------------------------------------------------------------------
__device__ __forceinline__ uint32_t smem_u32(const void* p) {
    uint32_t a;
    asm("{ .reg .u64 t; cvta.to.shared.u64 t, %1; cvt.u32.u64 %0, t; }"
        : "=r"(a) : "l"(p));
    return a;
}
__device__ __forceinline__ void cp16(uint32_t dst, const void* src) {
    asm volatile("cp.async.cg.shared.global [%0], [%1], 16;"
                 :: "r"(dst), "l"(src) : "memory");
}
__device__ __forceinline__ void cp_commit() {
    asm volatile("cp.async.commit_group;" ::: "memory");
}
template<int N> __device__ __forceinline__ void cp_wait() {
    asm volatile("cp.async.wait_group %0;" :: "n"(N) : "memory");
}
__device__ __forceinline__ void ldmx4(uint32_t* r, uint32_t addr) {
    asm volatile("ldmatrix.sync.aligned.m8n8.x4.shared.b16 {%0,%1,%2,%3}, [%4];"
                 : "=r"(r[0]), "=r"(r[1]), "=r"(r[2]), "=r"(r[3]) : "r"(addr));
}
__device__ __forceinline__ void ldmx4t(uint32_t* r, uint32_t addr) {
    asm volatile("ldmatrix.sync.aligned.m8n8.x4.trans.shared.b16 {%0,%1,%2,%3}, [%4];"
                 : "=r"(r[0]), "=r"(r[1]), "=r"(r[2]), "=r"(r[3]) : "r"(addr));
}
__device__ __forceinline__ void mma16816(float* c, const uint32_t* a,
                                         uint32_t b0, uint32_t b1) {
    asm volatile(
        "mma.sync.aligned.m16n8k16.row.col.f32.bf16.bf16.f32 "
        "{%0,%1,%2,%3}, {%4,%5,%6,%7}, {%8,%9}, {%0,%1,%2,%3};"
        : "+f"(c[0]), "+f"(c[1]), "+f"(c[2]), "+f"(c[3])
        : "r"(a[0]), "r"(a[1]), "r"(a[2]), "r"(a[3]), "r"(b0), "r"(b1));
}
__device__ __forceinline__ float ex2f(float x) {
    float r;
    asm("ex2.approx.ftz.f32 %0, %1;" : "=f"(r) : "f"(x));
    return r;
}
__device__ __forceinline__ void pack_split(float a, float b,
                                           uint32_t& hi, uint32_t& lo) {
    __nv_bfloat16 ha = __float2bfloat16(a);
    __nv_bfloat16 hb = __float2bfloat16(b);
    __nv_bfloat16 la = __float2bfloat16(a - __bfloat162float(ha));
    __nv_bfloat16 lb = __float2bfloat16(b - __bfloat162float(hb));
    __nv_bfloat162 H; H.x = ha; H.y = hb;
    __nv_bfloat162 L; L.x = la; L.y = lb;
    hi = *reinterpret_cast<uint32_t*>(&H);
    lo = *reinterpret_cast<uint32_t*>(&L);
}

#define LOG2E 1.44269504088896340736f

// ---------------------------------------------------------------------------
// fp32 -> bf16 (hi, lo) split, elementwise x4
// ---------------------------------------------------------------------------
__global__ __launch_bounds__(256) void split_kernel(
    const float* __restrict__ in, __nv_bfloat16* __restrict__ hi,
    __nv_bfloat16* __restrict__ lo, int n4)
{
    int i = blockIdx.x * blockDim.x + threadIdx.x;
    if (i >= n4) return;
    float4 v = ((const float4*)in)[i];
    uint32_t h0, l0, h1, l1;
    pack_split(v.x, v.y, h0, l0);
    pack_split(v.z, v.w, h1, l1);
    ((uint32_t*)hi)[2*i]   = h0;
    ((uint32_t*)hi)[2*i+1] = h1;
    ((uint32_t*)lo)[2*i]   = l0;
    ((uint32_t*)lo)[2*i+1] = l1;
}

// ---------------------------------------------------------------------------
// Weight transpose + split: W[K][N] fp32 -> Wt_hi/lo[N][K] bf16
// ---------------------------------------------------------------------------
__global__ __launch_bounds__(256) void wsplit_kernel(
    const float* __restrict__ W, __nv_bfloat16* __restrict__ Whi,
    __nv_bfloat16* __restrict__ Wlo)
{
    __shared__ float t[32][33];
    const int tx = threadIdx.x, ty = threadIdx.y;
    const int bx = blockIdx.x * 32;
    const int by = blockIdx.y * 32;
#pragma unroll
    for (int j = 0; j < 32; j += 8)
        t[ty + j][tx] = W[(size_t)(by + ty + j) * DD + bx + tx];
    __syncthreads();
#pragma unroll
    for (int j = 0; j < 32; j += 8) {
        float v = t[tx][ty + j];
        __nv_bfloat16 h = __float2bfloat16(v);
        __nv_bfloat16 l = __float2bfloat16(v - __bfloat162float(h));
        size_t idx = (size_t)(bx + ty + j) * DD + by + tx;
        Whi[idx] = h;
        Wlo[idx] = l;
    }
}

// ---------------------------------------------------------------------------
// HMMA split-bf16 GEMM (unchanged from R4)
// ---------------------------------------------------------------------------
#define ROWP   80
#define MATB   (128*ROWP)
#define STAGEB (4*MATB)
#define GEMM_SMEM (2*STAGEB)

__device__ __forceinline__ void stage_load(
    uint32_t sbase,
    const __nv_bfloat16* a_hi, const __nv_bfloat16* a_lo,
    const __nv_bfloat16* b_hi, const __nv_bfloat16* b_lo,
    int k0, int tid)
{
    const __nv_bfloat16* bases[4] = { a_hi + k0, a_lo + k0, b_hi + k0, b_lo + k0 };
#pragma unroll
    for (int mat = 0; mat < 4; mat++) {
#pragma unroll
        for (int i = 0; i < 2; i++) {
            int s = tid + i * 256;
            int row = s >> 2;
            int c = s & 3;
            cp16(sbase + mat * MATB + row * ROWP + c * 16,
                 bases[mat] + (size_t)row * DD + c * 8);
        }
    }
}

template<int MODE>
__global__ __launch_bounds__(256) void gemm_mma(
    const __nv_bfloat16* __restrict__ Ahi, const __nv_bfloat16* __restrict__ Alo,
    const __nv_bfloat16* __restrict__ Bhi, const __nv_bfloat16* __restrict__ Blo,
    float* __restrict__ Cf,
    __nv_bfloat16* __restrict__ Chi, __nv_bfloat16* __restrict__ Clo)
{
    extern __shared__ char smraw[];
    const uint32_t smb = smem_u32(smraw);

    const int tid  = threadIdx.x;
    const int wid  = tid >> 5;
    const int lane = tid & 31;
    const int n0 = blockIdx.x * 128;
    const int m0 = blockIdx.y * 128;
    const int wm = (wid & 3) * 32;
    const int wn = (wid >> 2) * 64;

    const __nv_bfloat16* a_hi = Ahi + (size_t)m0 * DD;
    const __nv_bfloat16* a_lo = Alo + (size_t)m0 * DD;
    const __nv_bfloat16* b_hi = Bhi + (size_t)n0 * DD;
    const __nv_bfloat16* b_lo = Blo + (size_t)n0 * DD;

    float acc[2][8][4];
#pragma unroll
    for (int i = 0; i < 2; i++)
#pragma unroll
        for (int j = 0; j < 8; j++)
#pragma unroll
            for (int k = 0; k < 4; k++) acc[i][j][k] = 0.f;

    const int a_row = lane & 15;
    const int a_chk = lane >> 4;
    const int b_mat = lane >> 3;
    const int b_row = (b_mat >> 1) * 8 + (lane & 7);
    const int b_chk = b_mat & 1;

    stage_load(smb, a_hi, a_lo, b_hi, b_lo, 0, tid);
    cp_commit();

    for (int it = 0; it < 32; it++) {
        if (it + 1 < 32) {
            stage_load(smb + ((it + 1) & 1) * STAGEB,
                       a_hi, a_lo, b_hi, b_lo, (it + 1) * 32, tid);
            cp_commit();
            cp_wait<1>();
        } else {
            cp_wait<0>();
        }
        __syncthreads();

        const uint32_t sb = smb + (it & 1) * STAGEB;
#pragma unroll
        for (int ks = 0; ks < 2; ks++) {
            uint32_t ah[2][4], al[2][4], bh[4][4], bl[4][4];
#pragma unroll
            for (int mt = 0; mt < 2; mt++) {
                uint32_t ad = sb + (wm + mt * 16 + a_row) * ROWP
                            + ks * 32 + a_chk * 16;
                ldmx4(ah[mt], ad);
                ldmx4(al[mt], ad + MATB);
            }
#pragma unroll
            for (int ng = 0; ng < 4; ng++) {
                uint32_t bd = sb + 2 * MATB
                            + (wn + ng * 16 + b_row) * ROWP
                            + ks * 32 + b_chk * 16;
                ldmx4(bh[ng], bd);
                ldmx4(bl[ng], bd + MATB);
            }
#pragma unroll
            for (int mt = 0; mt < 2; mt++)
#pragma unroll
                for (int ng = 0; ng < 4; ng++)
#pragma unroll
                    for (int h = 0; h < 2; h++) {
                        float* c = acc[mt][ng * 2 + h];
                        mma16816(c, ah[mt], bh[ng][h * 2], bh[ng][h * 2 + 1]);
                        mma16816(c, ah[mt], bl[ng][h * 2], bl[ng][h * 2 + 1]);
                        mma16816(c, al[mt], bh[ng][h * 2], bh[ng][h * 2 + 1]);
                    }
        }
        __syncthreads();
    }

    const int r0 = lane >> 2;
    const int cpair = (lane & 3) * 2;
#pragma unroll
    for (int mt = 0; mt < 2; mt++) {
#pragma unroll
        for (int nt = 0; nt < 8; nt++) {
            const int m = m0 + wm + mt * 16 + r0;
            const int n = n0 + wn + nt * 8 + cpair;
            if (MODE == 0) {
                float* dst0 = Cf + (size_t)m * DD + n;
                float* dst1 = Cf + (size_t)(m + 8) * DD + n;
                *(float2*)dst0 = make_float2(acc[mt][nt][0], acc[mt][nt][1]);
                *(float2*)dst1 = make_float2(acc[mt][nt][2], acc[mt][nt][3]);
            } else {
                const int b = m >> 11;
                const int t = m & (TT - 1);
                const int h = n >> 6;
                const int hd = n & (HD - 1);
                size_t i0 = ((size_t)((b * HH + h) * TT + t) << 6) + hd;
                size_t i1 = i0 + (size_t)(8 << 6);
                uint32_t h0, l0, h1, l1;
                pack_split(acc[mt][nt][0], acc[mt][nt][1], h0, l0);
                pack_split(acc[mt][nt][2], acc[mt][nt][3], h1, l1);
                *(uint32_t*)(Chi + i0) = h0;
                *(uint32_t*)(Clo + i0) = l0;
                *(uint32_t*)(Chi + i1) = h1;
                *(uint32_t*)(Clo + i1) = l1;
            }
        }
    }
}

// ---------------------------------------------------------------------------
// Forget gate v2: 8 rows per block, Wf staged in padded smem (L1-conflict fix)
// smem: xs[8*1024] fp32 (32KB) + wfs[1024*17] fp32 (~68KB)
// ---------------------------------------------------------------------------
#define FG_SMEM ((8*1024 + 1024*17) * 4)

__global__ __launch_bounds__(128) void forget_kernel(
    const float* __restrict__ x, const float* __restrict__ Wf,
    const float* __restrict__ bf, float* __restrict__ lf)
{
    extern __shared__ float fsm[];
    float* xs  = fsm;              // [8][1024]
    float* wfs = fsm + 8 * 1024;   // [1024][17] padded

    const int tid = threadIdx.x;
    const int row0 = blockIdx.x * 8;

    // stage Wf (coalesced read, padded write)
    for (int i = tid; i < DD * HH; i += 128)
        wfs[(i >> 4) * 17 + (i & 15)] = Wf[i];
    // stage 8 rows of x (float4 coalesced)
    {
        const float4* src = (const float4*)(x + (size_t)row0 * DD);
        float4* dst = (float4*)xs;
        for (int i = tid; i < 8 * DD / 4; i += 128)
            dst[i] = src[i];
    }
    __syncthreads();

    const int h  = tid >> 3;
    const int l8 = tid & 7;
#pragma unroll
    for (int row = 0; row < 8; row++) {
        float acc = 0.f;
        const float* xr = xs + row * DD;
#pragma unroll 16
        for (int d = l8; d < DD; d += 8)
            acc = fmaf(xr[d], wfs[d * 17 + h], acc);
        acc += __shfl_xor_sync(0xffffffffu, acc, 1);
        acc += __shfl_xor_sync(0xffffffffu, acc, 2);
        acc += __shfl_xor_sync(0xffffffffu, acc, 4);
        if (l8 == 0) {
            float z = acc + bf[h];
            float ls = (z >= 0.f) ? -log1pf(__expf(-z)) : z - log1pf(__expf(z));
            ls = fminf(fmaxf(ls, -10.f), 0.f);
            const int grow = row0 + row;
            const int b = grow >> 11;
            const int t = grow & (TT - 1);
            lf[(size_t)(b * HH + h) * TT + t] = ls;
        }
    }
}

// ---------------------------------------------------------------------------
// Cumsum over T per (b,h): 256-thread block scan (8 elems/thread)
// ---------------------------------------------------------------------------
__global__ __launch_bounds__(256) void cumsum_kernel(float* __restrict__ lf)
{
    const int bh = blockIdx.x;
    float* p = lf + (size_t)bh * TT;
    const int tid = threadIdx.x;
    const int lane = tid & 31, wid = tid >> 5;
    __shared__ float wsum[8];

    float v[8];
    float s = 0.f;
#pragma unroll
    for (int i = 0; i < 8; i++) { v[i] = p[tid * 8 + i]; s += v[i]; }

    float ss = s;
#pragma unroll
    for (int off = 1; off < 32; off <<= 1) {
        float n = __shfl_up_sync(0xffffffffu, ss, off);
        if (lane >= off) ss += n;
    }
    if (lane == 31) wsum[wid] = ss;
    __syncthreads();
    float woff = 0.f;
#pragma unroll
    for (int w = 0; w < 8; w++)
        if (w < wid) woff += wsum[w];

    float run = woff + ss - s;   // exclusive prefix for this thread
#pragma unroll
    for (int i = 0; i < 8; i++) { run += v[i]; p[tid * 8 + i] = run; }
}

// ---------------------------------------------------------------------------
// HMMA forgetting attention with decay-window tile skipping.
// ---------------------------------------------------------------------------
#define ATILE  8192
#define ACKS   (4*ATILE)
#define ASTAGE (4*ATILE + 256)
#define AQOFF  (2*ASTAGE)
#define ATTN_SMEM (2*ASTAGE + 2*ATILE)

__device__ __forceinline__ uint32_t asw(int row, int chunk) {
    return (uint32_t)(row * 128 + ((chunk ^ (row & 7)) * 16));
}

__device__ __forceinline__ void attn_stage(
    uint32_t sb,
    const __nv_bfloat16* Kh, const __nv_bfloat16* Kl,
    const __nv_bfloat16* Vh, const __nv_bfloat16* Vl,
    const float* cptr, int k0, int tid)
{
    const __nv_bfloat16* mats[4] = {
        Kh + (size_t)k0 * HD, Kl + (size_t)k0 * HD,
        Vh + (size_t)k0 * HD, Vl + (size_t)k0 * HD };
#pragma unroll
    for (int mt = 0; mt < 4; mt++) {
#pragma unroll
        for (int i = 0; i < 4; i++) {
            int s = tid + i * 128;
            int row = s >> 3, c = s & 7;
            cp16(sb + mt * ATILE + asw(row, c), mats[mt] + row * HD + c * 8);
        }
    }
    if (tid < 16) cp16(sb + ACKS + tid * 16, cptr + k0 + tid * 4);
}

__global__ __launch_bounds__(128) void attn_mma(
    const __nv_bfloat16* __restrict__ Qhi, const __nv_bfloat16* __restrict__ Qlo,
    const __nv_bfloat16* __restrict__ Khi, const __nv_bfloat16* __restrict__ Klo,
    const __nv_bfloat16* __restrict__ Vhi, const __nv_bfloat16* __restrict__ Vlo,
    const float* __restrict__ C,
    __nv_bfloat16* __restrict__ Ohi, __nv_bfloat16* __restrict__ Olo)
{
    extern __shared__ char smraw[];
    const uint32_t smb = smem_u32(smraw);

    const int tid  = threadIdx.x;
    const int wid  = tid >> 5;
    const int lane = tid & 31;
    const int qt = blockIdx.x;
    const int bh = blockIdx.y;
    const int q0 = qt * 64;

    const __nv_bfloat16* Qh = Qhi + (size_t)bh * TT * HD;
    const __nv_bfloat16* Ql = Qlo + (size_t)bh * TT * HD;
    const __nv_bfloat16* Kh = Khi + (size_t)bh * TT * HD;
    const __nv_bfloat16* Kl = Klo + (size_t)bh * TT * HD;
    const __nv_bfloat16* Vh = Vhi + (size_t)bh * TT * HD;
    const __nv_bfloat16* Vl = Vlo + (size_t)bh * TT * HD;
    const float* cptr = C + (size_t)bh * TT;

    // ---- decay window: first k-tile that can contribute ----
    // skipped tiles have max in-tile decay = c[q0]-c[kt*64+63] < -60 ->
    // contribution < e^{5.5-60+5.5} = e^-49 of the always-live diagonal term.
    int kt_start;
    {
        const float cq0v = cptr[q0];
        int lo = 0, hi = qt;
        while (lo < hi) {
            int mid = (lo + hi) >> 1;
            if (cq0v - cptr[mid * 64 + 63] >= -60.f) hi = mid;
            else lo = mid + 1;
        }
        kt_start = lo;   // <= qt; diagonal tile never skipped
    }

    // ---- load Q tile (hi+lo) ----
#pragma unroll
    for (int i = 0; i < 8; i++) {
        int s = tid + i * 128;
        int mat = s >> 9;
        int rc = s & 511;
        int row = rc >> 3, c = rc & 7;
        const __nv_bfloat16* src = (mat == 0 ? Qh : Ql);
        cp16(smb + AQOFF + mat * ATILE + asw(row, c),
             src + (size_t)(q0 + row) * HD + c * 8);
    }
    cp_commit();
    cp_wait<0>();
    __syncthreads();

    const int a_row = lane & 15;
    const int a_chk = lane >> 4;
    uint32_t qh[4][4], ql[4][4];
#pragma unroll
    for (int ks = 0; ks < 4; ks++) {
        uint32_t ad = smb + AQOFF + asw(wid * 16 + a_row, ks * 2 + a_chk);
        ldmx4(qh[ks], ad);
        ldmx4(ql[ks], ad + ATILE);
    }

    const int r0 = wid * 16 + (lane >> 2);
    const float cq0 = cptr[q0 + r0];
    const float cq1 = cptr[q0 + r0 + 8];

    float m0 = -1e30f, m1 = -1e30f, l0 = 0.f, l1 = 0.f;
    float o[8][4];
#pragma unroll
    for (int i = 0; i < 8; i++)
#pragma unroll
        for (int j = 0; j < 4; j++) o[i][j] = 0.f;

    const int b_mat = lane >> 3;
    const int b_row = (b_mat >> 1) * 8 + (lane & 7);
    const int b_chk = b_mat & 1;
    const int v_g = lane >> 3;
    const int v_r = lane & 7;

    attn_stage(smb + (kt_start & 1) * ASTAGE, Kh, Kl, Vh, Vl, cptr,
               kt_start * 64, tid);
    cp_commit();

    for (int kt = kt_start; kt <= qt; kt++) {
        if (kt < qt) {
            attn_stage(smb + ((kt + 1) & 1) * ASTAGE,
                       Kh, Kl, Vh, Vl, cptr, (kt + 1) * 64, tid);
            cp_commit();
            cp_wait<1>();
        } else {
            cp_wait<0>();
        }
        __syncthreads();

        const uint32_t sb = smb + (kt & 1) * ASTAGE;
        const float* cks = (const float*)(smraw + (kt & 1) * ASTAGE + ACKS);

        // ---- S = Q K^T (3-product split) ----
        float s[8][4];
#pragma unroll
        for (int i = 0; i < 8; i++)
#pragma unroll
            for (int j = 0; j < 4; j++) s[i][j] = 0.f;

#pragma unroll
        for (int ks = 0; ks < 4; ks++) {
            uint32_t kh[4][4], kl[4][4];
#pragma unroll
            for (int ng = 0; ng < 4; ng++) {
                uint32_t bd = sb + asw(ng * 16 + b_row, ks * 2 + b_chk);
                ldmx4(kh[ng], bd);
                ldmx4(kl[ng], bd + ATILE);
            }
#pragma unroll
            for (int ng = 0; ng < 4; ng++)
#pragma unroll
                for (int h = 0; h < 2; h++) {
                    float* c = s[ng * 2 + h];
                    mma16816(c, qh[ks], kh[ng][h * 2], kh[ng][h * 2 + 1]);
                    mma16816(c, qh[ks], kl[ng][h * 2], kl[ng][h * 2 + 1]);
                    mma16816(c, ql[ks], kh[ng][h * 2], kh[ng][h * 2 + 1]);
                }
        }

        // ---- decay bias + causal mask ----
        const bool diag = (kt == qt);
        const int k0g = kt * 64;
#pragma unroll
        for (int nt = 0; nt < 8; nt++) {
            const int col = nt * 8 + (lane & 3) * 2;
            const float ck0 = cks[col], ck1 = cks[col + 1];
            float d00 = fmaxf(cq0 - ck0, -50.f);
            float d01 = fmaxf(cq0 - ck1, -50.f);
            float d10 = fmaxf(cq1 - ck0, -50.f);
            float d11 = fmaxf(cq1 - ck1, -50.f);
            s[nt][0] = fmaf(s[nt][0], 0.125f, d00);
            s[nt][1] = fmaf(s[nt][1], 0.125f, d01);
            s[nt][2] = fmaf(s[nt][2], 0.125f, d10);
            s[nt][3] = fmaf(s[nt][3], 0.125f, d11);
            if (diag) {
                if (k0g + col     > q0 + r0)     s[nt][0] = -1e30f;
                if (k0g + col + 1 > q0 + r0)     s[nt][1] = -1e30f;
                if (k0g + col     > q0 + r0 + 8) s[nt][2] = -1e30f;
                if (k0g + col + 1 > q0 + r0 + 8) s[nt][3] = -1e30f;
            }
        }

        // ---- online softmax ----
        float ml0 = -1e30f, ml1 = -1e30f;
#pragma unroll
        for (int nt = 0; nt < 8; nt++) {
            ml0 = fmaxf(ml0, fmaxf(s[nt][0], s[nt][1]));
            ml1 = fmaxf(ml1, fmaxf(s[nt][2], s[nt][3]));
        }
        ml0 = fmaxf(ml0, __shfl_xor_sync(0xffffffffu, ml0, 1));
        ml0 = fmaxf(ml0, __shfl_xor_sync(0xffffffffu, ml0, 2));
        ml1 = fmaxf(ml1, __shfl_xor_sync(0xffffffffu, ml1, 1));
        ml1 = fmaxf(ml1, __shfl_xor_sync(0xffffffffu, ml1, 2));
        const float mn0 = fmaxf(m0, ml0);
        const float mn1 = fmaxf(m1, ml1);
        const float corr0 = ex2f((m0 - mn0) * LOG2E);
        const float corr1 = ex2f((m1 - mn1) * LOG2E);
        m0 = mn0; m1 = mn1;

        float sum0 = 0.f, sum1 = 0.f;
#pragma unroll
        for (int nt = 0; nt < 8; nt++) {
            s[nt][0] = ex2f((s[nt][0] - mn0) * LOG2E);
            s[nt][1] = ex2f((s[nt][1] - mn0) * LOG2E);
            s[nt][2] = ex2f((s[nt][2] - mn1) * LOG2E);
            s[nt][3] = ex2f((s[nt][3] - mn1) * LOG2E);
            sum0 += s[nt][0] + s[nt][1];
            sum1 += s[nt][2] + s[nt][3];
        }
        l0 = l0 * corr0 + sum0;
        l1 = l1 * corr1 + sum1;
#pragma unroll
        for (int nt = 0; nt < 8; nt++) {
            o[nt][0] *= corr0; o[nt][1] *= corr0;
            o[nt][2] *= corr1; o[nt][3] *= corr1;
        }

        // ---- pack P (hi/lo) into A fragments ----
        uint32_t ph[4][4], pl[4][4];
#pragma unroll
        for (int kc = 0; kc < 4; kc++) {
            pack_split(s[kc*2][0],   s[kc*2][1],   ph[kc][0], pl[kc][0]);
            pack_split(s[kc*2][2],   s[kc*2][3],   ph[kc][1], pl[kc][1]);
            pack_split(s[kc*2+1][0], s[kc*2+1][1], ph[kc][2], pl[kc][2]);
            pack_split(s[kc*2+1][2], s[kc*2+1][3], ph[kc][3], pl[kc][3]);
        }

        // ---- O += P V (3-product split) ----
#pragma unroll
        for (int kc = 0; kc < 4; kc++) {
            uint32_t vh[4][4], vl[4][4];
#pragma unroll
            for (int p = 0; p < 4; p++) {
                int row = kc * 16 + (v_g & 1) * 8 + v_r;
                int chunk = p * 2 + (v_g >> 1);
                uint32_t vd = sb + 2 * ATILE + asw(row, chunk);
                ldmx4t(vh[p], vd);
                ldmx4t(vl[p], vd + ATILE);
            }
#pragma unroll
            for (int p = 0; p < 4; p++)
#pragma unroll
                for (int h = 0; h < 2; h++) {
                    float* c = o[p * 2 + h];
                    mma16816(c, ph[kc], vh[p][h * 2], vh[p][h * 2 + 1]);
                    mma16816(c, ph[kc], vl[p][h * 2], vl[p][h * 2 + 1]);
                    mma16816(c, pl[kc], vh[p][h * 2], vh[p][h * 2 + 1]);
                }
        }
        __syncthreads();
    }

    // ---- finalize + store O hi/lo ----
    l0 += __shfl_xor_sync(0xffffffffu, l0, 1);
    l0 += __shfl_xor_sync(0xffffffffu, l0, 2);
    l1 += __shfl_xor_sync(0xffffffffu, l1, 1);
    l1 += __shfl_xor_sync(0xffffffffu, l1, 2);
    const float inv0 = 1.f / l0;
    const float inv1 = 1.f / l1;

    const int b = bh >> 4, h = bh & 15;
    const int t0 = q0 + r0;
    size_t base0 = ((size_t)(b * TT + t0)) * DD + h * HD;
    size_t base1 = base0 + (size_t)8 * DD;
#pragma unroll
    for (int nt = 0; nt < 8; nt++) {
        const int col = nt * 8 + (lane & 3) * 2;
        uint32_t h0, lo0, h1, lo1;
        pack_split(o[nt][0] * inv0, o[nt][1] * inv0, h0, lo0);
        pack_split(o[nt][2] * inv1, o[nt][3] * inv1, h1, lo1);
        *(uint32_t*)(Ohi + base0 + col) = h0;
        *(uint32_t*)(Olo + base0 + col) = lo0;
        *(uint32_t*)(Ohi + base1 + col) = h1;
        *(uint32_t*)(Olo + base1 + col) = lo1;
    }
}

// ---------------------------------------------------------------------------
// kernel_launch
// ---------------------------------------------------------------------------
extern "C" void kernel_launch(void* const* d_in, const int* in_sizes, int n_in,
                              void* d_out, int out_size)
{
    (void)in_sizes; (void)n_in; (void)out_size;
    const float* x  = (const float*)d_in[0];
    const float* Wq = (const float*)d_in[1];
    const float* Wk = (const float*)d_in[2];
    const float* Wv = (const float*)d_in[3];
    const float* Wo = (const float*)d_in[4];
    const float* Wf = (const float*)d_in[5];
    const float* bf = (const float*)d_in[6];
    float* out = (float*)d_out;

    float* cp;
    cudaGetSymbolAddress((void**)&cp, g_c);

    __nv_bfloat16 *xhi, *xlo, *ohi, *olo;
    __nv_bfloat16 *qhi, *qlo, *khi, *klo, *vhi, *vlo;
    __nv_bfloat16 *wqh, *wql, *wkh, *wkl, *wvh, *wvl, *woh, *wol;
    cudaGetSymbolAddress((void**)&xhi, g_xhi);
    cudaGetSymbolAddress((void**)&xlo, g_xlo);
    cudaGetSymbolAddress((void**)&ohi, g_ohi);
    cudaGetSymbolAddress((void**)&olo, g_olo);
    cudaGetSymbolAddress((void**)&qhi, g_qhi);
    cudaGetSymbolAddress((void**)&qlo, g_qlo);
    cudaGetSymbolAddress((void**)&khi, g_khi);
    cudaGetSymbolAddress((void**)&klo, g_klo);
    cudaGetSymbolAddress((void**)&vhi, g_vhi);
    cudaGetSymbolAddress((void**)&vlo, g_vlo);
    cudaGetSymbolAddress((void**)&wqh, g_wqh);
    cudaGetSymbolAddress((void**)&wql, g_wql);
    cudaGetSymbolAddress((void**)&wkh, g_wkh);
    cudaGetSymbolAddress((void**)&wkl, g_wkl);
    cudaGetSymbolAddress((void**)&wvh, g_wvh);
    cudaGetSymbolAddress((void**)&wvl, g_wvl);
    cudaGetSymbolAddress((void**)&woh, g_woh);
    cudaGetSymbolAddress((void**)&wol, g_wol);

    cudaFuncSetAttribute(gemm_mma<0>,
                         cudaFuncAttributeMaxDynamicSharedMemorySize, GEMM_SMEM);
    cudaFuncSetAttribute(gemm_mma<1>,
                         cudaFuncAttributeMaxDynamicSharedMemorySize, GEMM_SMEM);
    cudaFuncSetAttribute(attn_mma,
                         cudaFuncAttributeMaxDynamicSharedMemorySize, ATTN_SMEM);
    cudaFuncSetAttribute(forget_kernel,
                         cudaFuncAttributeMaxDynamicSharedMemorySize, FG_SMEM);

    split_kernel<<<MM*DD/4/256, 256>>>(x, xhi, xlo, MM*DD/4);
    dim3 wgrid(32, 32), wblk(32, 8);
    wsplit_kernel<<<wgrid, wblk>>>(Wq, wqh, wql);
    wsplit_kernel<<<wgrid, wblk>>>(Wk, wkh, wkl);
    wsplit_kernel<<<wgrid, wblk>>>(Wv, wvh, wvl);
    wsplit_kernel<<<wgrid, wblk>>>(Wo, woh, wol);

    dim3 ggrid(DD / 128, MM / 128);
    gemm_mma<1><<<ggrid, 256, GEMM_SMEM>>>(xhi, xlo, wqh, wql, nullptr, qhi, qlo);
    gemm_mma<1><<<ggrid, 256, GEMM_SMEM>>>(xhi, xlo, wkh, wkl, nullptr, khi, klo);
    gemm_mma<1><<<ggrid, 256, GEMM_SMEM>>>(xhi, xlo, wvh, wvl, nullptr, vhi, vlo);

    forget_kernel<<<MM / 8, 128, FG_SMEM>>>(x, Wf, bf, cp);
    cumsum_kernel<<<BB * HH, 256>>>(cp);

    attn_mma<<<dim3(TT / 64, BB * HH), 128, ATTN_SMEM>>>(
        qhi, qlo, khi, klo, vhi, vlo, cp, ohi, olo);

    gemm_mma<0><<<ggrid, 256, GEMM_SMEM>>>(ohi, olo, woh, wol, out, nullptr, nullptr);
}

// round 6
// speedup vs baseline: 9.8264x; 1.3557x over previous
#include <cuda_runtime.h>
#include <cuda_fp16.h>
#include <math.h>
#include <stdint.h>

// Problem constants
#define BB 2
#define TT 2048
#define DD 1024
#define HH 16
#define HD 64
#define MM (BB*TT)   // 4096

// ---------------------------------------------------------------------------
// Scratch (device globals; no allocation allowed)
// ---------------------------------------------------------------------------
__device__ float g_c[BB*HH*TT];

__device__ __half g_xh[MM*DD];                       // x, single fp16
__device__ __half g_qhi[MM*DD], g_qlo[MM*DD];        // [B,H,T,HD]
__device__ __half g_khi[MM*DD], g_klo[MM*DD];
__device__ __half g_vhi[MM*DD], g_vlo[MM*DD];
__device__ __half g_ohi[MM*DD], g_olo[MM*DD];        // [B,T,D]
__device__ __half g_wqh[DD*DD], g_wql[DD*DD];        // Wt hi/lo [N][K]
__device__ __half g_wkh[DD*DD], g_wkl[DD*DD];
__device__ __half g_wvh[DD*DD], g_wvl[DD*DD];
__device__ __half g_woh[DD*DD], g_wol[DD*DD];

// ---------------------------------------------------------------------------
// PTX helpers (sm_100-safe: cp.async + ldmatrix + mma.sync fp16)
// ---------------------------------------------------------------------------
__device__ __forceinline__ uint32_t smem_u32(const void* p) {
    uint32_t a;
    asm("{ .reg .u64 t; cvta.to.shared.u64 t, %1; cvt.u32.u64 %0, t; }"
        : "=r"(a) : "l"(p));
    return a;
}
__device__ __forceinline__ void cp16(uint32_t dst, const void* src) {
    asm volatile("cp.async.cg.shared.global [%0], [%1], 16;"
                 :: "r"(dst), "l"(src) : "memory");
}
__device__ __forceinline__ void cp_commit() {
    asm volatile("cp.async.commit_group;" ::: "memory");
}
template<int N> __device__ __forceinline__ void cp_wait() {
    asm volatile("cp.async.wait_group %0;" :: "n"(N) : "memory");
}
__device__ __forceinline__ void ldmx4(uint32_t* r, uint32_t addr) {
    asm volatile("ldmatrix.sync.aligned.m8n8.x4.shared.b16 {%0,%1,%2,%3}, [%4];"
                 : "=r"(r[0]), "=r"(r[1]), "=r"(r[2]), "=r"(r[3]) : "r"(addr));
}
__device__ __forceinline__ void ldmx4t(uint32_t* r, uint32_t addr) {
    asm volatile("ldmatrix.sync.aligned.m8n8.x4.trans.shared.b16 {%0,%1,%2,%3}, [%4];"
                 : "=r"(r[0]), "=r"(r[1]), "=r"(r[2]), "=r"(r[3]) : "r"(addr));
}
__device__ __forceinline__ void mma16816(float* c, const uint32_t* a,
                                         uint32_t b0, uint32_t b1) {
    asm volatile(
        "mma.sync.aligned.m16n8k16.row.col.f32.f16.f16.f32 "
        "{%0,%1,%2,%3}, {%4,%5,%6,%7}, {%8,%9}, {%0,%1,%2,%3};"
        : "+f"(c[0]), "+f"(c[1]), "+f"(c[2]), "+f"(c[3])
        : "r"(a[0]), "r"(a[1]), "r"(a[2]), "r"(a[3]), "r"(b0), "r"(b1));
}
__device__ __forceinline__ float ex2f(float x) {
    float r;
    asm("ex2.approx.ftz.f32 %0, %1;" : "=f"(r) : "f"(x));
    return r;
}
__device__ __forceinline__ void pack_split(float a, float b,
                                           uint32_t& hi, uint32_t& lo) {
    __half ha = __float2half_rn(a);
    __half hb = __float2half_rn(b);
    __half la = __float2half_rn(a - __half2float(ha));
    __half lb = __float2half_rn(b - __half2float(hb));
    __half2 H = __halves2half2(ha, hb);
    __half2 L = __halves2half2(la, lb);
    hi = *reinterpret_cast<uint32_t*>(&H);
    lo = *reinterpret_cast<uint32_t*>(&L);
}
__device__ __forceinline__ uint32_t pack_h(float a, float b) {
    __half2 H = __halves2half2(__float2half_rn(a), __float2half_rn(b));
    return *reinterpret_cast<uint32_t*>(&H);
}

#define LOG2E 1.44269504088896340736f

// ---------------------------------------------------------------------------
// x fp32 -> single fp16
// ---------------------------------------------------------------------------
__global__ __launch_bounds__(256) void splitx_kernel(
    const float* __restrict__ in, __half* __restrict__ out, int n4)
{
    int i = blockIdx.x * blockDim.x + threadIdx.x;
    if (i >= n4) return;
    float4 v = ((const float4*)in)[i];
    ((uint32_t*)out)[2*i]   = pack_h(v.x, v.y);
    ((uint32_t*)out)[2*i+1] = pack_h(v.z, v.w);
}

// ---------------------------------------------------------------------------
// Weight transpose + fp16 hi/lo split, all 4 weights in one launch (grid.z)
// ---------------------------------------------------------------------------
__global__ __launch_bounds__(256) void wsplit_kernel(
    const float* __restrict__ W0, const float* __restrict__ W1,
    const float* __restrict__ W2, const float* __restrict__ W3,
    __half* __restrict__ H0, __half* __restrict__ L0,
    __half* __restrict__ H1, __half* __restrict__ L1,
    __half* __restrict__ H2, __half* __restrict__ L2,
    __half* __restrict__ H3, __half* __restrict__ L3)
{
    const int z = blockIdx.z;
    const float* W  = (z == 0) ? W0 : (z == 1) ? W1 : (z == 2) ? W2 : W3;
    __half* Whi     = (z == 0) ? H0 : (z == 1) ? H1 : (z == 2) ? H2 : H3;
    __half* Wlo     = (z == 0) ? L0 : (z == 1) ? L1 : (z == 2) ? L2 : L3;

    __shared__ float t[32][33];
    const int tx = threadIdx.x, ty = threadIdx.y;
    const int bx = blockIdx.x * 32;
    const int by = blockIdx.y * 32;
#pragma unroll
    for (int j = 0; j < 32; j += 8)
        t[ty + j][tx] = W[(size_t)(by + ty + j) * DD + bx + tx];
    __syncthreads();
#pragma unroll
    for (int j = 0; j < 32; j += 8) {
        float v = t[tx][ty + j];
        __half h = __float2half_rn(v);
        __half l = __float2half_rn(v - __half2float(h));
        size_t idx = (size_t)(bx + ty + j) * DD + by + tx;
        Whi[idx] = h;
        Wlo[idx] = l;
    }
}

// ---------------------------------------------------------------------------
// Fused QKV GEMM: A = x (single fp16), B = W hi/lo, 2-product.
// grid (24, 32): blockIdx.x>>3 selects {Q,K,V}; 128x128 tile, BK=32.
// Epilogue: fp16 hi/lo split store in [B,H,T,HD].
// ---------------------------------------------------------------------------
#define ROWP   80
#define MATB   (128*ROWP)
#define QSTAGE (3*MATB)
#define QKV_SMEM (2*QSTAGE)     // 61440

__global__ __launch_bounds__(256) void gemm_qkv(
    const __half* __restrict__ xh,
    const __half* __restrict__ wqh, const __half* __restrict__ wql,
    const __half* __restrict__ wkh, const __half* __restrict__ wkl,
    const __half* __restrict__ wvh, const __half* __restrict__ wvl,
    __half* __restrict__ qhi, __half* __restrict__ qlo,
    __half* __restrict__ khi, __half* __restrict__ klo,
    __half* __restrict__ vhi, __half* __restrict__ vlo)
{
    extern __shared__ char smraw[];
    const uint32_t smb = smem_u32(smraw);

    const int tid  = threadIdx.x;
    const int wid  = tid >> 5;
    const int lane = tid & 31;
    const int nmat = blockIdx.x >> 3;
    const int nloc = (blockIdx.x & 7) * 128;
    const int m0 = blockIdx.y * 128;
    const int wm = (wid & 3) * 32;
    const int wn = (wid >> 2) * 64;

    const __half* a_h = xh + (size_t)m0 * DD;
    const __half* b_h = ((nmat == 0) ? wqh : (nmat == 1) ? wkh : wvh)
                        + (size_t)nloc * DD;
    const __half* b_l = ((nmat == 0) ? wql : (nmat == 1) ? wkl : wvl)
                        + (size_t)nloc * DD;
    __half* Chi = (nmat == 0) ? qhi : (nmat == 1) ? khi : vhi;
    __half* Clo = (nmat == 0) ? qlo : (nmat == 1) ? klo : vlo;

    float acc[2][8][4];
#pragma unroll
    for (int i = 0; i < 2; i++)
#pragma unroll
        for (int j = 0; j < 8; j++)
#pragma unroll
            for (int k = 0; k < 4; k++) acc[i][j][k] = 0.f;

    const int a_row = lane & 15;
    const int a_chk = lane >> 4;
    const int b_mat = lane >> 3;
    const int b_row = (b_mat >> 1) * 8 + (lane & 7);
    const int b_chk = b_mat & 1;

    // stage loader: 3 tiles {A, Bh, Bl}
    auto stage = [&](uint32_t sbase, int k0) {
        const __half* bases[3] = { a_h + k0, b_h + k0, b_l + k0 };
#pragma unroll
        for (int mat = 0; mat < 3; mat++) {
#pragma unroll
            for (int i = 0; i < 2; i++) {
                int s = tid + i * 256;
                int row = s >> 2;
                int c = s & 3;
                cp16(sbase + mat * MATB + row * ROWP + c * 16,
                     bases[mat] + (size_t)row * DD + c * 8);
            }
        }
    };

    stage(smb, 0);
    cp_commit();

    for (int it = 0; it < 32; it++) {
        if (it + 1 < 32) {
            stage(smb + ((it + 1) & 1) * QSTAGE, (it + 1) * 32);
            cp_commit();
            cp_wait<1>();
        } else {
            cp_wait<0>();
        }
        __syncthreads();

        const uint32_t sb = smb + (it & 1) * QSTAGE;
#pragma unroll
        for (int ks = 0; ks < 2; ks++) {
            uint32_t af[2][4], bh[4][4], bl[4][4];
#pragma unroll
            for (int mt = 0; mt < 2; mt++) {
                uint32_t ad = sb + (wm + mt * 16 + a_row) * ROWP
                            + ks * 32 + a_chk * 16;
                ldmx4(af[mt], ad);
            }
#pragma unroll
            for (int ng = 0; ng < 4; ng++) {
                uint32_t bd = sb + MATB
                            + (wn + ng * 16 + b_row) * ROWP
                            + ks * 32 + b_chk * 16;
                ldmx4(bh[ng], bd);
                ldmx4(bl[ng], bd + MATB);
            }
#pragma unroll
            for (int mt = 0; mt < 2; mt++)
#pragma unroll
                for (int ng = 0; ng < 4; ng++)
#pragma unroll
                    for (int h = 0; h < 2; h++) {
                        float* c = acc[mt][ng * 2 + h];
                        mma16816(c, af[mt], bh[ng][h * 2], bh[ng][h * 2 + 1]);
                        mma16816(c, af[mt], bl[ng][h * 2], bl[ng][h * 2 + 1]);
                    }
        }
        __syncthreads();
    }

    const int r0 = lane >> 2;
    const int cpair = (lane & 3) * 2;
#pragma unroll
    for (int mt = 0; mt < 2; mt++) {
#pragma unroll
        for (int nt = 0; nt < 8; nt++) {
            const int m = m0 + wm + mt * 16 + r0;
            const int n = nloc + wn + nt * 8 + cpair;
            const int b = m >> 11;
            const int t = m & (TT - 1);
            const int h = n >> 6;
            const int hd = n & (HD - 1);
            size_t i0 = ((size_t)((b * HH + h) * TT + t) << 6) + hd;
            size_t i1 = i0 + (size_t)(8 << 6);
            uint32_t h0, l0, h1, l1;
            pack_split(acc[mt][nt][0], acc[mt][nt][1], h0, l0);
            pack_split(acc[mt][nt][2], acc[mt][nt][3], h1, l1);
            *(uint32_t*)(Chi + i0) = h0;
            *(uint32_t*)(Clo + i0) = l0;
            *(uint32_t*)(Chi + i1) = h1;
            *(uint32_t*)(Clo + i1) = l1;
        }
    }
}

// ---------------------------------------------------------------------------
// Output GEMM: O hi/lo x Wo hi/lo, 3-product, fp32 row-major store.
// ---------------------------------------------------------------------------
#define OSTAGE (4*MATB)
#define OUT_SMEM (2*OSTAGE)     // 81920

__global__ __launch_bounds__(256) void gemm_out(
    const __half* __restrict__ Ahi, const __half* __restrict__ Alo,
    const __half* __restrict__ Bhi, const __half* __restrict__ Blo,
    float* __restrict__ Cf)
{
    extern __shared__ char smraw[];
    const uint32_t smb = smem_u32(smraw);

    const int tid  = threadIdx.x;
    const int wid  = tid >> 5;
    const int lane = tid & 31;
    const int n0 = blockIdx.x * 128;
    const int m0 = blockIdx.y * 128;
    const int wm = (wid & 3) * 32;
    const int wn = (wid >> 2) * 64;

    const __half* a_hi = Ahi + (size_t)m0 * DD;
    const __half* a_lo = Alo + (size_t)m0 * DD;
    const __half* b_hi = Bhi + (size_t)n0 * DD;
    const __half* b_lo = Blo + (size_t)n0 * DD;

    float acc[2][8][4];
#pragma unroll
    for (int i = 0; i < 2; i++)
#pragma unroll
        for (int j = 0; j < 8; j++)
#pragma unroll
            for (int k = 0; k < 4; k++) acc[i][j][k] = 0.f;

    const int a_row = lane & 15;
    const int a_chk = lane >> 4;
    const int b_mat = lane >> 3;
    const int b_row = (b_mat >> 1) * 8 + (lane & 7);
    const int b_chk = b_mat & 1;

    auto stage = [&](uint32_t sbase, int k0) {
        const __half* bases[4] = { a_hi + k0, a_lo + k0, b_hi + k0, b_lo + k0 };
#pragma unroll
        for (int mat = 0; mat < 4; mat++) {
#pragma unroll
            for (int i = 0; i < 2; i++) {
                int s = tid + i * 256;
                int row = s >> 2;
                int c = s & 3;
                cp16(sbase + mat * MATB + row * ROWP + c * 16,
                     bases[mat] + (size_t)row * DD + c * 8);
            }
        }
    };

    stage(smb, 0);
    cp_commit();

    for (int it = 0; it < 32; it++) {
        if (it + 1 < 32) {
            stage(smb + ((it + 1) & 1) * OSTAGE, (it + 1) * 32);
            cp_commit();
            cp_wait<1>();
        } else {
            cp_wait<0>();
        }
        __syncthreads();

        const uint32_t sb = smb + (it & 1) * OSTAGE;
#pragma unroll
        for (int ks = 0; ks < 2; ks++) {
            uint32_t ah[2][4], al[2][4], bh[4][4], bl[4][4];
#pragma unroll
            for (int mt = 0; mt < 2; mt++) {
                uint32_t ad = sb + (wm + mt * 16 + a_row) * ROWP
                            + ks * 32 + a_chk * 16;
                ldmx4(ah[mt], ad);
                ldmx4(al[mt], ad + MATB);
            }
#pragma unroll
            for (int ng = 0; ng < 4; ng++) {
                uint32_t bd = sb + 2 * MATB
                            + (wn + ng * 16 + b_row) * ROWP
                            + ks * 32 + b_chk * 16;
                ldmx4(bh[ng], bd);
                ldmx4(bl[ng], bd + MATB);
            }
#pragma unroll
            for (int mt = 0; mt < 2; mt++)
#pragma unroll
                for (int ng = 0; ng < 4; ng++)
#pragma unroll
                    for (int h = 0; h < 2; h++) {
                        float* c = acc[mt][ng * 2 + h];
                        mma16816(c, ah[mt], bh[ng][h * 2], bh[ng][h * 2 + 1]);
                        mma16816(c, ah[mt], bl[ng][h * 2], bl[ng][h * 2 + 1]);
                        mma16816(c, al[mt], bh[ng][h * 2], bh[ng][h * 2 + 1]);
                    }
        }
        __syncthreads();
    }

    const int r0 = lane >> 2;
    const int cpair = (lane & 3) * 2;
#pragma unroll
    for (int mt = 0; mt < 2; mt++) {
#pragma unroll
        for (int nt = 0; nt < 8; nt++) {
            const int m = m0 + wm + mt * 16 + r0;
            const int n = n0 + wn + nt * 8 + cpair;
            float* dst0 = Cf + (size_t)m * DD + n;
            float* dst1 = Cf + (size_t)(m + 8) * DD + n;
            *(float2*)dst0 = make_float2(acc[mt][nt][0], acc[mt][nt][1]);
            *(float2*)dst1 = make_float2(acc[mt][nt][2], acc[mt][nt][3]);
        }
    }
}

// ---------------------------------------------------------------------------
// Forget gate (padded-smem version)
// ---------------------------------------------------------------------------
#define FG_SMEM ((8*1024 + 1024*17) * 4)

__global__ __launch_bounds__(128) void forget_kernel(
    const float* __restrict__ x, const float* __restrict__ Wf,
    const float* __restrict__ bf, float* __restrict__ lf)
{
    extern __shared__ float fsm[];
    float* xs  = fsm;
    float* wfs = fsm + 8 * 1024;

    const int tid = threadIdx.x;
    const int row0 = blockIdx.x * 8;

    for (int i = tid; i < DD * HH; i += 128)
        wfs[(i >> 4) * 17 + (i & 15)] = Wf[i];
    {
        const float4* src = (const float4*)(x + (size_t)row0 * DD);
        float4* dst = (float4*)xs;
        for (int i = tid; i < 8 * DD / 4; i += 128)
            dst[i] = src[i];
    }
    __syncthreads();

    const int h  = tid >> 3;
    const int l8 = tid & 7;
#pragma unroll
    for (int row = 0; row < 8; row++) {
        float acc = 0.f;
        const float* xr = xs + row * DD;
#pragma unroll 16
        for (int d = l8; d < DD; d += 8)
            acc = fmaf(xr[d], wfs[d * 17 + h], acc);
        acc += __shfl_xor_sync(0xffffffffu, acc, 1);
        acc += __shfl_xor_sync(0xffffffffu, acc, 2);
        acc += __shfl_xor_sync(0xffffffffu, acc, 4);
        if (l8 == 0) {
            float z = acc + bf[h];
            float ls = (z >= 0.f) ? -log1pf(__expf(-z)) : z - log1pf(__expf(z));
            ls = fminf(fmaxf(ls, -10.f), 0.f);
            const int grow = row0 + row;
            const int b = grow >> 11;
            const int t = grow & (TT - 1);
            lf[(size_t)(b * HH + h) * TT + t] = ls;
        }
    }
}

// ---------------------------------------------------------------------------
// Cumsum over T per (b,h)
// ---------------------------------------------------------------------------
__global__ __launch_bounds__(256) void cumsum_kernel(float* __restrict__ lf)
{
    const int bh = blockIdx.x;
    float* p = lf + (size_t)bh * TT;
    const int tid = threadIdx.x;
    const int lane = tid & 31, wid = tid >> 5;
    __shared__ float wsum[8];

    float v[8];
    float s = 0.f;
#pragma unroll
    for (int i = 0; i < 8; i++) { v[i] = p[tid * 8 + i]; s += v[i]; }

    float ss = s;
#pragma unroll
    for (int off = 1; off < 32; off <<= 1) {
        float n = __shfl_up_sync(0xffffffffu, ss, off);
        if (lane >= off) ss += n;
    }
    if (lane == 31) wsum[wid] = ss;
    __syncthreads();
    float woff = 0.f;
#pragma unroll
    for (int w = 0; w < 8; w++)
        if (w < wid) woff += wsum[w];

    float run = woff + ss - s;
#pragma unroll
    for (int i = 0; i < 8; i++) { run += v[i]; p[tid * 8 + i] = run; }
}

// ---------------------------------------------------------------------------
// HMMA forgetting attention (fp16 splits) with decay-window tile skipping.
// ---------------------------------------------------------------------------
#define ATILE  8192
#define ACKS   (4*ATILE)
#define ASTAGE (4*ATILE + 256)
#define AQOFF  (2*ASTAGE)
#define ATTN_SMEM (2*ASTAGE + 2*ATILE)

__device__ __forceinline__ uint32_t asw(int row, int chunk) {
    return (uint32_t)(row * 128 + ((chunk ^ (row & 7)) * 16));
}

__device__ __forceinline__ void attn_stage(
    uint32_t sb,
    const __half* Kh, const __half* Kl,
    const __half* Vh, const __half* Vl,
    const float* cptr, int k0, int tid)
{
    const __half* mats[4] = {
        Kh + (size_t)k0 * HD, Kl + (size_t)k0 * HD,
        Vh + (size_t)k0 * HD, Vl + (size_t)k0 * HD };
#pragma unroll
    for (int mt = 0; mt < 4; mt++) {
#pragma unroll
        for (int i = 0; i < 4; i++) {
            int s = tid + i * 128;
            int row = s >> 3, c = s & 7;
            cp16(sb + mt * ATILE + asw(row, c), mats[mt] + row * HD + c * 8);
        }
    }
    if (tid < 16) cp16(sb + ACKS + tid * 16, cptr + k0 + tid * 4);
}

__global__ __launch_bounds__(128) void attn_mma(
    const __half* __restrict__ Qhi, const __half* __restrict__ Qlo,
    const __half* __restrict__ Khi, const __half* __restrict__ Klo,
    const __half* __restrict__ Vhi, const __half* __restrict__ Vlo,
    const float* __restrict__ C,
    __half* __restrict__ Ohi, __half* __restrict__ Olo)
{
    extern __shared__ char smraw[];
    const uint32_t smb = smem_u32(smraw);

    const int tid  = threadIdx.x;
    const int wid  = tid >> 5;
    const int lane = tid & 31;
    const int qt = blockIdx.x;
    const int bh = blockIdx.y;
    const int q0 = qt * 64;

    const __half* Qh = Qhi + (size_t)bh * TT * HD;
    const __half* Ql = Qlo + (size_t)bh * TT * HD;
    const __half* Kh = Khi + (size_t)bh * TT * HD;
    const __half* Kl = Klo + (size_t)bh * TT * HD;
    const __half* Vh = Vhi + (size_t)bh * TT * HD;
    const __half* Vl = Vlo + (size_t)bh * TT * HD;
    const float* cptr = C + (size_t)bh * TT;

    // decay window (monotone c): first contributing k-tile
    int kt_start;
    {
        const float cq0v = cptr[q0];
        int lo = 0, hi = qt;
        while (lo < hi) {
            int mid = (lo + hi) >> 1;
            if (cq0v - cptr[mid * 64 + 63] >= -60.f) hi = mid;
            else lo = mid + 1;
        }
        kt_start = lo;
    }

    // load Q tile (hi+lo)
#pragma unroll
    for (int i = 0; i < 8; i++) {
        int s = tid + i * 128;
        int mat = s >> 9;
        int rc = s & 511;
        int row = rc >> 3, c = rc & 7;
        const __half* src = (mat == 0 ? Qh : Ql);
        cp16(smb + AQOFF + mat * ATILE + asw(row, c),
             src + (size_t)(q0 + row) * HD + c * 8);
    }
    cp_commit();
    cp_wait<0>();
    __syncthreads();

    const int a_row = lane & 15;
    const int a_chk = lane >> 4;
    uint32_t qh[4][4], ql[4][4];
#pragma unroll
    for (int ks = 0; ks < 4; ks++) {
        uint32_t ad = smb + AQOFF + asw(wid * 16 + a_row, ks * 2 + a_chk);
        ldmx4(qh[ks], ad);
        ldmx4(ql[ks], ad + ATILE);
    }

    const int r0 = wid * 16 + (lane >> 2);
    const float cq0 = cptr[q0 + r0];
    const float cq1 = cptr[q0 + r0 + 8];

    float m0 = -1e30f, m1 = -1e30f, l0 = 0.f, l1 = 0.f;
    float o[8][4];
#pragma unroll
    for (int i = 0; i < 8; i++)
#pragma unroll
        for (int j = 0; j < 4; j++) o[i][j] = 0.f;

    const int b_mat = lane >> 3;
    const int b_row = (b_mat >> 1) * 8 + (lane & 7);
    const int b_chk = b_mat & 1;
    const int v_g = lane >> 3;
    const int v_r = lane & 7;

    attn_stage(smb + (kt_start & 1) * ASTAGE, Kh, Kl, Vh, Vl, cptr,
               kt_start * 64, tid);
    cp_commit();

    for (int kt = kt_start; kt <= qt; kt++) {
        if (kt < qt) {
            attn_stage(smb + ((kt + 1) & 1) * ASTAGE,
                       Kh, Kl, Vh, Vl, cptr, (kt + 1) * 64, tid);
            cp_commit();
            cp_wait<1>();
        } else {
            cp_wait<0>();
        }
        __syncthreads();

        const uint32_t sb = smb + (kt & 1) * ASTAGE;
        const float* cks = (const float*)(smraw + (kt & 1) * ASTAGE + ACKS);

        float s[8][4];
#pragma unroll
        for (int i = 0; i < 8; i++)
#pragma unroll
            for (int j = 0; j < 4; j++) s[i][j] = 0.f;

#pragma unroll
        for (int ks = 0; ks < 4; ks++) {
            uint32_t kh[4][4], kl[4][4];
#pragma unroll
            for (int ng = 0; ng < 4; ng++) {
                uint32_t bd = sb + asw(ng * 16 + b_row, ks * 2 + b_chk);
                ldmx4(kh[ng], bd);
                ldmx4(kl[ng], bd + ATILE);
            }
#pragma unroll
            for (int ng = 0; ng < 4; ng++)
#pragma unroll
                for (int h = 0; h < 2; h++) {
                    float* c = s[ng * 2 + h];
                    mma16816(c, qh[ks], kh[ng][h * 2], kh[ng][h * 2 + 1]);
                    mma16816(c, qh[ks], kl[ng][h * 2], kl[ng][h * 2 + 1]);
                    mma16816(c, ql[ks], kh[ng][h * 2], kh[ng][h * 2 + 1]);
                }
        }

        const bool diag = (kt == qt);
        const int k0g = kt * 64;
#pragma unroll
        for (int nt = 0; nt < 8; nt++) {
            const int col = nt * 8 + (lane & 3) * 2;
            const float ck0 = cks[col], ck1 = cks[col + 1];
            float d00 = fmaxf(cq0 - ck0, -50.f);
            float d01 = fmaxf(cq0 - ck1, -50.f);
            float d10 = fmaxf(cq1 - ck0, -50.f);
            float d11 = fmaxf(cq1 - ck1, -50.f);
            s[nt][0] = fmaf(s[nt][0], 0.125f, d00);
            s[nt][1] = fmaf(s[nt][1], 0.125f, d01);
            s[nt][2] = fmaf(s[nt][2], 0.125f, d10);
            s[nt][3] = fmaf(s[nt][3], 0.125f, d11);
            if (diag) {
                if (k0g + col     > q0 + r0)     s[nt][0] = -1e30f;
                if (k0g + col + 1 > q0 + r0)     s[nt][1] = -1e30f;
                if (k0g + col     > q0 + r0 + 8) s[nt][2] = -1e30f;
                if (k0g + col + 1 > q0 + r0 + 8) s[nt][3] = -1e30f;
            }
        }

        float ml0 = -1e30f, ml1 = -1e30f;
#pragma unroll
        for (int nt = 0; nt < 8; nt++) {
            ml0 = fmaxf(ml0, fmaxf(s[nt][0], s[nt][1]));
            ml1 = fmaxf(ml1, fmaxf(s[nt][2], s[nt][3]));
        }
        ml0 = fmaxf(ml0, __shfl_xor_sync(0xffffffffu, ml0, 1));
        ml0 = fmaxf(ml0, __shfl_xor_sync(0xffffffffu, ml0, 2));
        ml1 = fmaxf(ml1, __shfl_xor_sync(0xffffffffu, ml1, 1));
        ml1 = fmaxf(ml1, __shfl_xor_sync(0xffffffffu, ml1, 2));
        const float mn0 = fmaxf(m0, ml0);
        const float mn1 = fmaxf(m1, ml1);
        const float corr0 = ex2f((m0 - mn0) * LOG2E);
        const float corr1 = ex2f((m1 - mn1) * LOG2E);
        m0 = mn0; m1 = mn1;

        float sum0 = 0.f, sum1 = 0.f;
#pragma unroll
        for (int nt = 0; nt < 8; nt++) {
            s[nt][0] = ex2f((s[nt][0] - mn0) * LOG2E);
            s[nt][1] = ex2f((s[nt][1] - mn0) * LOG2E);
            s[nt][2] = ex2f((s[nt][2] - mn1) * LOG2E);
            s[nt][3] = ex2f((s[nt][3] - mn1) * LOG2E);
            sum0 += s[nt][0] + s[nt][1];
            sum1 += s[nt][2] + s[nt][3];
        }
        l0 = l0 * corr0 + sum0;
        l1 = l1 * corr1 + sum1;
#pragma unroll
        for (int nt = 0; nt < 8; nt++) {
            o[nt][0] *= corr0; o[nt][1] *= corr0;
            o[nt][2] *= corr1; o[nt][3] *= corr1;
        }

        uint32_t ph[4][4], pl[4][4];
#pragma unroll
        for (int kc = 0; kc < 4; kc++) {
            pack_split(s[kc*2][0],   s[kc*2][1],   ph[kc][0], pl[kc][0]);
            pack_split(s[kc*2][2],   s[kc*2][3],   ph[kc][1], pl[kc][1]);
            pack_split(s[kc*2+1][0], s[kc*2+1][1], ph[kc][2], pl[kc][2]);
            pack_split(s[kc*2+1][2], s[kc*2+1][3], ph[kc][3], pl[kc][3]);
        }

#pragma unroll
        for (int kc = 0; kc < 4; kc++) {
            uint32_t vh[4][4], vl[4][4];
#pragma unroll
            for (int p = 0; p < 4; p++) {
                int row = kc * 16 + (v_g & 1) * 8 + v_r;
                int chunk = p * 2 + (v_g >> 1);
                uint32_t vd = sb + 2 * ATILE + asw(row, chunk);
                ldmx4t(vh[p], vd);
                ldmx4t(vl[p], vd + ATILE);
            }
#pragma unroll
            for (int p = 0; p < 4; p++)
#pragma unroll
                for (int h = 0; h < 2; h++) {
                    float* c = o[p * 2 + h];
                    mma16816(c, ph[kc], vh[p][h * 2], vh[p][h * 2 + 1]);
                    mma16816(c, ph[kc], vl[p][h * 2], vl[p][h * 2 + 1]);
                    mma16816(c, pl[kc], vh[p][h * 2], vh[p][h * 2 + 1]);
                }
        }
        __syncthreads();
    }

    l0 += __shfl_xor_sync(0xffffffffu, l0, 1);
    l0 += __shfl_xor_sync(0xffffffffu, l0, 2);
    l1 += __shfl_xor_sync(0xffffffffu, l1, 1);
    l1 += __shfl_xor_sync(0xffffffffu, l1, 2);
    const float inv0 = 1.f / l0;
    const float inv1 = 1.f / l1;

    const int b = bh >> 4, h = bh & 15;
    const int t0 = q0 + r0;
    size_t base0 = ((size_t)(b * TT + t0)) * DD + h * HD;
    size_t base1 = base0 + (size_t)8 * DD;
#pragma unroll
    for (int nt = 0; nt < 8; nt++) {
        const int col = nt * 8 + (lane & 3) * 2;
        uint32_t h0, lo0, h1, lo1;
        pack_split(o[nt][0] * inv0, o[nt][1] * inv0, h0, lo0);
        pack_split(o[nt][2] * inv1, o[nt][3] * inv1, h1, lo1);
        *(uint32_t*)(Ohi + base0 + col) = h0;
        *(uint32_t*)(Olo + base0 + col) = lo0;
        *(uint32_t*)(Ohi + base1 + col) = h1;
        *(uint32_t*)(Olo + base1 + col) = lo1;
    }
}

// ---------------------------------------------------------------------------
// kernel_launch
// ---------------------------------------------------------------------------
extern "C" void kernel_launch(void* const* d_in, const int* in_sizes, int n_in,
                              void* d_out, int out_size)
{
    (void)in_sizes; (void)n_in; (void)out_size;
    const float* x  = (const float*)d_in[0];
    const float* Wq = (const float*)d_in[1];
    const float* Wk = (const float*)d_in[2];
    const float* Wv = (const float*)d_in[3];
    const float* Wo = (const float*)d_in[4];
    const float* Wf = (const float*)d_in[5];
    const float* bf = (const float*)d_in[6];
    float* out = (float*)d_out;

    float* cp;
    cudaGetSymbolAddress((void**)&cp, g_c);

    __half *xh, *ohi, *olo;
    __half *qhi, *qlo, *khi, *klo, *vhi, *vlo;
    __half *wqh, *wql, *wkh, *wkl, *wvh, *wvl, *woh, *wol;
    cudaGetSymbolAddress((void**)&xh,  g_xh);
    cudaGetSymbolAddress((void**)&ohi, g_ohi);
    cudaGetSymbolAddress((void**)&olo, g_olo);
    cudaGetSymbolAddress((void**)&qhi, g_qhi);
    cudaGetSymbolAddress((void**)&qlo, g_qlo);
    cudaGetSymbolAddress((void**)&khi, g_khi);
    cudaGetSymbolAddress((void**)&klo, g_klo);
    cudaGetSymbolAddress((void**)&vhi, g_vhi);
    cudaGetSymbolAddress((void**)&vlo, g_vlo);
    cudaGetSymbolAddress((void**)&wqh, g_wqh);
    cudaGetSymbolAddress((void**)&wql, g_wql);
    cudaGetSymbolAddress((void**)&wkh, g_wkh);
    cudaGetSymbolAddress((void**)&wkl, g_wkl);
    cudaGetSymbolAddress((void**)&wvh, g_wvh);
    cudaGetSymbolAddress((void**)&wvl, g_wvl);
    cudaGetSymbolAddress((void**)&woh, g_woh);
    cudaGetSymbolAddress((void**)&wol, g_wol);

    cudaFuncSetAttribute(gemm_qkv,
                         cudaFuncAttributeMaxDynamicSharedMemorySize, QKV_SMEM);
    cudaFuncSetAttribute(gemm_out,
                         cudaFuncAttributeMaxDynamicSharedMemorySize, OUT_SMEM);
    cudaFuncSetAttribute(attn_mma,
                         cudaFuncAttributeMaxDynamicSharedMemorySize, ATTN_SMEM);
    cudaFuncSetAttribute(forget_kernel,
                         cudaFuncAttributeMaxDynamicSharedMemorySize, FG_SMEM);

    splitx_kernel<<<MM*DD/4/256, 256>>>(x, xh, MM*DD/4);
    wsplit_kernel<<<dim3(32, 32, 4), dim3(32, 8)>>>(
        Wq, Wk, Wv, Wo,
        wqh, wql, wkh, wkl, wvh, wvl, woh, wol);

    gemm_qkv<<<dim3(24, 32), 256, QKV_SMEM>>>(
        xh, wqh, wql, wkh, wkl, wvh, wvl,
        qhi, qlo, khi, klo, vhi, vlo);

    forget_kernel<<<MM / 8, 128, FG_SMEM>>>(x, Wf, bf, cp);
    cumsum_kernel<<<BB * HH, 256>>>(cp);

    attn_mma<<<dim3(TT / 64, BB * HH), 128, ATTN_SMEM>>>(
        qhi, qlo, khi, klo, vhi, vlo, cp, ohi, olo);

    gemm_out<<<dim3(DD / 128, MM / 128), 256, OUT_SMEM>>>(
        ohi, olo, woh, wol, out);
}

// round 7
// speedup vs baseline: 12.0916x; 1.2305x over previous
#include <cuda_runtime.h>
#include <cuda_fp16.h>
#include <math.h>
#include <stdint.h>

// Problem constants
#define BB 2
#define TT 2048
#define DD 1024
#define HH 16
#define HD 64
#define MM (BB*TT)   // 4096

// ---------------------------------------------------------------------------
// Scratch (device globals; no allocation allowed)
// ---------------------------------------------------------------------------
__device__ float g_c[BB*HH*TT];

__device__ __half g_xhi[MM*DD], g_xlo[MM*DD];        // x hi/lo fp16
__device__ __half g_qhi[MM*DD], g_qlo[MM*DD];        // [B,H,T,HD]
__device__ __half g_khi[MM*DD], g_klo[MM*DD];
__device__ __half g_vhi[MM*DD], g_vlo[MM*DD];
__device__ __half g_ohi[MM*DD];                      // attention out, single fp16
__device__ __half g_wqh[DD*DD], g_wql[DD*DD];        // Wt hi/lo [N][K]
__device__ __half g_wkh[DD*DD], g_wkl[DD*DD];
__device__ __half g_wvh[DD*DD], g_wvl[DD*DD];
__device__ __half g_woh[DD*DD], g_wol[DD*DD];
__device__ __half g_wfth[HH*DD], g_wftl[HH*DD];      // WfT hi/lo [16][1024]

// ---------------------------------------------------------------------------
// PTX helpers
// ---------------------------------------------------------------------------
__device__ __forceinline__ uint32_t smem_u32(const void* p) {
    uint32_t a;
    asm("{ .reg .u64 t; cvta.to.shared.u64 t, %1; cvt.u32.u64 %0, t; }"
        : "=r"(a) : "l"(p));
    return a;
}
__device__ __forceinline__ void cp16(uint32_t dst, const void* src) {
    asm volatile("cp.async.cg.shared.global [%0], [%1], 16;"
                 :: "r"(dst), "l"(src) : "memory");
}
__device__ __forceinline__ void cp_commit() {
    asm volatile("cp.async.commit_group;" ::: "memory");
}
template<int N> __device__ __forceinline__ void cp_wait() {
    asm volatile("cp.async.wait_group %0;" :: "n"(N) : "memory");
}
__device__ __forceinline__ void ldmx4(uint32_t* r, uint32_t addr) {
    asm volatile("ldmatrix.sync.aligned.m8n8.x4.shared.b16 {%0,%1,%2,%3}, [%4];"
                 : "=r"(r[0]), "=r"(r[1]), "=r"(r[2]), "=r"(r[3]) : "r"(addr));
}
__device__ __forceinline__ void ldmx4t(uint32_t* r, uint32_t addr) {
    asm volatile("ldmatrix.sync.aligned.m8n8.x4.trans.shared.b16 {%0,%1,%2,%3}, [%4];"
                 : "=r"(r[0]), "=r"(r[1]), "=r"(r[2]), "=r"(r[3]) : "r"(addr));
}
__device__ __forceinline__ void mma16816(float* c, const uint32_t* a,
                                         uint32_t b0, uint32_t b1) {
    asm volatile(
        "mma.sync.aligned.m16n8k16.row.col.f32.f16.f16.f32 "
        "{%0,%1,%2,%3}, {%4,%5,%6,%7}, {%8,%9}, {%0,%1,%2,%3};"
        : "+f"(c[0]), "+f"(c[1]), "+f"(c[2]), "+f"(c[3])
        : "r"(a[0]), "r"(a[1]), "r"(a[2]), "r"(a[3]), "r"(b0), "r"(b1));
}
__device__ __forceinline__ float ex2f(float x) {
    float r;
    asm("ex2.approx.ftz.f32 %0, %1;" : "=f"(r) : "f"(x));
    return r;
}
__device__ __forceinline__ void pack_split(float a, float b,
                                           uint32_t& hi, uint32_t& lo) {
    __half ha = __float2half_rn(a);
    __half hb = __float2half_rn(b);
    __half la = __float2half_rn(a - __half2float(ha));
    __half lb = __float2half_rn(b - __half2float(hb));
    __half2 H = __halves2half2(ha, hb);
    __half2 L = __halves2half2(la, lb);
    hi = *reinterpret_cast<uint32_t*>(&H);
    lo = *reinterpret_cast<uint32_t*>(&L);
}
__device__ __forceinline__ uint32_t pack_h(float a, float b) {
    __half2 H = __halves2half2(__float2half_rn(a), __float2half_rn(b));
    return *reinterpret_cast<uint32_t*>(&H);
}

#define LOG2E 1.44269504088896340736f

// ---------------------------------------------------------------------------
// x fp32 -> fp16 hi/lo
// ---------------------------------------------------------------------------
__global__ __launch_bounds__(256) void splitx_kernel(
    const float* __restrict__ in, __half* __restrict__ hi,
    __half* __restrict__ lo, int n4)
{
    int i = blockIdx.x * blockDim.x + threadIdx.x;
    if (i >= n4) return;
    float4 v = ((const float4*)in)[i];
    uint32_t h0, l0, h1, l1;
    pack_split(v.x, v.y, h0, l0);
    pack_split(v.z, v.w, h1, l1);
    ((uint32_t*)hi)[2*i]   = h0;
    ((uint32_t*)hi)[2*i+1] = h1;
    ((uint32_t*)lo)[2*i]   = l0;
    ((uint32_t*)lo)[2*i+1] = l1;
}

// ---------------------------------------------------------------------------
// Weight transpose + fp16 hi/lo split, all 4 big weights in one launch
// ---------------------------------------------------------------------------
__global__ __launch_bounds__(256) void wsplit_kernel(
    const float* __restrict__ W0, const float* __restrict__ W1,
    const float* __restrict__ W2, const float* __restrict__ W3,
    __half* __restrict__ H0, __half* __restrict__ L0,
    __half* __restrict__ H1, __half* __restrict__ L1,
    __half* __restrict__ H2, __half* __restrict__ L2,
    __half* __restrict__ H3, __half* __restrict__ L3)
{
    const int z = blockIdx.z;
    const float* W  = (z == 0) ? W0 : (z == 1) ? W1 : (z == 2) ? W2 : W3;
    __half* Whi     = (z == 0) ? H0 : (z == 1) ? H1 : (z == 2) ? H2 : H3;
    __half* Wlo     = (z == 0) ? L0 : (z == 1) ? L1 : (z == 2) ? L2 : L3;

    __shared__ float t[32][33];
    const int tx = threadIdx.x, ty = threadIdx.y;
    const int bx = blockIdx.x * 32;
    const int by = blockIdx.y * 32;
#pragma unroll
    for (int j = 0; j < 32; j += 8)
        t[ty + j][tx] = W[(size_t)(by + ty + j) * DD + bx + tx];
    __syncthreads();
#pragma unroll
    for (int j = 0; j < 32; j += 8) {
        float v = t[tx][ty + j];
        __half h = __float2half_rn(v);
        __half l = __float2half_rn(v - __half2float(h));
        size_t idx = (size_t)(bx + ty + j) * DD + by + tx;
        Whi[idx] = h;
        Wlo[idx] = l;
    }
}

// ---------------------------------------------------------------------------
// Wf [1024][16] fp32 -> WfT hi/lo [16][1024] fp16
// ---------------------------------------------------------------------------
__global__ __launch_bounds__(256) void wftsplit_kernel(
    const float* __restrict__ Wf,
    __half* __restrict__ Th, __half* __restrict__ Tl)
{
    int idx = blockIdx.x * 256 + threadIdx.x;     // 0..16383
    int h = idx >> 10;
    int d = idx & 1023;
    float v = Wf[d * HH + h];
    __half hi = __float2half_rn(v);
    __half lo = __float2half_rn(v - __half2float(hi));
    Th[h * DD + d] = hi;
    Tl[h * DD + d] = lo;
}

// ---------------------------------------------------------------------------
// Common swizzle for 128B-row tiles
// ---------------------------------------------------------------------------
__device__ __forceinline__ uint32_t asw(int row, int chunk) {
    return (uint32_t)(row * 128 + ((chunk ^ (row & 7)) * 16));
}

// ---------------------------------------------------------------------------
// Fused QKV GEMM: A = x hi (single fp16), B = W hi/lo, 2-product.
// ---------------------------------------------------------------------------
#define ROWP   80
#define MATB   (128*ROWP)
#define QSTAGE (3*MATB)
#define QKV_SMEM (2*QSTAGE)     // 61440

__global__ __launch_bounds__(256) void gemm_qkv(
    const __half* __restrict__ xh,
    const __half* __restrict__ wqh, const __half* __restrict__ wql,
    const __half* __restrict__ wkh, const __half* __restrict__ wkl,
    const __half* __restrict__ wvh, const __half* __restrict__ wvl,
    __half* __restrict__ qhi, __half* __restrict__ qlo,
    __half* __restrict__ khi, __half* __restrict__ klo,
    __half* __restrict__ vhi, __half* __restrict__ vlo)
{
    extern __shared__ char smraw[];
    const uint32_t smb = smem_u32(smraw);

    const int tid  = threadIdx.x;
    const int wid  = tid >> 5;
    const int lane = tid & 31;
    const int nmat = blockIdx.x >> 3;
    const int nloc = (blockIdx.x & 7) * 128;
    const int m0 = blockIdx.y * 128;
    const int wm = (wid & 3) * 32;
    const int wn = (wid >> 2) * 64;

    const __half* a_h = xh + (size_t)m0 * DD;
    const __half* b_h = ((nmat == 0) ? wqh : (nmat == 1) ? wkh : wvh)
                        + (size_t)nloc * DD;
    const __half* b_l = ((nmat == 0) ? wql : (nmat == 1) ? wkl : wvl)
                        + (size_t)nloc * DD;
    __half* Chi = (nmat == 0) ? qhi : (nmat == 1) ? khi : vhi;
    __half* Clo = (nmat == 0) ? qlo : (nmat == 1) ? klo : vlo;

    float acc[2][8][4];
#pragma unroll
    for (int i = 0; i < 2; i++)
#pragma unroll
        for (int j = 0; j < 8; j++)
#pragma unroll
            for (int k = 0; k < 4; k++) acc[i][j][k] = 0.f;

    const int a_row = lane & 15;
    const int a_chk = lane >> 4;
    const int b_mat = lane >> 3;
    const int b_row = (b_mat >> 1) * 8 + (lane & 7);
    const int b_chk = b_mat & 1;

    auto stage = [&](uint32_t sbase, int k0) {
        const __half* bases[3] = { a_h + k0, b_h + k0, b_l + k0 };
#pragma unroll
        for (int mat = 0; mat < 3; mat++) {
#pragma unroll
            for (int i = 0; i < 2; i++) {
                int s = tid + i * 256;
                int row = s >> 2;
                int c = s & 3;
                cp16(sbase + mat * MATB + row * ROWP + c * 16,
                     bases[mat] + (size_t)row * DD + c * 8);
            }
        }
    };

    stage(smb, 0);
    cp_commit();

    for (int it = 0; it < 32; it++) {
        if (it + 1 < 32) {
            stage(smb + ((it + 1) & 1) * QSTAGE, (it + 1) * 32);
            cp_commit();
            cp_wait<1>();
        } else {
            cp_wait<0>();
        }
        __syncthreads();

        const uint32_t sb = smb + (it & 1) * QSTAGE;
#pragma unroll
        for (int ks = 0; ks < 2; ks++) {
            uint32_t af[2][4], bh[4][4], bl[4][4];
#pragma unroll
            for (int mt = 0; mt < 2; mt++) {
                uint32_t ad = sb + (wm + mt * 16 + a_row) * ROWP
                            + ks * 32 + a_chk * 16;
                ldmx4(af[mt], ad);
            }
#pragma unroll
            for (int ng = 0; ng < 4; ng++) {
                uint32_t bd = sb + MATB
                            + (wn + ng * 16 + b_row) * ROWP
                            + ks * 32 + b_chk * 16;
                ldmx4(bh[ng], bd);
                ldmx4(bl[ng], bd + MATB);
            }
#pragma unroll
            for (int mt = 0; mt < 2; mt++)
#pragma unroll
                for (int ng = 0; ng < 4; ng++)
#pragma unroll
                    for (int h = 0; h < 2; h++) {
                        float* c = acc[mt][ng * 2 + h];
                        mma16816(c, af[mt], bh[ng][h * 2], bh[ng][h * 2 + 1]);
                        mma16816(c, af[mt], bl[ng][h * 2], bl[ng][h * 2 + 1]);
                    }
        }
        __syncthreads();
    }

    const int r0 = lane >> 2;
    const int cpair = (lane & 3) * 2;
#pragma unroll
    for (int mt = 0; mt < 2; mt++) {
#pragma unroll
        for (int nt = 0; nt < 8; nt++) {
            const int m = m0 + wm + mt * 16 + r0;
            const int n = nloc + wn + nt * 8 + cpair;
            const int b = m >> 11;
            const int t = m & (TT - 1);
            const int h = n >> 6;
            const int hd = n & (HD - 1);
            size_t i0 = ((size_t)((b * HH + h) * TT + t) << 6) + hd;
            size_t i1 = i0 + (size_t)(8 << 6);
            uint32_t h0, l0, h1, l1;
            pack_split(acc[mt][nt][0], acc[mt][nt][1], h0, l0);
            pack_split(acc[mt][nt][2], acc[mt][nt][3], h1, l1);
            *(uint32_t*)(Chi + i0) = h0;
            *(uint32_t*)(Clo + i0) = l0;
            *(uint32_t*)(Chi + i1) = h1;
            *(uint32_t*)(Clo + i1) = l1;
        }
    }
}

// ---------------------------------------------------------------------------
// Output GEMM: A = attention out (single fp16), B = Wo hi/lo, 2-product,
// fp32 row-major store.
// ---------------------------------------------------------------------------
__global__ __launch_bounds__(256) void gemm_out(
    const __half* __restrict__ Ah,
    const __half* __restrict__ Bhi, const __half* __restrict__ Blo,
    float* __restrict__ Cf)
{
    extern __shared__ char smraw[];
    const uint32_t smb = smem_u32(smraw);

    const int tid  = threadIdx.x;
    const int wid  = tid >> 5;
    const int lane = tid & 31;
    const int n0 = blockIdx.x * 128;
    const int m0 = blockIdx.y * 128;
    const int wm = (wid & 3) * 32;
    const int wn = (wid >> 2) * 64;

    const __half* a_h = Ah + (size_t)m0 * DD;
    const __half* b_h = Bhi + (size_t)n0 * DD;
    const __half* b_l = Blo + (size_t)n0 * DD;

    float acc[2][8][4];
#pragma unroll
    for (int i = 0; i < 2; i++)
#pragma unroll
        for (int j = 0; j < 8; j++)
#pragma unroll
            for (int k = 0; k < 4; k++) acc[i][j][k] = 0.f;

    const int a_row = lane & 15;
    const int a_chk = lane >> 4;
    const int b_mat = lane >> 3;
    const int b_row = (b_mat >> 1) * 8 + (lane & 7);
    const int b_chk = b_mat & 1;

    auto stage = [&](uint32_t sbase, int k0) {
        const __half* bases[3] = { a_h + k0, b_h + k0, b_l + k0 };
#pragma unroll
        for (int mat = 0; mat < 3; mat++) {
#pragma unroll
            for (int i = 0; i < 2; i++) {
                int s = tid + i * 256;
                int row = s >> 2;
                int c = s & 3;
                cp16(sbase + mat * MATB + row * ROWP + c * 16,
                     bases[mat] + (size_t)row * DD + c * 8);
            }
        }
    };

    stage(smb, 0);
    cp_commit();

    for (int it = 0; it < 32; it++) {
        if (it + 1 < 32) {
            stage(smb + ((it + 1) & 1) * QSTAGE, (it + 1) * 32);
            cp_commit();
            cp_wait<1>();
        } else {
            cp_wait<0>();
        }
        __syncthreads();

        const uint32_t sb = smb + (it & 1) * QSTAGE;
#pragma unroll
        for (int ks = 0; ks < 2; ks++) {
            uint32_t af[2][4], bh[4][4], bl[4][4];
#pragma unroll
            for (int mt = 0; mt < 2; mt++) {
                uint32_t ad = sb + (wm + mt * 16 + a_row) * ROWP
                            + ks * 32 + a_chk * 16;
                ldmx4(af[mt], ad);
            }
#pragma unroll
            for (int ng = 0; ng < 4; ng++) {
                uint32_t bd = sb + MATB
                            + (wn + ng * 16 + b_row) * ROWP
                            + ks * 32 + b_chk * 16;
                ldmx4(bh[ng], bd);
                ldmx4(bl[ng], bd + MATB);
            }
#pragma unroll
            for (int mt = 0; mt < 2; mt++)
#pragma unroll
                for (int ng = 0; ng < 4; ng++)
#pragma unroll
                    for (int h = 0; h < 2; h++) {
                        float* c = acc[mt][ng * 2 + h];
                        mma16816(c, af[mt], bh[ng][h * 2], bh[ng][h * 2 + 1]);
                        mma16816(c, af[mt], bl[ng][h * 2], bl[ng][h * 2 + 1]);
                    }
        }
        __syncthreads();
    }

    const int r0 = lane >> 2;
    const int cpair = (lane & 3) * 2;
#pragma unroll
    for (int mt = 0; mt < 2; mt++) {
#pragma unroll
        for (int nt = 0; nt < 8; nt++) {
            const int m = m0 + wm + mt * 16 + r0;
            const int n = n0 + wn + nt * 8 + cpair;
            float* dst0 = Cf + (size_t)m * DD + n;
            float* dst1 = Cf + (size_t)(m + 8) * DD + n;
            *(float2*)dst0 = make_float2(acc[mt][nt][0], acc[mt][nt][1]);
            *(float2*)dst1 = make_float2(acc[mt][nt][2], acc[mt][nt][3]);
        }
    }
}

// ---------------------------------------------------------------------------
// Forget gate as 3-product split-fp16 MMA GEMM: z = x @ Wf  (M=4096,N=16,K=1024)
// then logsigmoid+clip -> lf[b*HH+h][t].  ~fp32 accurate.
// ---------------------------------------------------------------------------
#define FG_XL   16384
#define FG_WH   32768
#define FG_WL   34816
#define FG_STG  36864
#define FGM_SMEM (2*FG_STG)   // 73728

__global__ __launch_bounds__(128) void forget_mma(
    const __half* __restrict__ xhi, const __half* __restrict__ xlo,
    const __half* __restrict__ wfh, const __half* __restrict__ wfl,
    const float* __restrict__ bf, float* __restrict__ lf)
{
    extern __shared__ char smraw[];
    const uint32_t smb = smem_u32(smraw);

    const int tid  = threadIdx.x;
    const int wid  = tid >> 5;
    const int lane = tid & 31;
    const int m0 = blockIdx.x * 128;
    const int wm = wid * 32;

    const __half* xh_ = xhi + (size_t)m0 * DD;
    const __half* xl_ = xlo + (size_t)m0 * DD;

    float acc[2][2][4];
#pragma unroll
    for (int i = 0; i < 2; i++)
#pragma unroll
        for (int j = 0; j < 2; j++)
#pragma unroll
            for (int k = 0; k < 4; k++) acc[i][j][k] = 0.f;

    const int a_row = lane & 15;
    const int a_chk = lane >> 4;
    const int b_mat = lane >> 3;
    const int b_row = (b_mat >> 1) * 8 + (lane & 7);
    const int b_chk = b_mat & 1;

    auto stage = [&](uint32_t sbase, int k0) {
#pragma unroll
        for (int i = 0; i < 8; i++) {
            int s = tid + i * 128;
            int row = s >> 3, c = s & 7;
            cp16(sbase + asw(row, c),         xh_ + (size_t)row * DD + k0 + c * 8);
            cp16(sbase + FG_XL + asw(row, c), xl_ + (size_t)row * DD + k0 + c * 8);
        }
        {   // Wf tiles: 16 rows x 8 chunks = 128 cp16 each
            int row = tid >> 3, c = tid & 7;
            cp16(sbase + FG_WH + asw(row, c), wfh + (size_t)row * DD + k0 + c * 8);
            cp16(sbase + FG_WL + asw(row, c), wfl + (size_t)row * DD + k0 + c * 8);
        }
    };

    stage(smb, 0);
    cp_commit();

    for (int it = 0; it < 16; it++) {
        if (it + 1 < 16) {
            stage(smb + ((it + 1) & 1) * FG_STG, (it + 1) * 64);
            cp_commit();
            cp_wait<1>();
        } else {
            cp_wait<0>();
        }
        __syncthreads();

        const uint32_t sb = smb + (it & 1) * FG_STG;
#pragma unroll
        for (int ks = 0; ks < 4; ks++) {
            uint32_t ah[2][4], al[2][4], bh[4], bl[4];
#pragma unroll
            for (int mt = 0; mt < 2; mt++) {
                uint32_t aoff = asw(wm + mt * 16 + a_row, ks * 2 + a_chk);
                ldmx4(ah[mt], sb + aoff);
                ldmx4(al[mt], sb + FG_XL + aoff);
            }
            {
                uint32_t boff = asw(b_row, ks * 2 + b_chk);
                ldmx4(bh, sb + FG_WH + boff);
                ldmx4(bl, sb + FG_WL + boff);
            }
#pragma unroll
            for (int mt = 0; mt < 2; mt++)
#pragma unroll
                for (int h = 0; h < 2; h++) {
                    float* c = acc[mt][h];
                    mma16816(c, ah[mt], bh[h * 2], bh[h * 2 + 1]);
                    mma16816(c, ah[mt], bl[h * 2], bl[h * 2 + 1]);
                    mma16816(c, al[mt], bh[h * 2], bh[h * 2 + 1]);
                }
        }
        __syncthreads();
    }

    // epilogue: z -> clip(logsigmoid(z)) -> lf[(b*HH+h)*TT + t]
    const int r0 = lane >> 2;
    const int cpair = (lane & 3) * 2;
#pragma unroll
    for (int mt = 0; mt < 2; mt++) {
#pragma unroll
        for (int nt = 0; nt < 2; nt++) {
            const int h0 = nt * 8 + cpair;
            const float bf0 = bf[h0], bf1 = bf[h0 + 1];
#pragma unroll
            for (int half = 0; half < 2; half++) {
                const int m = m0 + wm + mt * 16 + r0 + half * 8;
                const int b = m >> 11;
                const int t = m & (TT - 1);
                float z0 = acc[mt][nt][half * 2]     + bf0;
                float z1 = acc[mt][nt][half * 2 + 1] + bf1;
                float ls0 = (z0 >= 0.f) ? -log1pf(__expf(-z0))
                                        : z0 - log1pf(__expf(z0));
                float ls1 = (z1 >= 0.f) ? -log1pf(__expf(-z1))
                                        : z1 - log1pf(__expf(z1));
                ls0 = fminf(fmaxf(ls0, -10.f), 0.f);
                ls1 = fminf(fmaxf(ls1, -10.f), 0.f);
                lf[(size_t)(b * HH + h0)     * TT + t] = ls0;
                lf[(size_t)(b * HH + h0 + 1) * TT + t] = ls1;
            }
        }
    }
}

// ---------------------------------------------------------------------------
// Cumsum over T per (b,h)
// ---------------------------------------------------------------------------
__global__ __launch_bounds__(256) void cumsum_kernel(float* __restrict__ lf)
{
    const int bh = blockIdx.x;
    float* p = lf + (size_t)bh * TT;
    const int tid = threadIdx.x;
    const int lane = tid & 31, wid = tid >> 5;
    __shared__ float wsum[8];

    float v[8];
    float s = 0.f;
#pragma unroll
    for (int i = 0; i < 8; i++) { v[i] = p[tid * 8 + i]; s += v[i]; }

    float ss = s;
#pragma unroll
    for (int off = 1; off < 32; off <<= 1) {
        float n = __shfl_up_sync(0xffffffffu, ss, off);
        if (lane >= off) ss += n;
    }
    if (lane == 31) wsum[wid] = ss;
    __syncthreads();
    float woff = 0.f;
#pragma unroll
    for (int w = 0; w < 8; w++)
        if (w < wid) woff += wsum[w];

    float run = woff + ss - s;
#pragma unroll
    for (int i = 0; i < 8; i++) { run += v[i]; p[tid * 8 + i] = run; }
}

// ---------------------------------------------------------------------------
// HMMA forgetting attention (fp16 splits), decay-window skip, single-fp16 out.
// ---------------------------------------------------------------------------
#define ATILE  8192
#define ACKS   (4*ATILE)
#define ASTAGE (4*ATILE + 256)
#define AQOFF  (2*ASTAGE)
#define ATTN_SMEM (2*ASTAGE + 2*ATILE)

__device__ __forceinline__ void attn_stage(
    uint32_t sb,
    const __half* Kh, const __half* Kl,
    const __half* Vh, const __half* Vl,
    const float* cptr, int k0, int tid)
{
    const __half* mats[4] = {
        Kh + (size_t)k0 * HD, Kl + (size_t)k0 * HD,
        Vh + (size_t)k0 * HD, Vl + (size_t)k0 * HD };
#pragma unroll
    for (int mt = 0; mt < 4; mt++) {
#pragma unroll
        for (int i = 0; i < 4; i++) {
            int s = tid + i * 128;
            int row = s >> 3, c = s & 7;
            cp16(sb + mt * ATILE + asw(row, c), mats[mt] + row * HD + c * 8);
        }
    }
    if (tid < 16) cp16(sb + ACKS + tid * 16, cptr + k0 + tid * 4);
}

__global__ __launch_bounds__(128) void attn_mma(
    const __half* __restrict__ Qhi, const __half* __restrict__ Qlo,
    const __half* __restrict__ Khi, const __half* __restrict__ Klo,
    const __half* __restrict__ Vhi, const __half* __restrict__ Vlo,
    const float* __restrict__ C,
    __half* __restrict__ Ohi)
{
    extern __shared__ char smraw[];
    const uint32_t smb = smem_u32(smraw);

    const int tid  = threadIdx.x;
    const int wid  = tid >> 5;
    const int lane = tid & 31;
    const int qt = blockIdx.x;
    const int bh = blockIdx.y;
    const int q0 = qt * 64;

    const __half* Qh = Qhi + (size_t)bh * TT * HD;
    const __half* Ql = Qlo + (size_t)bh * TT * HD;
    const __half* Kh = Khi + (size_t)bh * TT * HD;
    const __half* Kl = Klo + (size_t)bh * TT * HD;
    const __half* Vh = Vhi + (size_t)bh * TT * HD;
    const __half* Vl = Vlo + (size_t)bh * TT * HD;
    const float* cptr = C + (size_t)bh * TT;

    int kt_start;
    {
        const float cq0v = cptr[q0];
        int lo = 0, hi = qt;
        while (lo < hi) {
            int mid = (lo + hi) >> 1;
            if (cq0v - cptr[mid * 64 + 63] >= -60.f) hi = mid;
            else lo = mid + 1;
        }
        kt_start = lo;
    }

#pragma unroll
    for (int i = 0; i < 8; i++) {
        int s = tid + i * 128;
        int mat = s >> 9;
        int rc = s & 511;
        int row = rc >> 3, c = rc & 7;
        const __half* src = (mat == 0 ? Qh : Ql);
        cp16(smb + AQOFF + mat * ATILE + asw(row, c),
             src + (size_t)(q0 + row) * HD + c * 8);
    }
    cp_commit();
    cp_wait<0>();
    __syncthreads();

    const int a_row = lane & 15;
    const int a_chk = lane >> 4;
    uint32_t qh[4][4], ql[4][4];
#pragma unroll
    for (int ks = 0; ks < 4; ks++) {
        uint32_t ad = smb + AQOFF + asw(wid * 16 + a_row, ks * 2 + a_chk);
        ldmx4(qh[ks], ad);
        ldmx4(ql[ks], ad + ATILE);
    }

    const int r0 = wid * 16 + (lane >> 2);
    const float cq0 = cptr[q0 + r0];
    const float cq1 = cptr[q0 + r0 + 8];

    float m0 = -1e30f, m1 = -1e30f, l0 = 0.f, l1 = 0.f;
    float o[8][4];
#pragma unroll
    for (int i = 0; i < 8; i++)
#pragma unroll
        for (int j = 0; j < 4; j++) o[i][j] = 0.f;

    const int b_mat = lane >> 3;
    const int b_row = (b_mat >> 1) * 8 + (lane & 7);
    const int b_chk = b_mat & 1;
    const int v_g = lane >> 3;
    const int v_r = lane & 7;

    attn_stage(smb + (kt_start & 1) * ASTAGE, Kh, Kl, Vh, Vl, cptr,
               kt_start * 64, tid);
    cp_commit();

    for (int kt = kt_start; kt <= qt; kt++) {
        if (kt < qt) {
            attn_stage(smb + ((kt + 1) & 1) * ASTAGE,
                       Kh, Kl, Vh, Vl, cptr, (kt + 1) * 64, tid);
            cp_commit();
            cp_wait<1>();
        } else {
            cp_wait<0>();
        }
        __syncthreads();

        const uint32_t sb = smb + (kt & 1) * ASTAGE;
        const float* cks = (const float*)(smraw + (kt & 1) * ASTAGE + ACKS);

        float s[8][4];
#pragma unroll
        for (int i = 0; i < 8; i++)
#pragma unroll
            for (int j = 0; j < 4; j++) s[i][j] = 0.f;

#pragma unroll
        for (int ks = 0; ks < 4; ks++) {
            uint32_t kh[4][4], kl[4][4];
#pragma unroll
            for (int ng = 0; ng < 4; ng++) {
                uint32_t bd = sb + asw(ng * 16 + b_row, ks * 2 + b_chk);
                ldmx4(kh[ng], bd);
                ldmx4(kl[ng], bd + ATILE);
            }
#pragma unroll
            for (int ng = 0; ng < 4; ng++)
#pragma unroll
                for (int h = 0; h < 2; h++) {
                    float* c = s[ng * 2 + h];
                    mma16816(c, qh[ks], kh[ng][h * 2], kh[ng][h * 2 + 1]);
                    mma16816(c, qh[ks], kl[ng][h * 2], kl[ng][h * 2 + 1]);
                    mma16816(c, ql[ks], kh[ng][h * 2], kh[ng][h * 2 + 1]);
                }
        }

        const bool diag = (kt == qt);
        const int k0g = kt * 64;
#pragma unroll
        for (int nt = 0; nt < 8; nt++) {
            const int col = nt * 8 + (lane & 3) * 2;
            const float ck0 = cks[col], ck1 = cks[col + 1];
            float d00 = fmaxf(cq0 - ck0, -50.f);
            float d01 = fmaxf(cq0 - ck1, -50.f);
            float d10 = fmaxf(cq1 - ck0, -50.f);
            float d11 = fmaxf(cq1 - ck1, -50.f);
            s[nt][0] = fmaf(s[nt][0], 0.125f, d00);
            s[nt][1] = fmaf(s[nt][1], 0.125f, d01);
            s[nt][2] = fmaf(s[nt][2], 0.125f, d10);
            s[nt][3] = fmaf(s[nt][3], 0.125f, d11);
            if (diag) {
                if (k0g + col     > q0 + r0)     s[nt][0] = -1e30f;
                if (k0g + col + 1 > q0 + r0)     s[nt][1] = -1e30f;
                if (k0g + col     > q0 + r0 + 8) s[nt][2] = -1e30f;
                if (k0g + col + 1 > q0 + r0 + 8) s[nt][3] = -1e30f;
            }
        }

        float ml0 = -1e30f, ml1 = -1e30f;
#pragma unroll
        for (int nt = 0; nt < 8; nt++) {
            ml0 = fmaxf(ml0, fmaxf(s[nt][0], s[nt][1]));
            ml1 = fmaxf(ml1, fmaxf(s[nt][2], s[nt][3]));
        }
        ml0 = fmaxf(ml0, __shfl_xor_sync(0xffffffffu, ml0, 1));
        ml0 = fmaxf(ml0, __shfl_xor_sync(0xffffffffu, ml0, 2));
        ml1 = fmaxf(ml1, __shfl_xor_sync(0xffffffffu, ml1, 1));
        ml1 = fmaxf(ml1, __shfl_xor_sync(0xffffffffu, ml1, 2));
        const float mn0 = fmaxf(m0, ml0);
        const float mn1 = fmaxf(m1, ml1);
        const float corr0 = ex2f((m0 - mn0) * LOG2E);
        const float corr1 = ex2f((m1 - mn1) * LOG2E);
        m0 = mn0; m1 = mn1;

        float sum0 = 0.f, sum1 = 0.f;
#pragma unroll
        for (int nt = 0; nt < 8; nt++) {
            s[nt][0] = ex2f((s[nt][0] - mn0) * LOG2E);
            s[nt][1] = ex2f((s[nt][1] - mn0) * LOG2E);
            s[nt][2] = ex2f((s[nt][2] - mn1) * LOG2E);
            s[nt][3] = ex2f((s[nt][3] - mn1) * LOG2E);
            sum0 += s[nt][0] + s[nt][1];
            sum1 += s[nt][2] + s[nt][3];
        }
        l0 = l0 * corr0 + sum0;
        l1 = l1 * corr1 + sum1;
#pragma unroll
        for (int nt = 0; nt < 8; nt++) {
            o[nt][0] *= corr0; o[nt][1] *= corr0;
            o[nt][2] *= corr1; o[nt][3] *= corr1;
        }

        uint32_t ph[4][4], pl[4][4];
#pragma unroll
        for (int kc = 0; kc < 4; kc++) {
            pack_split(s[kc*2][0],   s[kc*2][1],   ph[kc][0], pl[kc][0]);
            pack_split(s[kc*2][2],   s[kc*2][3],   ph[kc][1], pl[kc][1]);
            pack_split(s[kc*2+1][0], s[kc*2+1][1], ph[kc][2], pl[kc][2]);
            pack_split(s[kc*2+1][2], s[kc*2+1][3], ph[kc][3], pl[kc][3]);
        }

#pragma unroll
        for (int kc = 0; kc < 4; kc++) {
            uint32_t vh[4][4], vl[4][4];
#pragma unroll
            for (int p = 0; p < 4; p++) {
                int row = kc * 16 + (v_g & 1) * 8 + v_r;
                int chunk = p * 2 + (v_g >> 1);
                uint32_t vd = sb + 2 * ATILE + asw(row, chunk);
                ldmx4t(vh[p], vd);
                ldmx4t(vl[p], vd + ATILE);
            }
#pragma unroll
            for (int p = 0; p < 4; p++)
#pragma unroll
                for (int h = 0; h < 2; h++) {
                    float* c = o[p * 2 + h];
                    mma16816(c, ph[kc], vh[p][h * 2], vh[p][h * 2 + 1]);
                    mma16816(c, ph[kc], vl[p][h * 2], vl[p][h * 2 + 1]);
                    mma16816(c, pl[kc], vh[p][h * 2], vh[p][h * 2 + 1]);
                }
        }
        __syncthreads();
    }

    l0 += __shfl_xor_sync(0xffffffffu, l0, 1);
    l0 += __shfl_xor_sync(0xffffffffu, l0, 2);
    l1 += __shfl_xor_sync(0xffffffffu, l1, 1);
    l1 += __shfl_xor_sync(0xffffffffu, l1, 2);
    const float inv0 = 1.f / l0;
    const float inv1 = 1.f / l1;

    const int b = bh >> 4, h = bh & 15;
    const int t0 = q0 + r0;
    size_t base0 = ((size_t)(b * TT + t0)) * DD + h * HD;
    size_t base1 = base0 + (size_t)8 * DD;
#pragma unroll
    for (int nt = 0; nt < 8; nt++) {
        const int col = nt * 8 + (lane & 3) * 2;
        *(uint32_t*)(Ohi + base0 + col) = pack_h(o[nt][0] * inv0, o[nt][1] * inv0);
        *(uint32_t*)(Ohi + base1 + col) = pack_h(o[nt][2] * inv1, o[nt][3] * inv1);
    }
}

// ---------------------------------------------------------------------------
// kernel_launch
// ---------------------------------------------------------------------------
extern "C" void kernel_launch(void* const* d_in, const int* in_sizes, int n_in,
                              void* d_out, int out_size)
{
    (void)in_sizes; (void)n_in; (void)out_size;
    const float* x  = (const float*)d_in[0];
    const float* Wq = (const float*)d_in[1];
    const float* Wk = (const float*)d_in[2];
    const float* Wv = (const float*)d_in[3];
    const float* Wo = (const float*)d_in[4];
    const float* Wf = (const float*)d_in[5];
    const float* bf = (const float*)d_in[6];
    float* out = (float*)d_out;

    float* cp;
    cudaGetSymbolAddress((void**)&cp, g_c);

    __half *xhi, *xlo, *ohi;
    __half *qhi, *qlo, *khi, *klo, *vhi, *vlo;
    __half *wqh, *wql, *wkh, *wkl, *wvh, *wvl, *woh, *wol, *wfth, *wftl;
    cudaGetSymbolAddress((void**)&xhi, g_xhi);
    cudaGetSymbolAddress((void**)&xlo, g_xlo);
    cudaGetSymbolAddress((void**)&ohi, g_ohi);
    cudaGetSymbolAddress((void**)&qhi, g_qhi);
    cudaGetSymbolAddress((void**)&qlo, g_qlo);
    cudaGetSymbolAddress((void**)&khi, g_khi);
    cudaGetSymbolAddress((void**)&klo, g_klo);
    cudaGetSymbolAddress((void**)&vhi, g_vhi);
    cudaGetSymbolAddress((void**)&vlo, g_vlo);
    cudaGetSymbolAddress((void**)&wqh, g_wqh);
    cudaGetSymbolAddress((void**)&wql, g_wql);
    cudaGetSymbolAddress((void**)&wkh, g_wkh);
    cudaGetSymbolAddress((void**)&wkl, g_wkl);
    cudaGetSymbolAddress((void**)&wvh, g_wvh);
    cudaGetSymbolAddress((void**)&wvl, g_wvl);
    cudaGetSymbolAddress((void**)&woh, g_woh);
    cudaGetSymbolAddress((void**)&wol, g_wol);
    cudaGetSymbolAddress((void**)&wfth, g_wfth);
    cudaGetSymbolAddress((void**)&wftl, g_wftl);

    cudaFuncSetAttribute(gemm_qkv,
                         cudaFuncAttributeMaxDynamicSharedMemorySize, QKV_SMEM);
    cudaFuncSetAttribute(gemm_out,
                         cudaFuncAttributeMaxDynamicSharedMemorySize, QKV_SMEM);
    cudaFuncSetAttribute(attn_mma,
                         cudaFuncAttributeMaxDynamicSharedMemorySize, ATTN_SMEM);
    cudaFuncSetAttribute(forget_mma,
                         cudaFuncAttributeMaxDynamicSharedMemorySize, FGM_SMEM);

    splitx_kernel<<<MM*DD/4/256, 256>>>(x, xhi, xlo, MM*DD/4);
    wsplit_kernel<<<dim3(32, 32, 4), dim3(32, 8)>>>(
        Wq, Wk, Wv, Wo,
        wqh, wql, wkh, wkl, wvh, wvl, woh, wol);
    wftsplit_kernel<<<64, 256>>>(Wf, wfth, wftl);

    gemm_qkv<<<dim3(24, 32), 256, QKV_SMEM>>>(
        xhi, wqh, wql, wkh, wkl, wvh, wvl,
        qhi, qlo, khi, klo, vhi, vlo);

    forget_mma<<<MM / 128, 128, FGM_SMEM>>>(xhi, xlo, wfth, wftl, bf, cp);
    cumsum_kernel<<<BB * HH, 256>>>(cp);

    attn_mma<<<dim3(TT / 64, BB * HH), 128, ATTN_SMEM>>>(
        qhi, qlo, khi, klo, vhi, vlo, cp, ohi);

    gemm_out<<<dim3(DD / 128, MM / 128), 256, QKV_SMEM>>>(
        ohi, woh, wol, out);
}

// round 8
// speedup vs baseline: 13.2052x; 1.0921x over previous
#include <cuda_runtime.h>
#include <cuda_fp16.h>
#include <math.h>
#include <stdint.h>

// Problem constants
#define BB 2
#define TT 2048
#define DD 1024
#define HH 16
#define HD 64
#define MM (BB*TT)   // 4096

// ---------------------------------------------------------------------------
// Scratch (device globals; no allocation allowed)
// ---------------------------------------------------------------------------
__device__ float g_c[BB*HH*TT];

__device__ __half g_xhi[MM*DD], g_xlo[MM*DD];        // x hi/lo fp16
__device__ __half g_qhi[MM*DD], g_qlo[MM*DD];        // [B,H,T,HD]
__device__ __half g_khi[MM*DD], g_klo[MM*DD];
__device__ __half g_vhi[MM*DD], g_vlo[MM*DD];
__device__ __half g_ohi[MM*DD];                      // attention out, single fp16
__device__ __half g_wqh[DD*DD], g_wql[DD*DD];        // Wt hi/lo [N][K]
__device__ __half g_wkh[DD*DD], g_wkl[DD*DD];
__device__ __half g_wvh[DD*DD], g_wvl[DD*DD];
__device__ __half g_woh[DD*DD], g_wol[DD*DD];
__device__ __half g_wfth[HH*DD], g_wftl[HH*DD];      // WfT hi/lo [16][1024]

// ---------------------------------------------------------------------------
// PTX helpers
// ---------------------------------------------------------------------------
__device__ __forceinline__ uint32_t smem_u32(const void* p) {
    uint32_t a;
    asm("{ .reg .u64 t; cvta.to.shared.u64 t, %1; cvt.u32.u64 %0, t; }"
        : "=r"(a) : "l"(p));
    return a;
}
__device__ __forceinline__ void cp16(uint32_t dst, const void* src) {
    asm volatile("cp.async.cg.shared.global [%0], [%1], 16;"
                 :: "r"(dst), "l"(src) : "memory");
}
__device__ __forceinline__ void cp_commit() {
    asm volatile("cp.async.commit_group;" ::: "memory");
}
template<int N> __device__ __forceinline__ void cp_wait() {
    asm volatile("cp.async.wait_group %0;" :: "n"(N) : "memory");
}
__device__ __forceinline__ void ldmx4(uint32_t* r, uint32_t addr) {
    asm volatile("ldmatrix.sync.aligned.m8n8.x4.shared.b16 {%0,%1,%2,%3}, [%4];"
                 : "=r"(r[0]), "=r"(r[1]), "=r"(r[2]), "=r"(r[3]) : "r"(addr));
}
__device__ __forceinline__ void ldmx4t(uint32_t* r, uint32_t addr) {
    asm volatile("ldmatrix.sync.aligned.m8n8.x4.trans.shared.b16 {%0,%1,%2,%3}, [%4];"
                 : "=r"(r[0]), "=r"(r[1]), "=r"(r[2]), "=r"(r[3]) : "r"(addr));
}
__device__ __forceinline__ void mma16816(float* c, const uint32_t* a,
                                         uint32_t b0, uint32_t b1) {
    asm volatile(
        "mma.sync.aligned.m16n8k16.row.col.f32.f16.f16.f32 "
        "{%0,%1,%2,%3}, {%4,%5,%6,%7}, {%8,%9}, {%0,%1,%2,%3};"
        : "+f"(c[0]), "+f"(c[1]), "+f"(c[2]), "+f"(c[3])
        : "r"(a[0]), "r"(a[1]), "r"(a[2]), "r"(a[3]), "r"(b0), "r"(b1));
}
__device__ __forceinline__ float ex2f(float x) {
    float r;
    asm("ex2.approx.ftz.f32 %0, %1;" : "=f"(r) : "f"(x));
    return r;
}
__device__ __forceinline__ void pack_split(float a, float b,
                                           uint32_t& hi, uint32_t& lo) {
    __half ha = __float2half_rn(a);
    __half hb = __float2half_rn(b);
    __half la = __float2half_rn(a - __half2float(ha));
    __half lb = __float2half_rn(b - __half2float(hb));
    __half2 H = __halves2half2(ha, hb);
    __half2 L = __halves2half2(la, lb);
    hi = *reinterpret_cast<uint32_t*>(&H);
    lo = *reinterpret_cast<uint32_t*>(&L);
}
__device__ __forceinline__ uint32_t pack_h(float a, float b) {
    __half2 H = __halves2half2(__float2half_rn(a), __float2half_rn(b));
    return *reinterpret_cast<uint32_t*>(&H);
}

#define LOG2E 1.44269504088896340736f

// ---------------------------------------------------------------------------
// Common swizzle for 128B-row tiles (row-major, 8 x 16B chunks per row)
// ---------------------------------------------------------------------------
__device__ __forceinline__ uint32_t asw(int row, int chunk) {
    return (uint32_t)(row * 128 + ((chunk ^ (row & 7)) * 16));
}

// ---------------------------------------------------------------------------
// x fp32 -> fp16 hi/lo
// ---------------------------------------------------------------------------
__global__ __launch_bounds__(256) void splitx_kernel(
    const float* __restrict__ in, __half* __restrict__ hi,
    __half* __restrict__ lo, int n4)
{
    int i = blockIdx.x * blockDim.x + threadIdx.x;
    if (i >= n4) return;
    float4 v = ((const float4*)in)[i];
    uint32_t h0, l0, h1, l1;
    pack_split(v.x, v.y, h0, l0);
    pack_split(v.z, v.w, h1, l1);
    ((uint32_t*)hi)[2*i]   = h0;
    ((uint32_t*)hi)[2*i+1] = h1;
    ((uint32_t*)lo)[2*i]   = l0;
    ((uint32_t*)lo)[2*i+1] = l1;
}

// ---------------------------------------------------------------------------
// Weight transpose + fp16 hi/lo split, all 4 big weights in one launch
// ---------------------------------------------------------------------------
__global__ __launch_bounds__(256) void wsplit_kernel(
    const float* __restrict__ W0, const float* __restrict__ W1,
    const float* __restrict__ W2, const float* __restrict__ W3,
    __half* __restrict__ H0, __half* __restrict__ L0,
    __half* __restrict__ H1, __half* __restrict__ L1,
    __half* __restrict__ H2, __half* __restrict__ L2,
    __half* __restrict__ H3, __half* __restrict__ L3)
{
    const int z = blockIdx.z;
    const float* W  = (z == 0) ? W0 : (z == 1) ? W1 : (z == 2) ? W2 : W3;
    __half* Whi     = (z == 0) ? H0 : (z == 1) ? H1 : (z == 2) ? H2 : H3;
    __half* Wlo     = (z == 0) ? L0 : (z == 1) ? L1 : (z == 2) ? L2 : L3;

    __shared__ float t[32][33];
    const int tx = threadIdx.x, ty = threadIdx.y;
    const int bx = blockIdx.x * 32;
    const int by = blockIdx.y * 32;
#pragma unroll
    for (int j = 0; j < 32; j += 8)
        t[ty + j][tx] = W[(size_t)(by + ty + j) * DD + bx + tx];
    __syncthreads();
#pragma unroll
    for (int j = 0; j < 32; j += 8) {
        float v = t[tx][ty + j];
        __half h = __float2half_rn(v);
        __half l = __float2half_rn(v - __half2float(h));
        size_t idx = (size_t)(bx + ty + j) * DD + by + tx;
        Whi[idx] = h;
        Wlo[idx] = l;
    }
}

// ---------------------------------------------------------------------------
// Wf [1024][16] fp32 -> WfT hi/lo [16][1024] fp16
// ---------------------------------------------------------------------------
__global__ __launch_bounds__(256) void wftsplit_kernel(
    const float* __restrict__ Wf,
    __half* __restrict__ Th, __half* __restrict__ Tl)
{
    int idx = blockIdx.x * 256 + threadIdx.x;
    int h = idx >> 10;
    int d = idx & 1023;
    float v = Wf[d * HH + h];
    __half hi = __float2half_rn(v);
    __half lo = __float2half_rn(v - __half2float(hi));
    Th[h * DD + d] = hi;
    Tl[h * DD + d] = lo;
}

// ---------------------------------------------------------------------------
// Big-GEMM tiles: 128 rows x 64 k fp16 = 16KB, asw-swizzled 128B rows.
// Stage = 3 matrices {A, Bh, Bl} = 48KB, double buffered = 96KB.
// BK=64, 16 iterations, 4 k16-steps per iteration.
// ---------------------------------------------------------------------------
#define GT     16384
#define GSTG   (3*GT)
#define GEMM_SMEM (2*GSTG)   // 98304

// shared mainloop body for 2-product GEMM (A single fp16, B hi/lo)
template<typename EPILOG>
__device__ __forceinline__ void gemm2p_body(
    uint32_t smb, int tid,
    const __half* a_h, const __half* b_h, const __half* b_l,
    EPILOG epi)
{
    const int wid  = tid >> 5;
    const int lane = tid & 31;
    const int wm = (wid & 3) * 32;
    const int wn = (wid >> 2) * 64;

    float acc[2][8][4];
#pragma unroll
    for (int i = 0; i < 2; i++)
#pragma unroll
        for (int j = 0; j < 8; j++)
#pragma unroll
            for (int k = 0; k < 4; k++) acc[i][j][k] = 0.f;

    const int a_row = lane & 15;
    const int a_chk = lane >> 4;
    const int b_mat = lane >> 3;
    const int b_row = (b_mat >> 1) * 8 + (lane & 7);
    const int b_chk = b_mat & 1;

    auto stage = [&](uint32_t sbase, int k0) {
        const __half* bases[3] = { a_h + k0, b_h + k0, b_l + k0 };
#pragma unroll
        for (int mat = 0; mat < 3; mat++) {
#pragma unroll
            for (int i = 0; i < 4; i++) {
                int s = tid + i * 256;
                int row = s >> 3, c = s & 7;
                cp16(sbase + mat * GT + asw(row, c),
                     bases[mat] + (size_t)row * DD + c * 8);
            }
        }
    };

    stage(smb, 0);
    cp_commit();

    for (int it = 0; it < 16; it++) {
        if (it + 1 < 16) {
            stage(smb + ((it + 1) & 1) * GSTG, (it + 1) * 64);
            cp_commit();
            cp_wait<1>();
        } else {
            cp_wait<0>();
        }
        __syncthreads();

        const uint32_t sb = smb + (it & 1) * GSTG;
#pragma unroll
        for (int ks = 0; ks < 4; ks++) {
            uint32_t af[2][4], bh[4][4], bl[4][4];
#pragma unroll
            for (int mt = 0; mt < 2; mt++)
                ldmx4(af[mt], sb + asw(wm + mt * 16 + a_row, ks * 2 + a_chk));
#pragma unroll
            for (int ng = 0; ng < 4; ng++) {
                uint32_t bd = sb + GT + asw(wn + ng * 16 + b_row, ks * 2 + b_chk);
                ldmx4(bh[ng], bd);
                ldmx4(bl[ng], bd + GT);
            }
#pragma unroll
            for (int mt = 0; mt < 2; mt++)
#pragma unroll
                for (int ng = 0; ng < 4; ng++)
#pragma unroll
                    for (int h = 0; h < 2; h++) {
                        float* c = acc[mt][ng * 2 + h];
                        mma16816(c, af[mt], bh[ng][h * 2], bh[ng][h * 2 + 1]);
                        mma16816(c, af[mt], bl[ng][h * 2], bl[ng][h * 2 + 1]);
                    }
        }
        __syncthreads();
    }

    epi(acc, wm, wn, lane);
}

// ---------------------------------------------------------------------------
// Fused QKV GEMM: grid (24, 32). Epilogue: fp16 hi/lo split in [B,H,T,HD].
// ---------------------------------------------------------------------------
__global__ __launch_bounds__(256) void gemm_qkv(
    const __half* __restrict__ xh,
    const __half* __restrict__ wqh, const __half* __restrict__ wql,
    const __half* __restrict__ wkh, const __half* __restrict__ wkl,
    const __half* __restrict__ wvh, const __half* __restrict__ wvl,
    __half* __restrict__ qhi, __half* __restrict__ qlo,
    __half* __restrict__ khi, __half* __restrict__ klo,
    __half* __restrict__ vhi, __half* __restrict__ vlo)
{
    extern __shared__ char smraw[];
    const uint32_t smb = smem_u32(smraw);
    const int tid = threadIdx.x;
    const int nmat = blockIdx.x >> 3;
    const int nloc = (blockIdx.x & 7) * 128;
    const int m0 = blockIdx.y * 128;

    const __half* a_h = xh + (size_t)m0 * DD;
    const __half* b_h = ((nmat == 0) ? wqh : (nmat == 1) ? wkh : wvh)
                        + (size_t)nloc * DD;
    const __half* b_l = ((nmat == 0) ? wql : (nmat == 1) ? wkl : wvl)
                        + (size_t)nloc * DD;
    __half* Chi = (nmat == 0) ? qhi : (nmat == 1) ? khi : vhi;
    __half* Clo = (nmat == 0) ? qlo : (nmat == 1) ? klo : vlo;

    gemm2p_body(smb, tid, a_h, b_h, b_l,
        [&](float acc[2][8][4], int wm, int wn, int lane) {
            const int r0 = lane >> 2;
            const int cpair = (lane & 3) * 2;
#pragma unroll
            for (int mt = 0; mt < 2; mt++) {
#pragma unroll
                for (int nt = 0; nt < 8; nt++) {
                    const int m = m0 + wm + mt * 16 + r0;
                    const int n = nloc + wn + nt * 8 + cpair;
                    const int b = m >> 11;
                    const int t = m & (TT - 1);
                    const int h = n >> 6;
                    const int hd = n & (HD - 1);
                    size_t i0 = ((size_t)((b * HH + h) * TT + t) << 6) + hd;
                    size_t i1 = i0 + (size_t)(8 << 6);
                    uint32_t h0, l0, h1, l1;
                    pack_split(acc[mt][nt][0], acc[mt][nt][1], h0, l0);
                    pack_split(acc[mt][nt][2], acc[mt][nt][3], h1, l1);
                    *(uint32_t*)(Chi + i0) = h0;
                    *(uint32_t*)(Clo + i0) = l0;
                    *(uint32_t*)(Chi + i1) = h1;
                    *(uint32_t*)(Clo + i1) = l1;
                }
            }
        });
}

// ---------------------------------------------------------------------------
// Output GEMM: A single fp16, B hi/lo, fp32 row-major store.
// ---------------------------------------------------------------------------
__global__ __launch_bounds__(256) void gemm_out(
    const __half* __restrict__ Ah,
    const __half* __restrict__ Bhi, const __half* __restrict__ Blo,
    float* __restrict__ Cf)
{
    extern __shared__ char smraw[];
    const uint32_t smb = smem_u32(smraw);
    const int tid = threadIdx.x;
    const int n0 = blockIdx.x * 128;
    const int m0 = blockIdx.y * 128;

    const __half* a_h = Ah + (size_t)m0 * DD;
    const __half* b_h = Bhi + (size_t)n0 * DD;
    const __half* b_l = Blo + (size_t)n0 * DD;

    gemm2p_body(smb, tid, a_h, b_h, b_l,
        [&](float acc[2][8][4], int wm, int wn, int lane) {
            const int r0 = lane >> 2;
            const int cpair = (lane & 3) * 2;
#pragma unroll
            for (int mt = 0; mt < 2; mt++) {
#pragma unroll
                for (int nt = 0; nt < 8; nt++) {
                    const int m = m0 + wm + mt * 16 + r0;
                    const int n = n0 + wn + nt * 8 + cpair;
                    float* dst0 = Cf + (size_t)m * DD + n;
                    float* dst1 = Cf + (size_t)(m + 8) * DD + n;
                    *(float2*)dst0 = make_float2(acc[mt][nt][0], acc[mt][nt][1]);
                    *(float2*)dst1 = make_float2(acc[mt][nt][2], acc[mt][nt][3]);
                }
            }
        });
}

// ---------------------------------------------------------------------------
// Forget gate as 3-product split-fp16 MMA GEMM (M=4096,N=16,K=1024)
// ---------------------------------------------------------------------------
#define FG_XL   16384
#define FG_WH   32768
#define FG_WL   34816
#define FG_STG  36864
#define FGM_SMEM (2*FG_STG)   // 73728

__global__ __launch_bounds__(128) void forget_mma(
    const __half* __restrict__ xhi, const __half* __restrict__ xlo,
    const __half* __restrict__ wfh, const __half* __restrict__ wfl,
    const float* __restrict__ bf, float* __restrict__ lf)
{
    extern __shared__ char smraw[];
    const uint32_t smb = smem_u32(smraw);

    const int tid  = threadIdx.x;
    const int wid  = tid >> 5;
    const int lane = tid & 31;
    const int m0 = blockIdx.x * 128;
    const int wm = wid * 32;

    const __half* xh_ = xhi + (size_t)m0 * DD;
    const __half* xl_ = xlo + (size_t)m0 * DD;

    float acc[2][2][4];
#pragma unroll
    for (int i = 0; i < 2; i++)
#pragma unroll
        for (int j = 0; j < 2; j++)
#pragma unroll
            for (int k = 0; k < 4; k++) acc[i][j][k] = 0.f;

    const int a_row = lane & 15;
    const int a_chk = lane >> 4;
    const int b_mat = lane >> 3;
    const int b_row = (b_mat >> 1) * 8 + (lane & 7);
    const int b_chk = b_mat & 1;

    auto stage = [&](uint32_t sbase, int k0) {
#pragma unroll
        for (int i = 0; i < 8; i++) {
            int s = tid + i * 128;
            int row = s >> 3, c = s & 7;
            cp16(sbase + asw(row, c),         xh_ + (size_t)row * DD + k0 + c * 8);
            cp16(sbase + FG_XL + asw(row, c), xl_ + (size_t)row * DD + k0 + c * 8);
        }
        {
            int row = tid >> 3, c = tid & 7;
            cp16(sbase + FG_WH + asw(row, c), wfh + (size_t)row * DD + k0 + c * 8);
            cp16(sbase + FG_WL + asw(row, c), wfl + (size_t)row * DD + k0 + c * 8);
        }
    };

    stage(smb, 0);
    cp_commit();

    for (int it = 0; it < 16; it++) {
        if (it + 1 < 16) {
            stage(smb + ((it + 1) & 1) * FG_STG, (it + 1) * 64);
            cp_commit();
            cp_wait<1>();
        } else {
            cp_wait<0>();
        }
        __syncthreads();

        const uint32_t sb = smb + (it & 1) * FG_STG;
#pragma unroll
        for (int ks = 0; ks < 4; ks++) {
            uint32_t ah[2][4], al[2][4], bh[4], bl[4];
#pragma unroll
            for (int mt = 0; mt < 2; mt++) {
                uint32_t aoff = asw(wm + mt * 16 + a_row, ks * 2 + a_chk);
                ldmx4(ah[mt], sb + aoff);
                ldmx4(al[mt], sb + FG_XL + aoff);
            }
            {
                uint32_t boff = asw(b_row, ks * 2 + b_chk);
                ldmx4(bh, sb + FG_WH + boff);
                ldmx4(bl, sb + FG_WL + boff);
            }
#pragma unroll
            for (int mt = 0; mt < 2; mt++)
#pragma unroll
                for (int h = 0; h < 2; h++) {
                    float* c = acc[mt][h];
                    mma16816(c, ah[mt], bh[h * 2], bh[h * 2 + 1]);
                    mma16816(c, ah[mt], bl[h * 2], bl[h * 2 + 1]);
                    mma16816(c, al[mt], bh[h * 2], bh[h * 2 + 1]);
                }
        }
        __syncthreads();
    }

    const int r0 = lane >> 2;
    const int cpair = (lane & 3) * 2;
#pragma unroll
    for (int mt = 0; mt < 2; mt++) {
#pragma unroll
        for (int nt = 0; nt < 2; nt++) {
            const int h0 = nt * 8 + cpair;
            const float bf0 = bf[h0], bf1 = bf[h0 + 1];
#pragma unroll
            for (int half = 0; half < 2; half++) {
                const int m = m0 + wm + mt * 16 + r0 + half * 8;
                const int b = m >> 11;
                const int t = m & (TT - 1);
                float z0 = acc[mt][nt][half * 2]     + bf0;
                float z1 = acc[mt][nt][half * 2 + 1] + bf1;
                float ls0 = (z0 >= 0.f) ? -log1pf(__expf(-z0))
                                        : z0 - log1pf(__expf(z0));
                float ls1 = (z1 >= 0.f) ? -log1pf(__expf(-z1))
                                        : z1 - log1pf(__expf(z1));
                ls0 = fminf(fmaxf(ls0, -10.f), 0.f);
                ls1 = fminf(fmaxf(ls1, -10.f), 0.f);
                lf[(size_t)(b * HH + h0)     * TT + t] = ls0;
                lf[(size_t)(b * HH + h0 + 1) * TT + t] = ls1;
            }
        }
    }
}

// ---------------------------------------------------------------------------
// Cumsum over T per (b,h)
// ---------------------------------------------------------------------------
__global__ __launch_bounds__(256) void cumsum_kernel(float* __restrict__ lf)
{
    const int bh = blockIdx.x;
    float* p = lf + (size_t)bh * TT;
    const int tid = threadIdx.x;
    const int lane = tid & 31, wid = tid >> 5;
    __shared__ float wsum[8];

    float v[8];
    float s = 0.f;
#pragma unroll
    for (int i = 0; i < 8; i++) { v[i] = p[tid * 8 + i]; s += v[i]; }

    float ss = s;
#pragma unroll
    for (int off = 1; off < 32; off <<= 1) {
        float n = __shfl_up_sync(0xffffffffu, ss, off);
        if (lane >= off) ss += n;
    }
    if (lane == 31) wsum[wid] = ss;
    __syncthreads();
    float woff = 0.f;
#pragma unroll
    for (int w = 0; w < 8; w++)
        if (w < wid) woff += wsum[w];

    float run = woff + ss - s;
#pragma unroll
    for (int i = 0; i < 8; i++) { run += v[i]; p[tid * 8 + i] = run; }
}

// ---------------------------------------------------------------------------
// HMMA forgetting attention (fp16 splits), decay-window skip, single-fp16 out.
// ---------------------------------------------------------------------------
#define ATILE  8192
#define ACKS   (4*ATILE)
#define ASTAGE (4*ATILE + 256)
#define AQOFF  (2*ASTAGE)
#define ATTN_SMEM (2*ASTAGE + 2*ATILE)

__device__ __forceinline__ void attn_stage(
    uint32_t sb,
    const __half* Kh, const __half* Kl,
    const __half* Vh, const __half* Vl,
    const float* cptr, int k0, int tid)
{
    const __half* mats[4] = {
        Kh + (size_t)k0 * HD, Kl + (size_t)k0 * HD,
        Vh + (size_t)k0 * HD, Vl + (size_t)k0 * HD };
#pragma unroll
    for (int mt = 0; mt < 4; mt++) {
#pragma unroll
        for (int i = 0; i < 4; i++) {
            int s = tid + i * 128;
            int row = s >> 3, c = s & 7;
            cp16(sb + mt * ATILE + asw(row, c), mats[mt] + row * HD + c * 8);
        }
    }
    if (tid < 16) cp16(sb + ACKS + tid * 16, cptr + k0 + tid * 4);
}

__global__ __launch_bounds__(128) void attn_mma(
    const __half* __restrict__ Qhi, const __half* __restrict__ Qlo,
    const __half* __restrict__ Khi, const __half* __restrict__ Klo,
    const __half* __restrict__ Vhi, const __half* __restrict__ Vlo,
    const float* __restrict__ C,
    __half* __restrict__ Ohi)
{
    extern __shared__ char smraw[];
    const uint32_t smb = smem_u32(smraw);

    const int tid  = threadIdx.x;
    const int wid  = tid >> 5;
    const int lane = tid & 31;
    const int qt = blockIdx.x;
    const int bh = blockIdx.y;
    const int q0 = qt * 64;

    const __half* Qh = Qhi + (size_t)bh * TT * HD;
    const __half* Ql = Qlo + (size_t)bh * TT * HD;
    const __half* Kh = Khi + (size_t)bh * TT * HD;
    const __half* Kl = Klo + (size_t)bh * TT * HD;
    const __half* Vh = Vhi + (size_t)bh * TT * HD;
    const __half* Vl = Vlo + (size_t)bh * TT * HD;
    const float* cptr = C + (size_t)bh * TT;

    int kt_start;
    {
        const float cq0v = cptr[q0];
        int lo = 0, hi = qt;
        while (lo < hi) {
            int mid = (lo + hi) >> 1;
            if (cq0v - cptr[mid * 64 + 63] >= -60.f) hi = mid;
            else lo = mid + 1;
        }
        kt_start = lo;
    }

#pragma unroll
    for (int i = 0; i < 8; i++) {
        int s = tid + i * 128;
        int mat = s >> 9;
        int rc = s & 511;
        int row = rc >> 3, c = rc & 7;
        const __half* src = (mat == 0 ? Qh : Ql);
        cp16(smb + AQOFF + mat * ATILE + asw(row, c),
             src + (size_t)(q0 + row) * HD + c * 8);
    }
    cp_commit();
    cp_wait<0>();
    __syncthreads();

    const int a_row = lane & 15;
    const int a_chk = lane >> 4;
    uint32_t qh[4][4], ql[4][4];
#pragma unroll
    for (int ks = 0; ks < 4; ks++) {
        uint32_t ad = smb + AQOFF + asw(wid * 16 + a_row, ks * 2 + a_chk);
        ldmx4(qh[ks], ad);
        ldmx4(ql[ks], ad + ATILE);
    }

    const int r0 = wid * 16 + (lane >> 2);
    const float cq0 = cptr[q0 + r0];
    const float cq1 = cptr[q0 + r0 + 8];

    float m0 = -1e30f, m1 = -1e30f, l0 = 0.f, l1 = 0.f;
    float o[8][4];
#pragma unroll
    for (int i = 0; i < 8; i++)
#pragma unroll
        for (int j = 0; j < 4; j++) o[i][j] = 0.f;

    const int b_mat = lane >> 3;
    const int b_row = (b_mat >> 1) * 8 + (lane & 7);
    const int b_chk = b_mat & 1;
    const int v_g = lane >> 3;
    const int v_r = lane & 7;

    attn_stage(smb + (kt_start & 1) * ASTAGE, Kh, Kl, Vh, Vl, cptr,
               kt_start * 64, tid);
    cp_commit();

    for (int kt = kt_start; kt <= qt; kt++) {
        if (kt < qt) {
            attn_stage(smb + ((kt + 1) & 1) * ASTAGE,
                       Kh, Kl, Vh, Vl, cptr, (kt + 1) * 64, tid);
            cp_commit();
            cp_wait<1>();
        } else {
            cp_wait<0>();
        }
        __syncthreads();

        const uint32_t sb = smb + (kt & 1) * ASTAGE;
        const float* cks = (const float*)(smraw + (kt & 1) * ASTAGE + ACKS);

        float s[8][4];
#pragma unroll
        for (int i = 0; i < 8; i++)
#pragma unroll
            for (int j = 0; j < 4; j++) s[i][j] = 0.f;

#pragma unroll
        for (int ks = 0; ks < 4; ks++) {
            uint32_t kh[4][4], kl[4][4];
#pragma unroll
            for (int ng = 0; ng < 4; ng++) {
                uint32_t bd = sb + asw(ng * 16 + b_row, ks * 2 + b_chk);
                ldmx4(kh[ng], bd);
                ldmx4(kl[ng], bd + ATILE);
            }
#pragma unroll
            for (int ng = 0; ng < 4; ng++)
#pragma unroll
                for (int h = 0; h < 2; h++) {
                    float* c = s[ng * 2 + h];
                    mma16816(c, qh[ks], kh[ng][h * 2], kh[ng][h * 2 + 1]);
                    mma16816(c, qh[ks], kl[ng][h * 2], kl[ng][h * 2 + 1]);
                    mma16816(c, ql[ks], kh[ng][h * 2], kh[ng][h * 2 + 1]);
                }
        }

        const bool diag = (kt == qt);
        const int k0g = kt * 64;
#pragma unroll
        for (int nt = 0; nt < 8; nt++) {
            const int col = nt * 8 + (lane & 3) * 2;
            const float ck0 = cks[col], ck1 = cks[col + 1];
            float d00 = fmaxf(cq0 - ck0, -50.f);
            float d01 = fmaxf(cq0 - ck1, -50.f);
            float d10 = fmaxf(cq1 - ck0, -50.f);
            float d11 = fmaxf(cq1 - ck1, -50.f);
            s[nt][0] = fmaf(s[nt][0], 0.125f, d00);
            s[nt][1] = fmaf(s[nt][1], 0.125f, d01);
            s[nt][2] = fmaf(s[nt][2], 0.125f, d10);
            s[nt][3] = fmaf(s[nt][3], 0.125f, d11);
            if (diag) {
                if (k0g + col     > q0 + r0)     s[nt][0] = -1e30f;
                if (k0g + col + 1 > q0 + r0)     s[nt][1] = -1e30f;
                if (k0g + col     > q0 + r0 + 8) s[nt][2] = -1e30f;
                if (k0g + col + 1 > q0 + r0 + 8) s[nt][3] = -1e30f;
            }
        }

        float ml0 = -1e30f, ml1 = -1e30f;
#pragma unroll
        for (int nt = 0; nt < 8; nt++) {
            ml0 = fmaxf(ml0, fmaxf(s[nt][0], s[nt][1]));
            ml1 = fmaxf(ml1, fmaxf(s[nt][2], s[nt][3]));
        }
        ml0 = fmaxf(ml0, __shfl_xor_sync(0xffffffffu, ml0, 1));
        ml0 = fmaxf(ml0, __shfl_xor_sync(0xffffffffu, ml0, 2));
        ml1 = fmaxf(ml1, __shfl_xor_sync(0xffffffffu, ml1, 1));
        ml1 = fmaxf(ml1, __shfl_xor_sync(0xffffffffu, ml1, 2));
        const float mn0 = fmaxf(m0, ml0);
        const float mn1 = fmaxf(m1, ml1);
        const float corr0 = ex2f((m0 - mn0) * LOG2E);
        const float corr1 = ex2f((m1 - mn1) * LOG2E);
        m0 = mn0; m1 = mn1;

        float sum0 = 0.f, sum1 = 0.f;
#pragma unroll
        for (int nt = 0; nt < 8; nt++) {
            s[nt][0] = ex2f((s[nt][0] - mn0) * LOG2E);
            s[nt][1] = ex2f((s[nt][1] - mn0) * LOG2E);
            s[nt][2] = ex2f((s[nt][2] - mn1) * LOG2E);
            s[nt][3] = ex2f((s[nt][3] - mn1) * LOG2E);
            sum0 += s[nt][0] + s[nt][1];
            sum1 += s[nt][2] + s[nt][3];
        }
        l0 = l0 * corr0 + sum0;
        l1 = l1 * corr1 + sum1;
#pragma unroll
        for (int nt = 0; nt < 8; nt++) {
            o[nt][0] *= corr0; o[nt][1] *= corr0;
            o[nt][2] *= corr1; o[nt][3] *= corr1;
        }

        uint32_t ph[4][4], pl[4][4];
#pragma unroll
        for (int kc = 0; kc < 4; kc++) {
            pack_split(s[kc*2][0],   s[kc*2][1],   ph[kc][0], pl[kc][0]);
            pack_split(s[kc*2][2],   s[kc*2][3],   ph[kc][1], pl[kc][1]);
            pack_split(s[kc*2+1][0], s[kc*2+1][1], ph[kc][2], pl[kc][2]);
            pack_split(s[kc*2+1][2], s[kc*2+1][3], ph[kc][3], pl[kc][3]);
        }

#pragma unroll
        for (int kc = 0; kc < 4; kc++) {
            uint32_t vh[4][4], vl[4][4];
#pragma unroll
            for (int p = 0; p < 4; p++) {
                int row = kc * 16 + (v_g & 1) * 8 + v_r;
                int chunk = p * 2 + (v_g >> 1);
                uint32_t vd = sb + 2 * ATILE + asw(row, chunk);
                ldmx4t(vh[p], vd);
                ldmx4t(vl[p], vd + ATILE);
            }
#pragma unroll
            for (int p = 0; p < 4; p++)
#pragma unroll
                for (int h = 0; h < 2; h++) {
                    float* c = o[p * 2 + h];
                    mma16816(c, ph[kc], vh[p][h * 2], vh[p][h * 2 + 1]);
                    mma16816(c, ph[kc], vl[p][h * 2], vl[p][h * 2 + 1]);
                    mma16816(c, pl[kc], vh[p][h * 2], vh[p][h * 2 + 1]);
                }
        }
        __syncthreads();
    }

    l0 += __shfl_xor_sync(0xffffffffu, l0, 1);
    l0 += __shfl_xor_sync(0xffffffffu, l0, 2);
    l1 += __shfl_xor_sync(0xffffffffu, l1, 1);
    l1 += __shfl_xor_sync(0xffffffffu, l1, 2);
    const float inv0 = 1.f / l0;
    const float inv1 = 1.f / l1;

    const int b = bh >> 4, h = bh & 15;
    const int t0 = q0 + r0;
    size_t base0 = ((size_t)(b * TT + t0)) * DD + h * HD;
    size_t base1 = base0 + (size_t)8 * DD;
#pragma unroll
    for (int nt = 0; nt < 8; nt++) {
        const int col = nt * 8 + (lane & 3) * 2;
        *(uint32_t*)(Ohi + base0 + col) = pack_h(o[nt][0] * inv0, o[nt][1] * inv0);
        *(uint32_t*)(Ohi + base1 + col) = pack_h(o[nt][2] * inv1, o[nt][3] * inv1);
    }
}

// ---------------------------------------------------------------------------
// kernel_launch
// ---------------------------------------------------------------------------
extern "C" void kernel_launch(void* const* d_in, const int* in_sizes, int n_in,
                              void* d_out, int out_size)
{
    (void)in_sizes; (void)n_in; (void)out_size;
    const float* x  = (const float*)d_in[0];
    const float* Wq = (const float*)d_in[1];
    const float* Wk = (const float*)d_in[2];
    const float* Wv = (const float*)d_in[3];
    const float* Wo = (const float*)d_in[4];
    const float* Wf = (const float*)d_in[5];
    const float* bf = (const float*)d_in[6];
    float* out = (float*)d_out;

    float* cp;
    cudaGetSymbolAddress((void**)&cp, g_c);

    __half *xhi, *xlo, *ohi;
    __half *qhi, *qlo, *khi, *klo, *vhi, *vlo;
    __half *wqh, *wql, *wkh, *wkl, *wvh, *wvl, *woh, *wol, *wfth, *wftl;
    cudaGetSymbolAddress((void**)&xhi, g_xhi);
    cudaGetSymbolAddress((void**)&xlo, g_xlo);
    cudaGetSymbolAddress((void**)&ohi, g_ohi);
    cudaGetSymbolAddress((void**)&qhi, g_qhi);
    cudaGetSymbolAddress((void**)&qlo, g_qlo);
    cudaGetSymbolAddress((void**)&khi, g_khi);
    cudaGetSymbolAddress((void**)&klo, g_klo);
    cudaGetSymbolAddress((void**)&vhi, g_vhi);
    cudaGetSymbolAddress((void**)&vlo, g_vlo);
    cudaGetSymbolAddress((void**)&wqh, g_wqh);
    cudaGetSymbolAddress((void**)&wql, g_wql);
    cudaGetSymbolAddress((void**)&wkh, g_wkh);
    cudaGetSymbolAddress((void**)&wkl, g_wkl);
    cudaGetSymbolAddress((void**)&wvh, g_wvh);
    cudaGetSymbolAddress((void**)&wvl, g_wvl);
    cudaGetSymbolAddress((void**)&woh, g_woh);
    cudaGetSymbolAddress((void**)&wol, g_wol);
    cudaGetSymbolAddress((void**)&wfth, g_wfth);
    cudaGetSymbolAddress((void**)&wftl, g_wftl);

    cudaFuncSetAttribute(gemm_qkv,
                         cudaFuncAttributeMaxDynamicSharedMemorySize, GEMM_SMEM);
    cudaFuncSetAttribute(gemm_out,
                         cudaFuncAttributeMaxDynamicSharedMemorySize, GEMM_SMEM);
    cudaFuncSetAttribute(attn_mma,
                         cudaFuncAttributeMaxDynamicSharedMemorySize, ATTN_SMEM);
    cudaFuncSetAttribute(forget_mma,
                         cudaFuncAttributeMaxDynamicSharedMemorySize, FGM_SMEM);

    splitx_kernel<<<MM*DD/4/256, 256>>>(x, xhi, xlo, MM*DD/4);
    wsplit_kernel<<<dim3(32, 32, 4), dim3(32, 8)>>>(
        Wq, Wk, Wv, Wo,
        wqh, wql, wkh, wkl, wvh, wvl, woh, wol);
    wftsplit_kernel<<<64, 256>>>(Wf, wfth, wftl);

    gemm_qkv<<<dim3(24, 32), 256, GEMM_SMEM>>>(
        xhi, wqh, wql, wkh, wkl, wvh, wvl,
        qhi, qlo, khi, klo, vhi, vlo);

    forget_mma<<<MM / 128, 128, FGM_SMEM>>>(xhi, xlo, wfth, wftl, bf, cp);
    cumsum_kernel<<<BB * HH, 256>>>(cp);

    attn_mma<<<dim3(TT / 64, BB * HH), 128, ATTN_SMEM>>>(
        qhi, qlo, khi, klo, vhi, vlo, cp, ohi);

    gemm_out<<<dim3(DD / 128, MM / 128), 256, GEMM_SMEM>>>(
        ohi, woh, wol, out);
}

// round 9
// speedup vs baseline: 14.4395x; 1.0935x over previous
#include <cuda_runtime.h>
#include <cuda_fp16.h>
#include <math.h>
#include <stdint.h>

// Problem constants
#define BB 2
#define TT 2048
#define DD 1024
#define HH 16
#define HD 64
#define MM (BB*TT)   // 4096

// ---------------------------------------------------------------------------
// Scratch (device globals; no allocation allowed)
// ---------------------------------------------------------------------------
__device__ float g_c[BB*HH*TT];

__device__ __half g_xhi[MM*DD], g_xlo[MM*DD];        // x hi/lo fp16
__device__ __half g_qhi[MM*DD], g_qlo[MM*DD];        // [B,H,T,HD]
__device__ __half g_khi[MM*DD], g_klo[MM*DD];
__device__ __half g_vhi[MM*DD], g_vlo[MM*DD];
__device__ __half g_ohi[MM*DD];                      // attention out, single fp16
__device__ __half g_wqh[DD*DD], g_wql[DD*DD];        // Wt hi/lo [N][K]
__device__ __half g_wkh[DD*DD], g_wkl[DD*DD];
__device__ __half g_wvh[DD*DD], g_wvl[DD*DD];
__device__ __half g_woh[DD*DD], g_wol[DD*DD];
__device__ __half g_wfth[HH*DD], g_wftl[HH*DD];      // WfT hi/lo [16][1024]

// ---------------------------------------------------------------------------
// PTX helpers
// ---------------------------------------------------------------------------
__device__ __forceinline__ uint32_t smem_u32(const void* p) {
    uint32_t a;
    asm("{ .reg .u64 t; cvta.to.shared.u64 t, %1; cvt.u32.u64 %0, t; }"
        : "=r"(a) : "l"(p));
    return a;
}
__device__ __forceinline__ void cp16(uint32_t dst, const void* src) {
    asm volatile("cp.async.cg.shared.global [%0], [%1], 16;"
                 :: "r"(dst), "l"(src) : "memory");
}
__device__ __forceinline__ void cp_commit() {
    asm volatile("cp.async.commit_group;" ::: "memory");
}
template<int N> __device__ __forceinline__ void cp_wait() {
    asm volatile("cp.async.wait_group %0;" :: "n"(N) : "memory");
}
__device__ __forceinline__ void ldmx4(uint32_t* r, uint32_t addr) {
    asm volatile("ldmatrix.sync.aligned.m8n8.x4.shared.b16 {%0,%1,%2,%3}, [%4];"
                 : "=r"(r[0]), "=r"(r[1]), "=r"(r[2]), "=r"(r[3]) : "r"(addr));
}
__device__ __forceinline__ void ldmx4t(uint32_t* r, uint32_t addr) {
    asm volatile("ldmatrix.sync.aligned.m8n8.x4.trans.shared.b16 {%0,%1,%2,%3}, [%4];"
                 : "=r"(r[0]), "=r"(r[1]), "=r"(r[2]), "=r"(r[3]) : "r"(addr));
}
__device__ __forceinline__ void mma16816(float* c, const uint32_t* a,
                                         uint32_t b0, uint32_t b1) {
    asm volatile(
        "mma.sync.aligned.m16n8k16.row.col.f32.f16.f16.f32 "
        "{%0,%1,%2,%3}, {%4,%5,%6,%7}, {%8,%9}, {%0,%1,%2,%3};"
        : "+f"(c[0]), "+f"(c[1]), "+f"(c[2]), "+f"(c[3])
        : "r"(a[0]), "r"(a[1]), "r"(a[2]), "r"(a[3]), "r"(b0), "r"(b1));
}
__device__ __forceinline__ float ex2f(float x) {
    float r;
    asm("ex2.approx.ftz.f32 %0, %1;" : "=f"(r) : "f"(x));
    return r;
}
__device__ __forceinline__ void pack_split(float a, float b,
                                           uint32_t& hi, uint32_t& lo) {
    __half ha = __float2half_rn(a);
    __half hb = __float2half_rn(b);
    __half la = __float2half_rn(a - __half2float(ha));
    __half lb = __float2half_rn(b - __half2float(hb));
    __half2 H = __halves2half2(ha, hb);
    __half2 L = __halves2half2(la, lb);
    hi = *reinterpret_cast<uint32_t*>(&H);
    lo = *reinterpret_cast<uint32_t*>(&L);
}
__device__ __forceinline__ uint32_t pack_h(float a, float b) {
    __half2 H = __halves2half2(__float2half_rn(a), __float2half_rn(b));
    return *reinterpret_cast<uint32_t*>(&H);
}

#define LOG2E 1.44269504088896340736f

// ---------------------------------------------------------------------------
// Common swizzle for 128B-row tiles (row-major, 8 x 16B chunks per row)
// ---------------------------------------------------------------------------
__device__ __forceinline__ uint32_t asw(int row, int chunk) {
    return (uint32_t)(row * 128 + ((chunk ^ (row & 7)) * 16));
}

// ---------------------------------------------------------------------------
// x fp32 -> fp16 hi/lo
// ---------------------------------------------------------------------------
__global__ __launch_bounds__(256) void splitx_kernel(
    const float* __restrict__ in, __half* __restrict__ hi,
    __half* __restrict__ lo, int n4)
{
    int i = blockIdx.x * blockDim.x + threadIdx.x;
    if (i >= n4) return;
    float4 v = ((const float4*)in)[i];
    uint32_t h0, l0, h1, l1;
    pack_split(v.x, v.y, h0, l0);
    pack_split(v.z, v.w, h1, l1);
    ((uint32_t*)hi)[2*i]   = h0;
    ((uint32_t*)hi)[2*i+1] = h1;
    ((uint32_t*)lo)[2*i]   = l0;
    ((uint32_t*)lo)[2*i+1] = l1;
}

// ---------------------------------------------------------------------------
// Weight transpose + fp16 hi/lo split, all 4 big weights in one launch
// ---------------------------------------------------------------------------
__global__ __launch_bounds__(256) void wsplit_kernel(
    const float* __restrict__ W0, const float* __restrict__ W1,
    const float* __restrict__ W2, const float* __restrict__ W3,
    __half* __restrict__ H0, __half* __restrict__ L0,
    __half* __restrict__ H1, __half* __restrict__ L1,
    __half* __restrict__ H2, __half* __restrict__ L2,
    __half* __restrict__ H3, __half* __restrict__ L3)
{
    const int z = blockIdx.z;
    const float* W  = (z == 0) ? W0 : (z == 1) ? W1 : (z == 2) ? W2 : W3;
    __half* Whi     = (z == 0) ? H0 : (z == 1) ? H1 : (z == 2) ? H2 : H3;
    __half* Wlo     = (z == 0) ? L0 : (z == 1) ? L1 : (z == 2) ? L2 : L3;

    __shared__ float t[32][33];
    const int tx = threadIdx.x, ty = threadIdx.y;
    const int bx = blockIdx.x * 32;
    const int by = blockIdx.y * 32;
#pragma unroll
    for (int j = 0; j < 32; j += 8)
        t[ty + j][tx] = W[(size_t)(by + ty + j) * DD + bx + tx];
    __syncthreads();
#pragma unroll
    for (int j = 0; j < 32; j += 8) {
        float v = t[tx][ty + j];
        __half h = __float2half_rn(v);
        __half l = __float2half_rn(v - __half2float(h));
        size_t idx = (size_t)(bx + ty + j) * DD + by + tx;
        Whi[idx] = h;
        Wlo[idx] = l;
    }
}

// ---------------------------------------------------------------------------
// Wf [1024][16] fp32 -> WfT hi/lo [16][1024] fp16
// ---------------------------------------------------------------------------
__global__ __launch_bounds__(256) void wftsplit_kernel(
    const float* __restrict__ Wf,
    __half* __restrict__ Th, __half* __restrict__ Tl)
{
    int idx = blockIdx.x * 256 + threadIdx.x;
    int h = idx >> 10;
    int d = idx & 1023;
    float v = Wf[d * HH + h];
    __half hi = __float2half_rn(v);
    __half lo = __float2half_rn(v - __half2float(hi));
    Th[h * DD + d] = hi;
    Tl[h * DD + d] = lo;
}

// ---------------------------------------------------------------------------
// Big-GEMM tiles: 128 rows x 64 k fp16 = 16KB, asw-swizzled 128B rows.
// Stage = 3 matrices {A, Bh, Bl} = 48KB, double buffered = 96KB.
// __launch_bounds__(256,2): cap 128 regs -> 2 CTAs/SM (RF was the blocker).
// ---------------------------------------------------------------------------
#define GT     16384
#define GSTG   (3*GT)
#define GEMM_SMEM (2*GSTG)   // 98304

template<typename EPILOG>
__device__ __forceinline__ void gemm2p_body(
    uint32_t smb, int tid,
    const __half* a_h, const __half* b_h, const __half* b_l,
    EPILOG epi)
{
    const int wid  = tid >> 5;
    const int lane = tid & 31;
    const int wm = (wid & 3) * 32;
    const int wn = (wid >> 2) * 64;

    float acc[2][8][4];
#pragma unroll
    for (int i = 0; i < 2; i++)
#pragma unroll
        for (int j = 0; j < 8; j++)
#pragma unroll
            for (int k = 0; k < 4; k++) acc[i][j][k] = 0.f;

    const int a_row = lane & 15;
    const int a_chk = lane >> 4;
    const int b_mat = lane >> 3;
    const int b_row = (b_mat >> 1) * 8 + (lane & 7);
    const int b_chk = b_mat & 1;

    auto stage = [&](uint32_t sbase, int k0) {
        const __half* bases[3] = { a_h + k0, b_h + k0, b_l + k0 };
#pragma unroll
        for (int mat = 0; mat < 3; mat++) {
#pragma unroll
            for (int i = 0; i < 4; i++) {
                int s = tid + i * 256;
                int row = s >> 3, c = s & 7;
                cp16(sbase + mat * GT + asw(row, c),
                     bases[mat] + (size_t)row * DD + c * 8);
            }
        }
    };

    stage(smb, 0);
    cp_commit();

    for (int it = 0; it < 16; it++) {
        if (it + 1 < 16) {
            stage(smb + ((it + 1) & 1) * GSTG, (it + 1) * 64);
            cp_commit();
            cp_wait<1>();
        } else {
            cp_wait<0>();
        }
        __syncthreads();

        const uint32_t sb = smb + (it & 1) * GSTG;
#pragma unroll
        for (int ks = 0; ks < 4; ks++) {
            uint32_t af[2][4], bh[4][4], bl[4][4];
#pragma unroll
            for (int mt = 0; mt < 2; mt++)
                ldmx4(af[mt], sb + asw(wm + mt * 16 + a_row, ks * 2 + a_chk));
#pragma unroll
            for (int ng = 0; ng < 4; ng++) {
                uint32_t bd = sb + GT + asw(wn + ng * 16 + b_row, ks * 2 + b_chk);
                ldmx4(bh[ng], bd);
                ldmx4(bl[ng], bd + GT);
            }
#pragma unroll
            for (int mt = 0; mt < 2; mt++)
#pragma unroll
                for (int ng = 0; ng < 4; ng++)
#pragma unroll
                    for (int h = 0; h < 2; h++) {
                        float* c = acc[mt][ng * 2 + h];
                        mma16816(c, af[mt], bh[ng][h * 2], bh[ng][h * 2 + 1]);
                        mma16816(c, af[mt], bl[ng][h * 2], bl[ng][h * 2 + 1]);
                    }
        }
        __syncthreads();
    }

    epi(acc, wm, wn, lane);
}

// ---------------------------------------------------------------------------
// Fused QKV GEMM: grid (24, 32). Epilogue: fp16 hi/lo split in [B,H,T,HD].
// ---------------------------------------------------------------------------
__global__ __launch_bounds__(256, 2) void gemm_qkv(
    const __half* __restrict__ xh,
    const __half* __restrict__ wqh, const __half* __restrict__ wql,
    const __half* __restrict__ wkh, const __half* __restrict__ wkl,
    const __half* __restrict__ wvh, const __half* __restrict__ wvl,
    __half* __restrict__ qhi, __half* __restrict__ qlo,
    __half* __restrict__ khi, __half* __restrict__ klo,
    __half* __restrict__ vhi, __half* __restrict__ vlo)
{
    extern __shared__ char smraw[];
    const uint32_t smb = smem_u32(smraw);
    const int tid = threadIdx.x;
    const int nmat = blockIdx.x >> 3;
    const int nloc = (blockIdx.x & 7) * 128;
    const int m0 = blockIdx.y * 128;

    const __half* a_h = xh + (size_t)m0 * DD;
    const __half* b_h = ((nmat == 0) ? wqh : (nmat == 1) ? wkh : wvh)
                        + (size_t)nloc * DD;
    const __half* b_l = ((nmat == 0) ? wql : (nmat == 1) ? wkl : wvl)
                        + (size_t)nloc * DD;
    __half* Chi = (nmat == 0) ? qhi : (nmat == 1) ? khi : vhi;
    __half* Clo = (nmat == 0) ? qlo : (nmat == 1) ? klo : vlo;

    gemm2p_body(smb, tid, a_h, b_h, b_l,
        [&](float acc[2][8][4], int wm, int wn, int lane) {
            const int r0 = lane >> 2;
            const int cpair = (lane & 3) * 2;
#pragma unroll
            for (int mt = 0; mt < 2; mt++) {
#pragma unroll
                for (int nt = 0; nt < 8; nt++) {
                    const int m = m0 + wm + mt * 16 + r0;
                    const int n = nloc + wn + nt * 8 + cpair;
                    const int b = m >> 11;
                    const int t = m & (TT - 1);
                    const int h = n >> 6;
                    const int hd = n & (HD - 1);
                    size_t i0 = ((size_t)((b * HH + h) * TT + t) << 6) + hd;
                    size_t i1 = i0 + (size_t)(8 << 6);
                    uint32_t h0, l0, h1, l1;
                    pack_split(acc[mt][nt][0], acc[mt][nt][1], h0, l0);
                    pack_split(acc[mt][nt][2], acc[mt][nt][3], h1, l1);
                    *(uint32_t*)(Chi + i0) = h0;
                    *(uint32_t*)(Clo + i0) = l0;
                    *(uint32_t*)(Chi + i1) = h1;
                    *(uint32_t*)(Clo + i1) = l1;
                }
            }
        });
}

// ---------------------------------------------------------------------------
// Output GEMM: A single fp16, B hi/lo, fp32 row-major store.
// ---------------------------------------------------------------------------
__global__ __launch_bounds__(256, 2) void gemm_out(
    const __half* __restrict__ Ah,
    const __half* __restrict__ Bhi, const __half* __restrict__ Blo,
    float* __restrict__ Cf)
{
    extern __shared__ char smraw[];
    const uint32_t smb = smem_u32(smraw);
    const int tid = threadIdx.x;
    const int n0 = blockIdx.x * 128;
    const int m0 = blockIdx.y * 128;

    const __half* a_h = Ah + (size_t)m0 * DD;
    const __half* b_h = Bhi + (size_t)n0 * DD;
    const __half* b_l = Blo + (size_t)n0 * DD;

    gemm2p_body(smb, tid, a_h, b_h, b_l,
        [&](float acc[2][8][4], int wm, int wn, int lane) {
            const int r0 = lane >> 2;
            const int cpair = (lane & 3) * 2;
#pragma unroll
            for (int mt = 0; mt < 2; mt++) {
#pragma unroll
                for (int nt = 0; nt < 8; nt++) {
                    const int m = m0 + wm + mt * 16 + r0;
                    const int n = n0 + wn + nt * 8 + cpair;
                    float* dst0 = Cf + (size_t)m * DD + n;
                    float* dst1 = Cf + (size_t)(m + 8) * DD + n;
                    *(float2*)dst0 = make_float2(acc[mt][nt][0], acc[mt][nt][1]);
                    *(float2*)dst1 = make_float2(acc[mt][nt][2], acc[mt][nt][3]);
                }
            }
        });
}

// ---------------------------------------------------------------------------
// Forget gate as 3-product split-fp16 MMA GEMM (M=4096,N=16,K=1024)
// ---------------------------------------------------------------------------
#define FG_XL   16384
#define FG_WH   32768
#define FG_WL   34816
#define FG_STG  36864
#define FGM_SMEM (2*FG_STG)   // 73728

__global__ __launch_bounds__(128) void forget_mma(
    const __half* __restrict__ xhi, const __half* __restrict__ xlo,
    const __half* __restrict__ wfh, const __half* __restrict__ wfl,
    const float* __restrict__ bf, float* __restrict__ lf)
{
    extern __shared__ char smraw[];
    const uint32_t smb = smem_u32(smraw);

    const int tid  = threadIdx.x;
    const int wid  = tid >> 5;
    const int lane = tid & 31;
    const int m0 = blockIdx.x * 128;
    const int wm = wid * 32;

    const __half* xh_ = xhi + (size_t)m0 * DD;
    const __half* xl_ = xlo + (size_t)m0 * DD;

    float acc[2][2][4];
#pragma unroll
    for (int i = 0; i < 2; i++)
#pragma unroll
        for (int j = 0; j < 2; j++)
#pragma unroll
            for (int k = 0; k < 4; k++) acc[i][j][k] = 0.f;

    const int a_row = lane & 15;
    const int a_chk = lane >> 4;
    const int b_mat = lane >> 3;
    const int b_row = (b_mat >> 1) * 8 + (lane & 7);
    const int b_chk = b_mat & 1;

    auto stage = [&](uint32_t sbase, int k0) {
#pragma unroll
        for (int i = 0; i < 8; i++) {
            int s = tid + i * 128;
            int row = s >> 3, c = s & 7;
            cp16(sbase + asw(row, c),         xh_ + (size_t)row * DD + k0 + c * 8);
            cp16(sbase + FG_XL + asw(row, c), xl_ + (size_t)row * DD + k0 + c * 8);
        }
        {
            int row = tid >> 3, c = tid & 7;
            cp16(sbase + FG_WH + asw(row, c), wfh + (size_t)row * DD + k0 + c * 8);
            cp16(sbase + FG_WL + asw(row, c), wfl + (size_t)row * DD + k0 + c * 8);
        }
    };

    stage(smb, 0);
    cp_commit();

    for (int it = 0; it < 16; it++) {
        if (it + 1 < 16) {
            stage(smb + ((it + 1) & 1) * FG_STG, (it + 1) * 64);
            cp_commit();
            cp_wait<1>();
        } else {
            cp_wait<0>();
        }
        __syncthreads();

        const uint32_t sb = smb + (it & 1) * FG_STG;
#pragma unroll
        for (int ks = 0; ks < 4; ks++) {
            uint32_t ah[2][4], al[2][4], bh[4], bl[4];
#pragma unroll
            for (int mt = 0; mt < 2; mt++) {
                uint32_t aoff = asw(wm + mt * 16 + a_row, ks * 2 + a_chk);
                ldmx4(ah[mt], sb + aoff);
                ldmx4(al[mt], sb + FG_XL + aoff);
            }
            {
                uint32_t boff = asw(b_row, ks * 2 + b_chk);
                ldmx4(bh, sb + FG_WH + boff);
                ldmx4(bl, sb + FG_WL + boff);
            }
#pragma unroll
            for (int mt = 0; mt < 2; mt++)
#pragma unroll
                for (int h = 0; h < 2; h++) {
                    float* c = acc[mt][h];
                    mma16816(c, ah[mt], bh[h * 2], bh[h * 2 + 1]);
                    mma16816(c, ah[mt], bl[h * 2], bl[h * 2 + 1]);
                    mma16816(c, al[mt], bh[h * 2], bh[h * 2 + 1]);
                }
        }
        __syncthreads();
    }

    const int r0 = lane >> 2;
    const int cpair = (lane & 3) * 2;
#pragma unroll
    for (int mt = 0; mt < 2; mt++) {
#pragma unroll
        for (int nt = 0; nt < 2; nt++) {
            const int h0 = nt * 8 + cpair;
            const float bf0 = bf[h0], bf1 = bf[h0 + 1];
#pragma unroll
            for (int half = 0; half < 2; half++) {
                const int m = m0 + wm + mt * 16 + r0 + half * 8;
                const int b = m >> 11;
                const int t = m & (TT - 1);
                float z0 = acc[mt][nt][half * 2]     + bf0;
                float z1 = acc[mt][nt][half * 2 + 1] + bf1;
                float ls0 = (z0 >= 0.f) ? -log1pf(__expf(-z0))
                                        : z0 - log1pf(__expf(z0));
                float ls1 = (z1 >= 0.f) ? -log1pf(__expf(-z1))
                                        : z1 - log1pf(__expf(z1));
                ls0 = fminf(fmaxf(ls0, -10.f), 0.f);
                ls1 = fminf(fmaxf(ls1, -10.f), 0.f);
                lf[(size_t)(b * HH + h0)     * TT + t] = ls0;
                lf[(size_t)(b * HH + h0 + 1) * TT + t] = ls1;
            }
        }
    }
}

// ---------------------------------------------------------------------------
// Cumsum over T per (b,h)
// ---------------------------------------------------------------------------
__global__ __launch_bounds__(256) void cumsum_kernel(float* __restrict__ lf)
{
    const int bh = blockIdx.x;
    float* p = lf + (size_t)bh * TT;
    const int tid = threadIdx.x;
    const int lane = tid & 31, wid = tid >> 5;
    __shared__ float wsum[8];

    float v[8];
    float s = 0.f;
#pragma unroll
    for (int i = 0; i < 8; i++) { v[i] = p[tid * 8 + i]; s += v[i]; }

    float ss = s;
#pragma unroll
    for (int off = 1; off < 32; off <<= 1) {
        float n = __shfl_up_sync(0xffffffffu, ss, off);
        if (lane >= off) ss += n;
    }
    if (lane == 31) wsum[wid] = ss;
    __syncthreads();
    float woff = 0.f;
#pragma unroll
    for (int w = 0; w < 8; w++)
        if (w < wid) woff += wsum[w];

    float run = woff + ss - s;
#pragma unroll
    for (int i = 0; i < 8; i++) { run += v[i]; p[tid * 8 + i] = run; }
}

// ---------------------------------------------------------------------------
// HMMA forgetting attention (fp16 splits), decay-window skip, single-fp16 out.
// ---------------------------------------------------------------------------
#define ATILE  8192
#define ACKS   (4*ATILE)
#define ASTAGE (4*ATILE + 256)
#define AQOFF  (2*ASTAGE)
#define ATTN_SMEM (2*ASTAGE + 2*ATILE)

__device__ __forceinline__ void attn_stage(
    uint32_t sb,
    const __half* Kh, const __half* Kl,
    const __half* Vh, const __half* Vl,
    const float* cptr, int k0, int tid)
{
    const __half* mats[4] = {
        Kh + (size_t)k0 * HD, Kl + (size_t)k0 * HD,
        Vh + (size_t)k0 * HD, Vl + (size_t)k0 * HD };
#pragma unroll
    for (int mt = 0; mt < 4; mt++) {
#pragma unroll
        for (int i = 0; i < 4; i++) {
            int s = tid + i * 128;
            int row = s >> 3, c = s & 7;
            cp16(sb + mt * ATILE + asw(row, c), mats[mt] + row * HD + c * 8);
        }
    }
    if (tid < 16) cp16(sb + ACKS + tid * 16, cptr + k0 + tid * 4);
}

__global__ __launch_bounds__(128) void attn_mma(
    const __half* __restrict__ Qhi, const __half* __restrict__ Qlo,
    const __half* __restrict__ Khi, const __half* __restrict__ Klo,
    const __half* __restrict__ Vhi, const __half* __restrict__ Vlo,
    const float* __restrict__ C,
    __half* __restrict__ Ohi)
{
    extern __shared__ char smraw[];
    const uint32_t smb = smem_u32(smraw);

    const int tid  = threadIdx.x;
    const int wid  = tid >> 5;
    const int lane = tid & 31;
    const int qt = blockIdx.x;
    const int bh = blockIdx.y;
    const int q0 = qt * 64;

    const __half* Qh = Qhi + (size_t)bh * TT * HD;
    const __half* Ql = Qlo + (size_t)bh * TT * HD;
    const __half* Kh = Khi + (size_t)bh * TT * HD;
    const __half* Kl = Klo + (size_t)bh * TT * HD;
    const __half* Vh = Vhi + (size_t)bh * TT * HD;
    const __half* Vl = Vlo + (size_t)bh * TT * HD;
    const float* cptr = C + (size_t)bh * TT;

    int kt_start;
    {
        const float cq0v = cptr[q0];
        int lo = 0, hi = qt;
        while (lo < hi) {
            int mid = (lo + hi) >> 1;
            if (cq0v - cptr[mid * 64 + 63] >= -60.f) hi = mid;
            else lo = mid + 1;
        }
        kt_start = lo;
    }

#pragma unroll
    for (int i = 0; i < 8; i++) {
        int s = tid + i * 128;
        int mat = s >> 9;
        int rc = s & 511;
        int row = rc >> 3, c = rc & 7;
        const __half* src = (mat == 0 ? Qh : Ql);
        cp16(smb + AQOFF + mat * ATILE + asw(row, c),
             src + (size_t)(q0 + row) * HD + c * 8);
    }
    cp_commit();
    cp_wait<0>();
    __syncthreads();

    const int a_row = lane & 15;
    const int a_chk = lane >> 4;
    uint32_t qh[4][4], ql[4][4];
#pragma unroll
    for (int ks = 0; ks < 4; ks++) {
        uint32_t ad = smb + AQOFF + asw(wid * 16 + a_row, ks * 2 + a_chk);
        ldmx4(qh[ks], ad);
        ldmx4(ql[ks], ad + ATILE);
    }

    const int r0 = wid * 16 + (lane >> 2);
    const float cq0 = cptr[q0 + r0];
    const float cq1 = cptr[q0 + r0 + 8];

    float m0 = -1e30f, m1 = -1e30f, l0 = 0.f, l1 = 0.f;
    float o[8][4];
#pragma unroll
    for (int i = 0; i < 8; i++)
#pragma unroll
        for (int j = 0; j < 4; j++) o[i][j] = 0.f;

    const int b_mat = lane >> 3;
    const int b_row = (b_mat >> 1) * 8 + (lane & 7);
    const int b_chk = b_mat & 1;
    const int v_g = lane >> 3;
    const int v_r = lane & 7;

    attn_stage(smb + (kt_start & 1) * ASTAGE, Kh, Kl, Vh, Vl, cptr,
               kt_start * 64, tid);
    cp_commit();

    for (int kt = kt_start; kt <= qt; kt++) {
        if (kt < qt) {
            attn_stage(smb + ((kt + 1) & 1) * ASTAGE,
                       Kh, Kl, Vh, Vl, cptr, (kt + 1) * 64, tid);
            cp_commit();
            cp_wait<1>();
        } else {
            cp_wait<0>();
        }
        __syncthreads();

        const uint32_t sb = smb + (kt & 1) * ASTAGE;
        const float* cks = (const float*)(smraw + (kt & 1) * ASTAGE + ACKS);

        float s[8][4];
#pragma unroll
        for (int i = 0; i < 8; i++)
#pragma unroll
            for (int j = 0; j < 4; j++) s[i][j] = 0.f;

#pragma unroll
        for (int ks = 0; ks < 4; ks++) {
            uint32_t kh[4][4], kl[4][4];
#pragma unroll
            for (int ng = 0; ng < 4; ng++) {
                uint32_t bd = sb + asw(ng * 16 + b_row, ks * 2 + b_chk);
                ldmx4(kh[ng], bd);
                ldmx4(kl[ng], bd + ATILE);
            }
#pragma unroll
            for (int ng = 0; ng < 4; ng++)
#pragma unroll
                for (int h = 0; h < 2; h++) {
                    float* c = s[ng * 2 + h];
                    mma16816(c, qh[ks], kh[ng][h * 2], kh[ng][h * 2 + 1]);
                    mma16816(c, qh[ks], kl[ng][h * 2], kl[ng][h * 2 + 1]);
                    mma16816(c, ql[ks], kh[ng][h * 2], kh[ng][h * 2 + 1]);
                }
        }

        const bool diag = (kt == qt);
        const int k0g = kt * 64;
#pragma unroll
        for (int nt = 0; nt < 8; nt++) {
            const int col = nt * 8 + (lane & 3) * 2;
            const float ck0 = cks[col], ck1 = cks[col + 1];
            float d00 = fmaxf(cq0 - ck0, -50.f);
            float d01 = fmaxf(cq0 - ck1, -50.f);
            float d10 = fmaxf(cq1 - ck0, -50.f);
            float d11 = fmaxf(cq1 - ck1, -50.f);
            s[nt][0] = fmaf(s[nt][0], 0.125f, d00);
            s[nt][1] = fmaf(s[nt][1], 0.125f, d01);
            s[nt][2] = fmaf(s[nt][2], 0.125f, d10);
            s[nt][3] = fmaf(s[nt][3], 0.125f, d11);
            if (diag) {
                if (k0g + col     > q0 + r0)     s[nt][0] = -1e30f;
                if (k0g + col + 1 > q0 + r0)     s[nt][1] = -1e30f;
                if (k0g + col     > q0 + r0 + 8) s[nt][2] = -1e30f;
                if (k0g + col + 1 > q0 + r0 + 8) s[nt][3] = -1e30f;
            }
        }

        float ml0 = -1e30f, ml1 = -1e30f;
#pragma unroll
        for (int nt = 0; nt < 8; nt++) {
            ml0 = fmaxf(ml0, fmaxf(s[nt][0], s[nt][1]));
            ml1 = fmaxf(ml1, fmaxf(s[nt][2], s[nt][3]));
        }
        ml0 = fmaxf(ml0, __shfl_xor_sync(0xffffffffu, ml0, 1));
        ml0 = fmaxf(ml0, __shfl_xor_sync(0xffffffffu, ml0, 2));
        ml1 = fmaxf(ml1, __shfl_xor_sync(0xffffffffu, ml1, 1));
        ml1 = fmaxf(ml1, __shfl_xor_sync(0xffffffffu, ml1, 2));
        const float mn0 = fmaxf(m0, ml0);
        const float mn1 = fmaxf(m1, ml1);
        const float corr0 = ex2f((m0 - mn0) * LOG2E);
        const float corr1 = ex2f((m1 - mn1) * LOG2E);
        m0 = mn0; m1 = mn1;

        float sum0 = 0.f, sum1 = 0.f;
#pragma unroll
        for (int nt = 0; nt < 8; nt++) {
            s[nt][0] = ex2f((s[nt][0] - mn0) * LOG2E);
            s[nt][1] = ex2f((s[nt][1] - mn0) * LOG2E);
            s[nt][2] = ex2f((s[nt][2] - mn1) * LOG2E);
            s[nt][3] = ex2f((s[nt][3] - mn1) * LOG2E);
            sum0 += s[nt][0] + s[nt][1];
            sum1 += s[nt][2] + s[nt][3];
        }
        l0 = l0 * corr0 + sum0;
        l1 = l1 * corr1 + sum1;
#pragma unroll
        for (int nt = 0; nt < 8; nt++) {
            o[nt][0] *= corr0; o[nt][1] *= corr0;
            o[nt][2] *= corr1; o[nt][3] *= corr1;
        }

        uint32_t ph[4][4], pl[4][4];
#pragma unroll
        for (int kc = 0; kc < 4; kc++) {
            pack_split(s[kc*2][0],   s[kc*2][1],   ph[kc][0], pl[kc][0]);
            pack_split(s[kc*2][2],   s[kc*2][3],   ph[kc][1], pl[kc][1]);
            pack_split(s[kc*2+1][0], s[kc*2+1][1], ph[kc][2], pl[kc][2]);
            pack_split(s[kc*2+1][2], s[kc*2+1][3], ph[kc][3], pl[kc][3]);
        }

#pragma unroll
        for (int kc = 0; kc < 4; kc++) {
            uint32_t vh[4][4], vl[4][4];
#pragma unroll
            for (int p = 0; p < 4; p++) {
                int row = kc * 16 + (v_g & 1) * 8 + v_r;
                int chunk = p * 2 + (v_g >> 1);
                uint32_t vd = sb + 2 * ATILE + asw(row, chunk);
                ldmx4t(vh[p], vd);
                ldmx4t(vl[p], vd + ATILE);
            }
#pragma unroll
            for (int p = 0; p < 4; p++)
#pragma unroll
                for (int h = 0; h < 2; h++) {
                    float* c = o[p * 2 + h];
                    mma16816(c, ph[kc], vh[p][h * 2], vh[p][h * 2 + 1]);
                    mma16816(c, ph[kc], vl[p][h * 2], vl[p][h * 2 + 1]);
                    mma16816(c, pl[kc], vh[p][h * 2], vh[p][h * 2 + 1]);
                }
        }
        __syncthreads();
    }

    l0 += __shfl_xor_sync(0xffffffffu, l0, 1);
    l0 += __shfl_xor_sync(0xffffffffu, l0, 2);
    l1 += __shfl_xor_sync(0xffffffffu, l1, 1);
    l1 += __shfl_xor_sync(0xffffffffu, l1, 2);
    const float inv0 = 1.f / l0;
    const float inv1 = 1.f / l1;

    const int b = bh >> 4, h = bh & 15;
    const int t0 = q0 + r0;
    size_t base0 = ((size_t)(b * TT + t0)) * DD + h * HD;
    size_t base1 = base0 + (size_t)8 * DD;
#pragma unroll
    for (int nt = 0; nt < 8; nt++) {
        const int col = nt * 8 + (lane & 3) * 2;
        *(uint32_t*)(Ohi + base0 + col) = pack_h(o[nt][0] * inv0, o[nt][1] * inv0);
        *(uint32_t*)(Ohi + base1 + col) = pack_h(o[nt][2] * inv1, o[nt][3] * inv1);
    }
}

// ---------------------------------------------------------------------------
// kernel_launch
// ---------------------------------------------------------------------------
extern "C" void kernel_launch(void* const* d_in, const int* in_sizes, int n_in,
                              void* d_out, int out_size)
{
    (void)in_sizes; (void)n_in; (void)out_size;
    const float* x  = (const float*)d_in[0];
    const float* Wq = (const float*)d_in[1];
    const float* Wk = (const float*)d_in[2];
    const float* Wv = (const float*)d_in[3];
    const float* Wo = (const float*)d_in[4];
    const float* Wf = (const float*)d_in[5];
    const float* bf = (const float*)d_in[6];
    float* out = (float*)d_out;

    float* cp;
    cudaGetSymbolAddress((void**)&cp, g_c);

    __half *xhi, *xlo, *ohi;
    __half *qhi, *qlo, *khi, *klo, *vhi, *vlo;
    __half *wqh, *wql, *wkh, *wkl, *wvh, *wvl, *woh, *wol, *wfth, *wftl;
    cudaGetSymbolAddress((void**)&xhi, g_xhi);
    cudaGetSymbolAddress((void**)&xlo, g_xlo);
    cudaGetSymbolAddress((void**)&ohi, g_ohi);
    cudaGetSymbolAddress((void**)&qhi, g_qhi);
    cudaGetSymbolAddress((void**)&qlo, g_qlo);
    cudaGetSymbolAddress((void**)&khi, g_khi);
    cudaGetSymbolAddress((void**)&klo, g_klo);
    cudaGetSymbolAddress((void**)&vhi, g_vhi);
    cudaGetSymbolAddress((void**)&vlo, g_vlo);
    cudaGetSymbolAddress((void**)&wqh, g_wqh);
    cudaGetSymbolAddress((void**)&wql, g_wql);
    cudaGetSymbolAddress((void**)&wkh, g_wkh);
    cudaGetSymbolAddress((void**)&wkl, g_wkl);
    cudaGetSymbolAddress((void**)&wvh, g_wvh);
    cudaGetSymbolAddress((void**)&wvl, g_wvl);
    cudaGetSymbolAddress((void**)&woh, g_woh);
    cudaGetSymbolAddress((void**)&wol, g_wol);
    cudaGetSymbolAddress((void**)&wfth, g_wfth);
    cudaGetSymbolAddress((void**)&wftl, g_wftl);

    cudaFuncSetAttribute(gemm_qkv,
                         cudaFuncAttributeMaxDynamicSharedMemorySize, GEMM_SMEM);
    cudaFuncSetAttribute(gemm_out,
                         cudaFuncAttributeMaxDynamicSharedMemorySize, GEMM_SMEM);
    cudaFuncSetAttribute(attn_mma,
                         cudaFuncAttributeMaxDynamicSharedMemorySize, ATTN_SMEM);
    cudaFuncSetAttribute(forget_mma,
                         cudaFuncAttributeMaxDynamicSharedMemorySize, FGM_SMEM);

    splitx_kernel<<<MM*DD/4/256, 256>>>(x, xhi, xlo, MM*DD/4);
    wsplit_kernel<<<dim3(32, 32, 4), dim3(32, 8)>>>(
        Wq, Wk, Wv, Wo,
        wqh, wql, wkh, wkl, wvh, wvl, woh, wol);
    wftsplit_kernel<<<64, 256>>>(Wf, wfth, wftl);

    gemm_qkv<<<dim3(24, 32), 256, GEMM_SMEM>>>(
        xhi, wqh, wql, wkh, wkl, wvh, wvl,
        qhi, qlo, khi, klo, vhi, vlo);

    forget_mma<<<MM / 128, 128, FGM_SMEM>>>(xhi, xlo, wfth, wftl, bf, cp);
    cumsum_kernel<<<BB * HH, 256>>>(cp);

    attn_mma<<<dim3(TT / 64, BB * HH), 128, ATTN_SMEM>>>(
        qhi, qlo, khi, klo, vhi, vlo, cp, ohi);

    gemm_out<<<dim3(DD / 128, MM / 128), 256, GEMM_SMEM>>>(
        ohi, woh, wol, out);
}

// round 10
// speedup vs baseline: 20.5970x; 1.4264x over previous
#include <cuda_runtime.h>
#include <cuda_fp16.h>
#include <math.h>
#include <stdint.h>

// Problem constants
#define BB 2
#define TT 2048
#define DD 1024
#define HH 16
#define HD 64
#define MM (BB*TT)   // 4096

// ---------------------------------------------------------------------------
// Scratch (device globals; no allocation allowed)
// ---------------------------------------------------------------------------
__device__ float g_c[BB*HH*TT];

__device__ __half g_xhi[MM*DD], g_xlo[MM*DD];        // x hi/lo fp16
__device__ __half g_qhi[MM*DD], g_qlo[MM*DD];        // [B,H,T,HD]
__device__ __half g_khi[MM*DD], g_klo[MM*DD];
__device__ __half g_vhi[MM*DD], g_vlo[MM*DD];
__device__ __half g_ohi[MM*DD];                      // attention out, single fp16
__device__ __half g_wqh[DD*DD];                      // Wt hi only [N][K]
__device__ __half g_wkh[DD*DD];
__device__ __half g_wvh[DD*DD];
__device__ __half g_woh[DD*DD];
__device__ __half g_wfth[HH*DD], g_wftl[HH*DD];      // WfT hi/lo [16][1024]

// ---------------------------------------------------------------------------
// PTX helpers
// ---------------------------------------------------------------------------
__device__ __forceinline__ uint32_t smem_u32(const void* p) {
    uint32_t a;
    asm("{ .reg .u64 t; cvta.to.shared.u64 t, %1; cvt.u32.u64 %0, t; }"
        : "=r"(a) : "l"(p));
    return a;
}
__device__ __forceinline__ void cp16(uint32_t dst, const void* src) {
    asm volatile("cp.async.cg.shared.global [%0], [%1], 16;"
                 :: "r"(dst), "l"(src) : "memory");
}
__device__ __forceinline__ void cp_commit() {
    asm volatile("cp.async.commit_group;" ::: "memory");
}
template<int N> __device__ __forceinline__ void cp_wait() {
    asm volatile("cp.async.wait_group %0;" :: "n"(N) : "memory");
}
__device__ __forceinline__ void ldmx4(uint32_t* r, uint32_t addr) {
    asm volatile("ldmatrix.sync.aligned.m8n8.x4.shared.b16 {%0,%1,%2,%3}, [%4];"
                 : "=r"(r[0]), "=r"(r[1]), "=r"(r[2]), "=r"(r[3]) : "r"(addr));
}
__device__ __forceinline__ void ldmx4t(uint32_t* r, uint32_t addr) {
    asm volatile("ldmatrix.sync.aligned.m8n8.x4.trans.shared.b16 {%0,%1,%2,%3}, [%4];"
                 : "=r"(r[0]), "=r"(r[1]), "=r"(r[2]), "=r"(r[3]) : "r"(addr));
}
__device__ __forceinline__ void mma16816(float* c, const uint32_t* a,
                                         uint32_t b0, uint32_t b1) {
    asm volatile(
        "mma.sync.aligned.m16n8k16.row.col.f32.f16.f16.f32 "
        "{%0,%1,%2,%3}, {%4,%5,%6,%7}, {%8,%9}, {%0,%1,%2,%3};"
        : "+f"(c[0]), "+f"(c[1]), "+f"(c[2]), "+f"(c[3])
        : "r"(a[0]), "r"(a[1]), "r"(a[2]), "r"(a[3]), "r"(b0), "r"(b1));
}
__device__ __forceinline__ float ex2f(float x) {
    float r;
    asm("ex2.approx.ftz.f32 %0, %1;" : "=f"(r) : "f"(x));
    return r;
}
__device__ __forceinline__ void pack_split(float a, float b,
                                           uint32_t& hi, uint32_t& lo) {
    __half ha = __float2half_rn(a);
    __half hb = __float2half_rn(b);
    __half la = __float2half_rn(a - __half2float(ha));
    __half lb = __float2half_rn(b - __half2float(hb));
    __half2 H = __halves2half2(ha, hb);
    __half2 L = __halves2half2(la, lb);
    hi = *reinterpret_cast<uint32_t*>(&H);
    lo = *reinterpret_cast<uint32_t*>(&L);
}
__device__ __forceinline__ uint32_t pack_h(float a, float b) {
    __half2 H = __halves2half2(__float2half_rn(a), __float2half_rn(b));
    return *reinterpret_cast<uint32_t*>(&H);
}

#define LOG2E 1.44269504088896340736f

// ---------------------------------------------------------------------------
// Common swizzle for 128B-row tiles (row-major, 8 x 16B chunks per row)
// ---------------------------------------------------------------------------
__device__ __forceinline__ uint32_t asw(int row, int chunk) {
    return (uint32_t)(row * 128 + ((chunk ^ (row & 7)) * 16));
}

// ---------------------------------------------------------------------------
// x fp32 -> fp16 hi/lo
// ---------------------------------------------------------------------------
__global__ __launch_bounds__(256) void splitx_kernel(
    const float* __restrict__ in, __half* __restrict__ hi,
    __half* __restrict__ lo, int n4)
{
    int i = blockIdx.x * blockDim.x + threadIdx.x;
    if (i >= n4) return;
    float4 v = ((const float4*)in)[i];
    uint32_t h0, l0, h1, l1;
    pack_split(v.x, v.y, h0, l0);
    pack_split(v.z, v.w, h1, l1);
    ((uint32_t*)hi)[2*i]   = h0;
    ((uint32_t*)hi)[2*i+1] = h1;
    ((uint32_t*)lo)[2*i]   = l0;
    ((uint32_t*)lo)[2*i+1] = l1;
}

// ---------------------------------------------------------------------------
// Weight transpose + fp16 (hi only), all 4 big weights in one launch
// ---------------------------------------------------------------------------
__global__ __launch_bounds__(256) void wsplit_kernel(
    const float* __restrict__ W0, const float* __restrict__ W1,
    const float* __restrict__ W2, const float* __restrict__ W3,
    __half* __restrict__ H0, __half* __restrict__ H1,
    __half* __restrict__ H2, __half* __restrict__ H3)
{
    const int z = blockIdx.z;
    const float* W  = (z == 0) ? W0 : (z == 1) ? W1 : (z == 2) ? W2 : W3;
    __half* Whi     = (z == 0) ? H0 : (z == 1) ? H1 : (z == 2) ? H2 : H3;

    __shared__ float t[32][33];
    const int tx = threadIdx.x, ty = threadIdx.y;
    const int bx = blockIdx.x * 32;
    const int by = blockIdx.y * 32;
#pragma unroll
    for (int j = 0; j < 32; j += 8)
        t[ty + j][tx] = W[(size_t)(by + ty + j) * DD + bx + tx];
    __syncthreads();
#pragma unroll
    for (int j = 0; j < 32; j += 8) {
        float v = t[tx][ty + j];
        Whi[(size_t)(bx + ty + j) * DD + by + tx] = __float2half_rn(v);
    }
}

// ---------------------------------------------------------------------------
// Wf [1024][16] fp32 -> WfT hi/lo [16][1024] fp16 (forget path stays 3-product)
// ---------------------------------------------------------------------------
__global__ __launch_bounds__(256) void wftsplit_kernel(
    const float* __restrict__ Wf,
    __half* __restrict__ Th, __half* __restrict__ Tl)
{
    int idx = blockIdx.x * 256 + threadIdx.x;
    int h = idx >> 10;
    int d = idx & 1023;
    float v = Wf[d * HH + h];
    __half hi = __float2half_rn(v);
    __half lo = __float2half_rn(v - __half2float(hi));
    Th[h * DD + d] = hi;
    Tl[h * DD + d] = lo;
}

// ---------------------------------------------------------------------------
// Big-GEMM tiles: 128 rows x 64 k fp16 = 16KB, asw-swizzled.
// 1-product (pure fp16 weights): stage = {A, B} = 32KB, double buffer 64KB.
// ---------------------------------------------------------------------------
#define GT     16384
#define GSTG   (2*GT)
#define GEMM_SMEM (2*GSTG)   // 65536

template<typename EPILOG>
__device__ __forceinline__ void gemm1p_body(
    uint32_t smb, int tid,
    const __half* a_h, const __half* b_h,
    EPILOG epi)
{
    const int wid  = tid >> 5;
    const int lane = tid & 31;
    const int wm = (wid & 3) * 32;
    const int wn = (wid >> 2) * 64;

    float acc[2][8][4];
#pragma unroll
    for (int i = 0; i < 2; i++)
#pragma unroll
        for (int j = 0; j < 8; j++)
#pragma unroll
            for (int k = 0; k < 4; k++) acc[i][j][k] = 0.f;

    const int a_row = lane & 15;
    const int a_chk = lane >> 4;
    const int b_mat = lane >> 3;
    const int b_row = (b_mat >> 1) * 8 + (lane & 7);
    const int b_chk = b_mat & 1;

    auto stage = [&](uint32_t sbase, int k0) {
        const __half* bases[2] = { a_h + k0, b_h + k0 };
#pragma unroll
        for (int mat = 0; mat < 2; mat++) {
#pragma unroll
            for (int i = 0; i < 4; i++) {
                int s = tid + i * 256;
                int row = s >> 3, c = s & 7;
                cp16(sbase + mat * GT + asw(row, c),
                     bases[mat] + (size_t)row * DD + c * 8);
            }
        }
    };

    stage(smb, 0);
    cp_commit();

    for (int it = 0; it < 16; it++) {
        if (it + 1 < 16) {
            stage(smb + ((it + 1) & 1) * GSTG, (it + 1) * 64);
            cp_commit();
            cp_wait<1>();
        } else {
            cp_wait<0>();
        }
        __syncthreads();

        const uint32_t sb = smb + (it & 1) * GSTG;
#pragma unroll
        for (int ks = 0; ks < 4; ks++) {
            uint32_t af[2][4], bf[4][4];
#pragma unroll
            for (int mt = 0; mt < 2; mt++)
                ldmx4(af[mt], sb + asw(wm + mt * 16 + a_row, ks * 2 + a_chk));
#pragma unroll
            for (int ng = 0; ng < 4; ng++)
                ldmx4(bf[ng], sb + GT + asw(wn + ng * 16 + b_row, ks * 2 + b_chk));
#pragma unroll
            for (int mt = 0; mt < 2; mt++)
#pragma unroll
                for (int ng = 0; ng < 4; ng++)
#pragma unroll
                    for (int h = 0; h < 2; h++)
                        mma16816(acc[mt][ng * 2 + h], af[mt],
                                 bf[ng][h * 2], bf[ng][h * 2 + 1]);
        }
        __syncthreads();
    }

    epi(acc, wm, wn, lane);
}

// ---------------------------------------------------------------------------
// Fused QKV GEMM: grid (24, 32). Epilogue: fp16 hi/lo split in [B,H,T,HD].
// ---------------------------------------------------------------------------
__global__ __launch_bounds__(256, 2) void gemm_qkv(
    const __half* __restrict__ xh,
    const __half* __restrict__ wqh, const __half* __restrict__ wkh,
    const __half* __restrict__ wvh,
    __half* __restrict__ qhi, __half* __restrict__ qlo,
    __half* __restrict__ khi, __half* __restrict__ klo,
    __half* __restrict__ vhi, __half* __restrict__ vlo)
{
    extern __shared__ char smraw[];
    const uint32_t smb = smem_u32(smraw);
    const int tid = threadIdx.x;
    const int nmat = blockIdx.x >> 3;
    const int nloc = (blockIdx.x & 7) * 128;
    const int m0 = blockIdx.y * 128;

    const __half* a_h = xh + (size_t)m0 * DD;
    const __half* b_h = ((nmat == 0) ? wqh : (nmat == 1) ? wkh : wvh)
                        + (size_t)nloc * DD;
    __half* Chi = (nmat == 0) ? qhi : (nmat == 1) ? khi : vhi;
    __half* Clo = (nmat == 0) ? qlo : (nmat == 1) ? klo : vlo;

    gemm1p_body(smb, tid, a_h, b_h,
        [&](float acc[2][8][4], int wm, int wn, int lane) {
            const int r0 = lane >> 2;
            const int cpair = (lane & 3) * 2;
#pragma unroll
            for (int mt = 0; mt < 2; mt++) {
#pragma unroll
                for (int nt = 0; nt < 8; nt++) {
                    const int m = m0 + wm + mt * 16 + r0;
                    const int n = nloc + wn + nt * 8 + cpair;
                    const int b = m >> 11;
                    const int t = m & (TT - 1);
                    const int h = n >> 6;
                    const int hd = n & (HD - 1);
                    size_t i0 = ((size_t)((b * HH + h) * TT + t) << 6) + hd;
                    size_t i1 = i0 + (size_t)(8 << 6);
                    uint32_t h0, l0, h1, l1;
                    pack_split(acc[mt][nt][0], acc[mt][nt][1], h0, l0);
                    pack_split(acc[mt][nt][2], acc[mt][nt][3], h1, l1);
                    *(uint32_t*)(Chi + i0) = h0;
                    *(uint32_t*)(Clo + i0) = l0;
                    *(uint32_t*)(Chi + i1) = h1;
                    *(uint32_t*)(Clo + i1) = l1;
                }
            }
        });
}

// ---------------------------------------------------------------------------
// Output GEMM: A single fp16, B single fp16, fp32 row-major store.
// ---------------------------------------------------------------------------
__global__ __launch_bounds__(256, 2) void gemm_out(
    const __half* __restrict__ Ah,
    const __half* __restrict__ Bhi,
    float* __restrict__ Cf)
{
    extern __shared__ char smraw[];
    const uint32_t smb = smem_u32(smraw);
    const int tid = threadIdx.x;
    const int n0 = blockIdx.x * 128;
    const int m0 = blockIdx.y * 128;

    const __half* a_h = Ah + (size_t)m0 * DD;
    const __half* b_h = Bhi + (size_t)n0 * DD;

    gemm1p_body(smb, tid, a_h, b_h,
        [&](float acc[2][8][4], int wm, int wn, int lane) {
            const int r0 = lane >> 2;
            const int cpair = (lane & 3) * 2;
#pragma unroll
            for (int mt = 0; mt < 2; mt++) {
#pragma unroll
                for (int nt = 0; nt < 8; nt++) {
                    const int m = m0 + wm + mt * 16 + r0;
                    const int n = n0 + wn + nt * 8 + cpair;
                    float* dst0 = Cf + (size_t)m * DD + n;
                    float* dst1 = Cf + (size_t)(m + 8) * DD + n;
                    *(float2*)dst0 = make_float2(acc[mt][nt][0], acc[mt][nt][1]);
                    *(float2*)dst1 = make_float2(acc[mt][nt][2], acc[mt][nt][3]);
                }
            }
        });
}

// ---------------------------------------------------------------------------
// Forget gate as 3-product split-fp16 MMA GEMM (M=4096,N=16,K=1024)
// ---------------------------------------------------------------------------
#define FG_XL   16384
#define FG_WH   32768
#define FG_WL   34816
#define FG_STG  36864
#define FGM_SMEM (2*FG_STG)   // 73728

__global__ __launch_bounds__(128) void forget_mma(
    const __half* __restrict__ xhi, const __half* __restrict__ xlo,
    const __half* __restrict__ wfh, const __half* __restrict__ wfl,
    const float* __restrict__ bf, float* __restrict__ lf)
{
    extern __shared__ char smraw[];
    const uint32_t smb = smem_u32(smraw);

    const int tid  = threadIdx.x;
    const int wid  = tid >> 5;
    const int lane = tid & 31;
    const int m0 = blockIdx.x * 128;
    const int wm = wid * 32;

    const __half* xh_ = xhi + (size_t)m0 * DD;
    const __half* xl_ = xlo + (size_t)m0 * DD;

    float acc[2][2][4];
#pragma unroll
    for (int i = 0; i < 2; i++)
#pragma unroll
        for (int j = 0; j < 2; j++)
#pragma unroll
            for (int k = 0; k < 4; k++) acc[i][j][k] = 0.f;

    const int a_row = lane & 15;
    const int a_chk = lane >> 4;
    const int b_mat = lane >> 3;
    const int b_row = (b_mat >> 1) * 8 + (lane & 7);
    const int b_chk = b_mat & 1;

    auto stage = [&](uint32_t sbase, int k0) {
#pragma unroll
        for (int i = 0; i < 8; i++) {
            int s = tid + i * 128;
            int row = s >> 3, c = s & 7;
            cp16(sbase + asw(row, c),         xh_ + (size_t)row * DD + k0 + c * 8);
            cp16(sbase + FG_XL + asw(row, c), xl_ + (size_t)row * DD + k0 + c * 8);
        }
        {
            int row = tid >> 3, c = tid & 7;
            cp16(sbase + FG_WH + asw(row, c), wfh + (size_t)row * DD + k0 + c * 8);
            cp16(sbase + FG_WL + asw(row, c), wfl + (size_t)row * DD + k0 + c * 8);
        }
    };

    stage(smb, 0);
    cp_commit();

    for (int it = 0; it < 16; it++) {
        if (it + 1 < 16) {
            stage(smb + ((it + 1) & 1) * FG_STG, (it + 1) * 64);
            cp_commit();
            cp_wait<1>();
        } else {
            cp_wait<0>();
        }
        __syncthreads();

        const uint32_t sb = smb + (it & 1) * FG_STG;
#pragma unroll
        for (int ks = 0; ks < 4; ks++) {
            uint32_t ah[2][4], al[2][4], bh[4], bl[4];
#pragma unroll
            for (int mt = 0; mt < 2; mt++) {
                uint32_t aoff = asw(wm + mt * 16 + a_row, ks * 2 + a_chk);
                ldmx4(ah[mt], sb + aoff);
                ldmx4(al[mt], sb + FG_XL + aoff);
            }
            {
                uint32_t boff = asw(b_row, ks * 2 + b_chk);
                ldmx4(bh, sb + FG_WH + boff);
                ldmx4(bl, sb + FG_WL + boff);
            }
#pragma unroll
            for (int mt = 0; mt < 2; mt++)
#pragma unroll
                for (int h = 0; h < 2; h++) {
                    float* c = acc[mt][h];
                    mma16816(c, ah[mt], bh[h * 2], bh[h * 2 + 1]);
                    mma16816(c, ah[mt], bl[h * 2], bl[h * 2 + 1]);
                    mma16816(c, al[mt], bh[h * 2], bh[h * 2 + 1]);
                }
        }
        __syncthreads();
    }

    const int r0 = lane >> 2;
    const int cpair = (lane & 3) * 2;
#pragma unroll
    for (int mt = 0; mt < 2; mt++) {
#pragma unroll
        for (int nt = 0; nt < 2; nt++) {
            const int h0 = nt * 8 + cpair;
            const float bf0 = bf[h0], bf1 = bf[h0 + 1];
#pragma unroll
            for (int half = 0; half < 2; half++) {
                const int m = m0 + wm + mt * 16 + r0 + half * 8;
                const int b = m >> 11;
                const int t = m & (TT - 1);
                float z0 = acc[mt][nt][half * 2]     + bf0;
                float z1 = acc[mt][nt][half * 2 + 1] + bf1;
                float ls0 = (z0 >= 0.f) ? -log1pf(__expf(-z0))
                                        : z0 - log1pf(__expf(z0));
                float ls1 = (z1 >= 0.f) ? -log1pf(__expf(-z1))
                                        : z1 - log1pf(__expf(z1));
                ls0 = fminf(fmaxf(ls0, -10.f), 0.f);
                ls1 = fminf(fmaxf(ls1, -10.f), 0.f);
                lf[(size_t)(b * HH + h0)     * TT + t] = ls0;
                lf[(size_t)(b * HH + h0 + 1) * TT + t] = ls1;
            }
        }
    }
}

// ---------------------------------------------------------------------------
// Cumsum over T per (b,h)
// ---------------------------------------------------------------------------
__global__ __launch_bounds__(256) void cumsum_kernel(float* __restrict__ lf)
{
    const int bh = blockIdx.x;
    float* p = lf + (size_t)bh * TT;
    const int tid = threadIdx.x;
    const int lane = tid & 31, wid = tid >> 5;
    __shared__ float wsum[8];

    float v[8];
    float s = 0.f;
#pragma unroll
    for (int i = 0; i < 8; i++) { v[i] = p[tid * 8 + i]; s += v[i]; }

    float ss = s;
#pragma unroll
    for (int off = 1; off < 32; off <<= 1) {
        float n = __shfl_up_sync(0xffffffffu, ss, off);
        if (lane >= off) ss += n;
    }
    if (lane == 31) wsum[wid] = ss;
    __syncthreads();
    float woff = 0.f;
#pragma unroll
    for (int w = 0; w < 8; w++)
        if (w < wid) woff += wsum[w];

    float run = woff + ss - s;
#pragma unroll
    for (int i = 0; i < 8; i++) { run += v[i]; p[tid * 8 + i] = run; }
}

// ---------------------------------------------------------------------------
// HMMA forgetting attention (fp16 splits), decay-window skip, single-fp16 out.
// ---------------------------------------------------------------------------
#define ATILE  8192
#define ACKS   (4*ATILE)
#define ASTAGE (4*ATILE + 256)
#define AQOFF  (2*ASTAGE)
#define ATTN_SMEM (2*ASTAGE + 2*ATILE)

__device__ __forceinline__ void attn_stage(
    uint32_t sb,
    const __half* Kh, const __half* Kl,
    const __half* Vh, const __half* Vl,
    const float* cptr, int k0, int tid)
{
    const __half* mats[4] = {
        Kh + (size_t)k0 * HD, Kl + (size_t)k0 * HD,
        Vh + (size_t)k0 * HD, Vl + (size_t)k0 * HD };
#pragma unroll
    for (int mt = 0; mt < 4; mt++) {
#pragma unroll
        for (int i = 0; i < 4; i++) {
            int s = tid + i * 128;
            int row = s >> 3, c = s & 7;
            cp16(sb + mt * ATILE + asw(row, c), mats[mt] + row * HD + c * 8);
        }
    }
    if (tid < 16) cp16(sb + ACKS + tid * 16, cptr + k0 + tid * 4);
}

__global__ __launch_bounds__(128) void attn_mma(
    const __half* __restrict__ Qhi, const __half* __restrict__ Qlo,
    const __half* __restrict__ Khi, const __half* __restrict__ Klo,
    const __half* __restrict__ Vhi, const __half* __restrict__ Vlo,
    const float* __restrict__ C,
    __half* __restrict__ Ohi)
{
    extern __shared__ char smraw[];
    const uint32_t smb = smem_u32(smraw);

    const int tid  = threadIdx.x;
    const int wid  = tid >> 5;
    const int lane = tid & 31;
    const int qt = blockIdx.x;
    const int bh = blockIdx.y;
    const int q0 = qt * 64;

    const __half* Qh = Qhi + (size_t)bh * TT * HD;
    const __half* Ql = Qlo + (size_t)bh * TT * HD;
    const __half* Kh = Khi + (size_t)bh * TT * HD;
    const __half* Kl = Klo + (size_t)bh * TT * HD;
    const __half* Vh = Vhi + (size_t)bh * TT * HD;
    const __half* Vl = Vlo + (size_t)bh * TT * HD;
    const float* cptr = C + (size_t)bh * TT;

    int kt_start;
    {
        const float cq0v = cptr[q0];
        int lo = 0, hi = qt;
        while (lo < hi) {
            int mid = (lo + hi) >> 1;
            if (cq0v - cptr[mid * 64 + 63] >= -60.f) hi = mid;
            else lo = mid + 1;
        }
        kt_start = lo;
    }

#pragma unroll
    for (int i = 0; i < 8; i++) {
        int s = tid + i * 128;
        int mat = s >> 9;
        int rc = s & 511;
        int row = rc >> 3, c = rc & 7;
        const __half* src = (mat == 0 ? Qh : Ql);
        cp16(smb + AQOFF + mat * ATILE + asw(row, c),
             src + (size_t)(q0 + row) * HD + c * 8);
    }
    cp_commit();
    cp_wait<0>();
    __syncthreads();

    const int a_row = lane & 15;
    const int a_chk = lane >> 4;
    uint32_t qh[4][4], ql[4][4];
#pragma unroll
    for (int ks = 0; ks < 4; ks++) {
        uint32_t ad = smb + AQOFF + asw(wid * 16 + a_row, ks * 2 + a_chk);
        ldmx4(qh[ks], ad);
        ldmx4(ql[ks], ad + ATILE);
    }

    const int r0 = wid * 16 + (lane >> 2);
    const float cq0 = cptr[q0 + r0];
    const float cq1 = cptr[q0 + r0 + 8];

    float m0 = -1e30f, m1 = -1e30f, l0 = 0.f, l1 = 0.f;
    float o[8][4];
#pragma unroll
    for (int i = 0; i < 8; i++)
#pragma unroll
        for (int j = 0; j < 4; j++) o[i][j] = 0.f;

    const int b_mat = lane >> 3;
    const int b_row = (b_mat >> 1) * 8 + (lane & 7);
    const int b_chk = b_mat & 1;
    const int v_g = lane >> 3;
    const int v_r = lane & 7;

    attn_stage(smb + (kt_start & 1) * ASTAGE, Kh, Kl, Vh, Vl, cptr,
               kt_start * 64, tid);
    cp_commit();

    for (int kt = kt_start; kt <= qt; kt++) {
        if (kt < qt) {
            attn_stage(smb + ((kt + 1) & 1) * ASTAGE,
                       Kh, Kl, Vh, Vl, cptr, (kt + 1) * 64, tid);
            cp_commit();
            cp_wait<1>();
        } else {
            cp_wait<0>();
        }
        __syncthreads();

        const uint32_t sb = smb + (kt & 1) * ASTAGE;
        const float* cks = (const float*)(smraw + (kt & 1) * ASTAGE + ACKS);

        float s[8][4];
#pragma unroll
        for (int i = 0; i < 8; i++)
#pragma unroll
            for (int j = 0; j < 4; j++) s[i][j] = 0.f;

#pragma unroll
        for (int ks = 0; ks < 4; ks++) {
            uint32_t kh[4][4], kl[4][4];
#pragma unroll
            for (int ng = 0; ng < 4; ng++) {
                uint32_t bd = sb + asw(ng * 16 + b_row, ks * 2 + b_chk);
                ldmx4(kh[ng], bd);
                ldmx4(kl[ng], bd + ATILE);
            }
#pragma unroll
            for (int ng = 0; ng < 4; ng++)
#pragma unroll
                for (int h = 0; h < 2; h++) {
                    float* c = s[ng * 2 + h];
                    mma16816(c, qh[ks], kh[ng][h * 2], kh[ng][h * 2 + 1]);
                    mma16816(c, qh[ks], kl[ng][h * 2], kl[ng][h * 2 + 1]);
                    mma16816(c, ql[ks], kh[ng][h * 2], kh[ng][h * 2 + 1]);
                }
        }

        const bool diag = (kt == qt);
        const int k0g = kt * 64;
#pragma unroll
        for (int nt = 0; nt < 8; nt++) {
            const int col = nt * 8 + (lane & 3) * 2;
            const float ck0 = cks[col], ck1 = cks[col + 1];
            float d00 = fmaxf(cq0 - ck0, -50.f);
            float d01 = fmaxf(cq0 - ck1, -50.f);
            float d10 = fmaxf(cq1 - ck0, -50.f);
            float d11 = fmaxf(cq1 - ck1, -50.f);
            s[nt][0] = fmaf(s[nt][0], 0.125f, d00);
            s[nt][1] = fmaf(s[nt][1], 0.125f, d01);
            s[nt][2] = fmaf(s[nt][2], 0.125f, d10);
            s[nt][3] = fmaf(s[nt][3], 0.125f, d11);
            if (diag) {
                if (k0g + col     > q0 + r0)     s[nt][0] = -1e30f;
                if (k0g + col + 1 > q0 + r0)     s[nt][1] = -1e30f;
                if (k0g + col     > q0 + r0 + 8) s[nt][2] = -1e30f;
                if (k0g + col + 1 > q0 + r0 + 8) s[nt][3] = -1e30f;
            }
        }

        float ml0 = -1e30f, ml1 = -1e30f;
#pragma unroll
        for (int nt = 0; nt < 8; nt++) {
            ml0 = fmaxf(ml0, fmaxf(s[nt][0], s[nt][1]));
            ml1 = fmaxf(ml1, fmaxf(s[nt][2], s[nt][3]));
        }
        ml0 = fmaxf(ml0, __shfl_xor_sync(0xffffffffu, ml0, 1));
        ml0 = fmaxf(ml0, __shfl_xor_sync(0xffffffffu, ml0, 2));
        ml1 = fmaxf(ml1, __shfl_xor_sync(0xffffffffu, ml1, 1));
        ml1 = fmaxf(ml1, __shfl_xor_sync(0xffffffffu, ml1, 2));
        const float mn0 = fmaxf(m0, ml0);
        const float mn1 = fmaxf(m1, ml1);
        const float corr0 = ex2f((m0 - mn0) * LOG2E);
        const float corr1 = ex2f((m1 - mn1) * LOG2E);
        m0 = mn0; m1 = mn1;

        float sum0 = 0.f, sum1 = 0.f;
#pragma unroll
        for (int nt = 0; nt < 8; nt++) {
            s[nt][0] = ex2f((s[nt][0] - mn0) * LOG2E);
            s[nt][1] = ex2f((s[nt][1] - mn0) * LOG2E);
            s[nt][2] = ex2f((s[nt][2] - mn1) * LOG2E);
            s[nt][3] = ex2f((s[nt][3] - mn1) * LOG2E);
            sum0 += s[nt][0] + s[nt][1];
            sum1 += s[nt][2] + s[nt][3];
        }
        l0 = l0 * corr0 + sum0;
        l1 = l1 * corr1 + sum1;
#pragma unroll
        for (int nt = 0; nt < 8; nt++) {
            o[nt][0] *= corr0; o[nt][1] *= corr0;
            o[nt][2] *= corr1; o[nt][3] *= corr1;
        }

        uint32_t ph[4][4], pl[4][4];
#pragma unroll
        for (int kc = 0; kc < 4; kc++) {
            pack_split(s[kc*2][0],   s[kc*2][1],   ph[kc][0], pl[kc][0]);
            pack_split(s[kc*2][2],   s[kc*2][3],   ph[kc][1], pl[kc][1]);
            pack_split(s[kc*2+1][0], s[kc*2+1][1], ph[kc][2], pl[kc][2]);
            pack_split(s[kc*2+1][2], s[kc*2+1][3], ph[kc][3], pl[kc][3]);
        }

#pragma unroll
        for (int kc = 0; kc < 4; kc++) {
            uint32_t vh[4][4], vl[4][4];
#pragma unroll
            for (int p = 0; p < 4; p++) {
                int row = kc * 16 + (v_g & 1) * 8 + v_r;
                int chunk = p * 2 + (v_g >> 1);
                uint32_t vd = sb + 2 * ATILE + asw(row, chunk);
                ldmx4t(vh[p], vd);
                ldmx4t(vl[p], vd + ATILE);
            }
#pragma unroll
            for (int p = 0; p < 4; p++)
#pragma unroll
                for (int h = 0; h < 2; h++) {
                    float* c = o[p * 2 + h];
                    mma16816(c, ph[kc], vh[p][h * 2], vh[p][h * 2 + 1]);
                    mma16816(c, ph[kc], vl[p][h * 2], vl[p][h * 2 + 1]);
                    mma16816(c, pl[kc], vh[p][h * 2], vh[p][h * 2 + 1]);
                }
        }
        __syncthreads();
    }

    l0 += __shfl_xor_sync(0xffffffffu, l0, 1);
    l0 += __shfl_xor_sync(0xffffffffu, l0, 2);
    l1 += __shfl_xor_sync(0xffffffffu, l1, 1);
    l1 += __shfl_xor_sync(0xffffffffu, l1, 2);
    const float inv0 = 1.f / l0;
    const float inv1 = 1.f / l1;

    const int b = bh >> 4, h = bh & 15;
    const int t0 = q0 + r0;
    size_t base0 = ((size_t)(b * TT + t0)) * DD + h * HD;
    size_t base1 = base0 + (size_t)8 * DD;
#pragma unroll
    for (int nt = 0; nt < 8; nt++) {
        const int col = nt * 8 + (lane & 3) * 2;
        *(uint32_t*)(Ohi + base0 + col) = pack_h(o[nt][0] * inv0, o[nt][1] * inv0);
        *(uint32_t*)(Ohi + base1 + col) = pack_h(o[nt][2] * inv1, o[nt][3] * inv1);
    }
}

// ---------------------------------------------------------------------------
// kernel_launch
// ---------------------------------------------------------------------------
extern "C" void kernel_launch(void* const* d_in, const int* in_sizes, int n_in,
                              void* d_out, int out_size)
{
    (void)in_sizes; (void)n_in; (void)out_size;
    const float* x  = (const float*)d_in[0];
    const float* Wq = (const float*)d_in[1];
    const float* Wk = (const float*)d_in[2];
    const float* Wv = (const float*)d_in[3];
    const float* Wo = (const float*)d_in[4];
    const float* Wf = (const float*)d_in[5];
    const float* bf = (const float*)d_in[6];
    float* out = (float*)d_out;

    float* cp;
    cudaGetSymbolAddress((void**)&cp, g_c);

    __half *xhi, *xlo, *ohi;
    __half *qhi, *qlo, *khi, *klo, *vhi, *vlo;
    __half *wqh, *wkh, *wvh, *woh, *wfth, *wftl;
    cudaGetSymbolAddress((void**)&xhi, g_xhi);
    cudaGetSymbolAddress((void**)&xlo, g_xlo);
    cudaGetSymbolAddress((void**)&ohi, g_ohi);
    cudaGetSymbolAddress((void**)&qhi, g_qhi);
    cudaGetSymbolAddress((void**)&qlo, g_qlo);
    cudaGetSymbolAddress((void**)&khi, g_khi);
    cudaGetSymbolAddress((void**)&klo, g_klo);
    cudaGetSymbolAddress((void**)&vhi, g_vhi);
    cudaGetSymbolAddress((void**)&vlo, g_vlo);
    cudaGetSymbolAddress((void**)&wqh, g_wqh);
    cudaGetSymbolAddress((void**)&wkh, g_wkh);
    cudaGetSymbolAddress((void**)&wvh, g_wvh);
    cudaGetSymbolAddress((void**)&woh, g_woh);
    cudaGetSymbolAddress((void**)&wfth, g_wfth);
    cudaGetSymbolAddress((void**)&wftl, g_wftl);

    cudaFuncSetAttribute(gemm_qkv,
                         cudaFuncAttributeMaxDynamicSharedMemorySize, GEMM_SMEM);
    cudaFuncSetAttribute(gemm_out,
                         cudaFuncAttributeMaxDynamicSharedMemorySize, GEMM_SMEM);
    cudaFuncSetAttribute(attn_mma,
                         cudaFuncAttributeMaxDynamicSharedMemorySize, ATTN_SMEM);
    cudaFuncSetAttribute(forget_mma,
                         cudaFuncAttributeMaxDynamicSharedMemorySize, FGM_SMEM);

    splitx_kernel<<<MM*DD/4/256, 256>>>(x, xhi, xlo, MM*DD/4);
    wsplit_kernel<<<dim3(32, 32, 4), dim3(32, 8)>>>(
        Wq, Wk, Wv, Wo, wqh, wkh, wvh, woh);
    wftsplit_kernel<<<64, 256>>>(Wf, wfth, wftl);

    gemm_qkv<<<dim3(24, 32), 256, GEMM_SMEM>>>(
        xhi, wqh, wkh, wvh,
        qhi, qlo, khi, klo, vhi, vlo);

    forget_mma<<<MM / 128, 128, FGM_SMEM>>>(xhi, xlo, wfth, wftl, bf, cp);
    cumsum_kernel<<<BB * HH, 256>>>(cp);

    attn_mma<<<dim3(TT / 64, BB * HH), 128, ATTN_SMEM>>>(
        qhi, qlo, khi, klo, vhi, vlo, cp, ohi);

    gemm_out<<<dim3(DD / 128, MM / 128), 256, GEMM_SMEM>>>(
        ohi, woh, out);
}